// round 9
// baseline (speedup 1.0000x reference)
#include <cuda_runtime.h>
#include <cuda_fp16.h>
#include <math.h>
#include <stdint.h>

// ---------------- problem constants ----------------
#define S_LEN 1024
#define HID_D 7168
#define NH 128
#define DN 128
#define DR 64
#define DV 128
#define QLORA 1536
#define KVLORA 512
#define COMP_D (QLORA + KVLORA + DR)      // 2112
#define QD (NH * (DN + DR))               // 24576
#define KVD (NH * (DN + DV))              // 32768
#define CTX_D (NH * DV)                   // 16384
#define DQK 192

// ---------------- scratch (device globals) ----------------
__device__ float g_comp[S_LEN * COMP_D];
__device__ __half g_ah[(size_t)S_LEN * 16384];                   // activations hi (also ctx)
__device__ __half g_al[(size_t)S_LEN * 16384];                   // activations lo
__device__ __half g_wa_h[15597568];                              // w_kv_a hi (2176*7168)
__device__ __half g_wa_l[15597568];                              // w_kv_a lo
__device__ __half g_wq[(size_t)QD * QLORA];                      // w_q_b^T
__device__ __half g_wkv[(size_t)KVD * KVLORA];                   // w_kv_b^T
__device__ __half g_wo[(size_t)HID_D * CTX_D];                   // w_o^T
__device__ float g_kv[(size_t)S_LEN * KVD];                      // v half only used
__device__ float g_kpe[S_LEN * DR];
__device__ float g_part[(size_t)S_LEN * HID_D];                  // w_o K-split partial
__device__ __half g_qh[(size_t)NH * S_LEN * DQK];
__device__ __half g_ql[(size_t)NH * S_LEN * DQK];
__device__ __half g_kh[(size_t)NH * S_LEN * DQK];
__device__ __half g_kl[(size_t)NH * S_LEN * DQK];
__device__ __half g_vth[(size_t)NH * DV * S_LEN];

// ---------------- PTX helpers ----------------
__device__ __forceinline__ uint32_t smem_u32(const void* p) {
    uint32_t a;
    asm("{ .reg .u64 t; cvta.to.shared.u64 t, %1; cvt.u32.u64 %0, t; }" : "=r"(a) : "l"(p));
    return a;
}
#define CP16(dst, src) \
    asm volatile("cp.async.cg.shared.global [%0], [%1], 16;" :: "r"(dst), "l"(src) : "memory")
#define CP_COMMIT() asm volatile("cp.async.commit_group;" ::: "memory")
#define CP_WAIT0() asm volatile("cp.async.wait_group 0;" ::: "memory")

template <int N>
__device__ __forceinline__ void cp_wait() {
    asm volatile("cp.async.wait_group %0;" :: "n"(N) : "memory");
}

#define LDSM4(r, a) \
    asm volatile("ldmatrix.sync.aligned.m8n8.x4.shared.b16 {%0,%1,%2,%3}, [%4];" \
        : "=r"((r)[0]), "=r"((r)[1]), "=r"((r)[2]), "=r"((r)[3]) : "r"(a))

#define MMA_F16(d, a, b0, b1) \
    asm volatile("mma.sync.aligned.m16n8k16.row.col.f32.f16.f16.f32 " \
        "{%0,%1,%2,%3}, {%4,%5,%6,%7}, {%8,%9}, {%0,%1,%2,%3};" \
        : "+f"((d)[0]), "+f"((d)[1]), "+f"((d)[2]), "+f"((d)[3]) \
        : "r"((a)[0]), "r"((a)[1]), "r"((a)[2]), "r"((a)[3]), "r"(b0), "r"(b1))

#define SWZ(o) ((o) ^ (((o) >> 3) & 0x70))

__device__ __forceinline__ void split_h(float v, __half& h, __half& l) {
    h = __float2half_rn(v);
    l = __float2half_rn(v - __half2float(h));
}

// ---------------- shared GEMM body, NSTAGE-deep cp.async pipeline ----------------
// NPASS=1: ah*bh        NPASS=2: ah*bh + al*bh        NPASS=3: + ah*bl
// Exactly one commit group per load slot (empty groups at tail keep counting exact).
template <int NPASS, int NSTAGE>
__device__ __forceinline__ void gemm_body(
    const __half* __restrict__ Ah, const __half* __restrict__ Al,
    const __half* __restrict__ Bh, const __half* __restrict__ Bl,
    int K, int nch, int m0, int n0, uint32_t sb, int tid, float acc[2][8][4])
{
    constexpr int CA = (NPASS >= 2) ? 2 : 1;
    constexpr int CB = (NPASS == 3) ? 2 : 1;
    constexpr int NT = CA + CB;
    constexpr int STAGE = NT * 16384;
    const int lane = tid & 31;
    const int wid = tid >> 5;
    const int wm = (wid & 3) * 32;
    const int wn = (wid >> 2) * 64;

    auto load_stage = [&](int c, int s) {
        const int kc = c << 6;
#pragma unroll
        for (int it = 0; it < NT * 4; it++) {
            const int t = tid + it * 256;
            const int tensor = t >> 10;
            const int rem = t & 1023;
            const int row = rem >> 3;
            const int ch = rem & 7;
            const __half* src;
            int grow;
            if (tensor < CA) {
                src = (CA == 2 && tensor == 1) ? Al : Ah;
                grow = m0 + row;
            } else {
                src = (CB == 2 && tensor == CA + 1) ? Bl : Bh;
                grow = n0 + row;
            }
            const __half* sp = src + (size_t)grow * K + kc + ch * 8;
            const uint32_t dst = sb + s * STAGE + tensor * 16384 + SWZ(row * 128 + ch * 16);
            CP16(dst, sp);
        }
        CP_COMMIT();
    };

    // prologue: fill NSTAGE-1 stages (empty commits if nch is short)
#pragma unroll
    for (int s = 0; s < NSTAGE - 1; s++) {
        if (s < nch) load_stage(s, s);
        else CP_COMMIT();
    }

    for (int c = 0; c < nch; c++) {
        const int buf = c % NSTAGE;
        cp_wait<NSTAGE - 2>();
        __syncthreads();
        if (c + NSTAGE - 1 < nch) load_stage(c + NSTAGE - 1, (c + NSTAGE - 1) % NSTAGE);
        else CP_COMMIT();

        const uint32_t st = sb + buf * STAGE;
        const uint32_t sA_h = st;
        const uint32_t sA_l = st + 16384;
        const uint32_t sB_h = st + CA * 16384;
        const uint32_t sB_l = sB_h + 16384;
        const int rl = lane & 15;
        const int kb = lane >> 4;

#pragma unroll
        for (int k16 = 0; k16 < 4; k16++) {
            const int kbyte = k16 * 32 + kb * 16;
            uint32_t afh[2][4], afl[2][4], bfh[4][4], bfl[4][4];
#pragma unroll
            for (int mt = 0; mt < 2; mt++) {
                const uint32_t off = SWZ((wm + mt * 16 + rl) * 128 + kbyte);
                LDSM4(afh[mt], sA_h + off);
                if (CA == 2) LDSM4(afl[mt], sA_l + off);
            }
#pragma unroll
            for (int q = 0; q < 4; q++) {
                const uint32_t off = SWZ((wn + q * 16 + rl) * 128 + kbyte);
                LDSM4(bfh[q], sB_h + off);
                if (CB == 2) LDSM4(bfl[q], sB_l + off);
            }
#pragma unroll
            for (int mt = 0; mt < 2; mt++)
#pragma unroll
                for (int nt = 0; nt < 8; nt++) {
                    const int q = nt >> 1, s = nt & 1;
                    MMA_F16(acc[mt][nt], afh[mt], bfh[q][s], bfh[q][s + 2]);
                    if (CA == 2) MMA_F16(acc[mt][nt], afl[mt], bfh[q][s], bfh[q][s + 2]);
                    if (CB == 2) MMA_F16(acc[mt][nt], afh[mt], bfl[q][s], bfl[q][s + 2]);
                }
        }
        // no trailing sync: next iteration's top sync guards stage overwrite
    }
}

#define GEMM_PROLOGUE() \
    extern __shared__ __align__(128) char smem[]; \
    const uint32_t sb = smem_u32(smem); \
    const int tid = threadIdx.x; \
    const int lane = tid & 31; \
    const int wid = tid >> 5; \
    const int m0 = blockIdx.y * 128, n0 = blockIdx.x * 128; \
    const int wm = (wid & 3) * 32, wn = (wid >> 2) * 64; \
    float acc[2][8][4]; \
    _Pragma("unroll") for (int mt = 0; mt < 2; mt++) \
    _Pragma("unroll") for (int nt = 0; nt < 8; nt++) \
    _Pragma("unroll") for (int e = 0; e < 4; e++) acc[mt][nt][e] = 0.0f;

// ---------------- comp GEMM: 3-pass, fp32 out ----------------
__global__ __launch_bounds__(256, 1) void mma_gemm3(
    const __half* __restrict__ Ah, const __half* __restrict__ Al,
    const __half* __restrict__ Bh, const __half* __restrict__ Bl,
    float* __restrict__ C, int N, int K)
{
    GEMM_PROLOGUE();
    gemm_body<3, 3>(Ah, Al, Bh, Bl, K, K >> 6, m0, n0, sb, tid, acc);
#pragma unroll
    for (int mt = 0; mt < 2; mt++) {
        const int row = m0 + wm + mt * 16 + (lane >> 2);
#pragma unroll
        for (int nt = 0; nt < 8; nt++) {
            const int col = n0 + wn + nt * 8 + (lane & 3) * 2;
            if (col < N) {
                *reinterpret_cast<float2*>(C + (size_t)row * N + col) =
                    make_float2(acc[mt][nt][0], acc[mt][nt][1]);
                *reinterpret_cast<float2*>(C + (size_t)(row + 8) * N + col) =
                    make_float2(acc[mt][nt][2], acc[mt][nt][3]);
            }
        }
    }
}

// ---------------- w_o GEMM: 1-pass, K-split over blockIdx.z ----------------
__global__ __launch_bounds__(256, 1) void mma_gemm1(
    const __half* __restrict__ Ah, const __half* __restrict__ Bh,
    float* __restrict__ C0, float* __restrict__ C1, int N, int K)
{
    GEMM_PROLOGUE();
    const int ks = blockIdx.z;
    const int Kh = K >> 1;
    gemm_body<1, 4>(Ah + ks * Kh, nullptr, Bh + ks * Kh, nullptr,
                    K, Kh >> 6, m0, n0, sb, tid, acc);
    float* C = ks ? C1 : C0;
#pragma unroll
    for (int mt = 0; mt < 2; mt++) {
        const int row = m0 + wm + mt * 16 + (lane >> 2);
#pragma unroll
        for (int nt = 0; nt < 8; nt++) {
            const int col = n0 + wn + nt * 8 + (lane & 3) * 2;
            *reinterpret_cast<float2*>(C + (size_t)row * N + col) =
                make_float2(acc[mt][nt][0], acc[mt][nt][1]);
            *reinterpret_cast<float2*>(C + (size_t)(row + 8) * N + col) =
                make_float2(acc[mt][nt][2], acc[mt][nt][3]);
        }
    }
}

// ---------------- out += part ----------------
__global__ void add_out(float* __restrict__ out, const float* __restrict__ part)
{
    const int i = blockIdx.x * blockDim.x + threadIdx.x;
    float4 a = reinterpret_cast<float4*>(out)[i];
    const float4 b = reinterpret_cast<const float4*>(part)[i];
    a.x += b.x; a.y += b.y; a.z += b.z; a.w += b.w;
    reinterpret_cast<float4*>(out)[i] = a;
}

// ---------------- RoPE angle ----------------
__device__ __forceinline__ void rope_cs(int s, int d, float& c, float& sn)
{
    const float inv = exp2f(-(float)d * (13.287712379549449f / 32.0f));
    sincosf((float)s * inv, &sn, &c);
}

// ---------------- q GEMM: 2-pass, fused RoPE + split, per-head layout -----------
__global__ __launch_bounds__(256, 1) void mma_gemm_q(
    const __half* __restrict__ Ah, const __half* __restrict__ Al,
    const __half* __restrict__ Bh,
    __half* __restrict__ Qh, __half* __restrict__ Ql)
{
    GEMM_PROLOGUE();
    gemm_body<2, 3>(Ah, Al, Bh, nullptr, QLORA, QLORA >> 6, m0, n0, sb, tid, acc);

    const int base64 = n0 + wn;
    if ((base64 / 64) % 3 != 2) {
#pragma unroll
        for (int mt = 0; mt < 2; mt++)
#pragma unroll
            for (int half_i = 0; half_i < 2; half_i++) {
                const int row = m0 + wm + mt * 16 + (lane >> 2) + half_i * 8;
#pragma unroll
                for (int nt = 0; nt < 8; nt++) {
                    const int c = base64 + nt * 8 + (lane & 3) * 2;
                    const int h = c / 192;
                    const int cr = c - h * 192;
                    const size_t o = ((size_t)h * S_LEN + row) * DQK + cr;
                    __half h0, l0, h1, l1;
                    split_h(acc[mt][nt][half_i * 2], h0, l0);
                    split_h(acc[mt][nt][half_i * 2 + 1], h1, l1);
                    *reinterpret_cast<__half2*>(Qh + o) = __half2(h0, h1);
                    *reinterpret_cast<__half2*>(Ql + o) = __half2(l0, l1);
                }
            }
    } else {
        const int h = base64 / 192;
#pragma unroll
        for (int mt = 0; mt < 2; mt++)
#pragma unroll
            for (int half_i = 0; half_i < 2; half_i++) {
                const int row = m0 + wm + mt * 16 + (lane >> 2) + half_i * 8;
                const size_t rb = ((size_t)h * S_LEN + row) * DQK + 128;
#pragma unroll
                for (int ntL = 0; ntL < 4; ntL++) {
                    const int d0 = ntL * 8 + (lane & 3) * 2;
                    float o0[2], o1[2];
#pragma unroll
                    for (int e = 0; e < 2; e++) {
                        float cc, ss;
                        rope_cs(row, d0 + e, cc, ss);
                        const float v1 = acc[mt][ntL][half_i * 2 + e];
                        const float v2 = acc[mt][ntL + 4][half_i * 2 + e];
                        o0[e] = v1 * cc - v2 * ss;
                        o1[e] = v2 * cc + v1 * ss;
                    }
                    __half h0, l0, h1, l1;
                    split_h(o0[0], h0, l0); split_h(o0[1], h1, l1);
                    *reinterpret_cast<__half2*>(Qh + rb + d0) = __half2(h0, h1);
                    *reinterpret_cast<__half2*>(Ql + rb + d0) = __half2(l0, l1);
                    split_h(o1[0], h0, l0); split_h(o1[1], h1, l1);
                    *reinterpret_cast<__half2*>(Qh + rb + d0 + 32) = __half2(h0, h1);
                    *reinterpret_cast<__half2*>(Ql + rb + d0 + 32) = __half2(l0, l1);
                }
            }
    }
}

// ---------------- kv GEMM: 2-pass, k_nope -> split per-head; v -> fp32 ----------
__global__ __launch_bounds__(256, 1) void mma_gemm_kv(
    const __half* __restrict__ Ah, const __half* __restrict__ Al,
    const __half* __restrict__ Bh,
    __half* __restrict__ Kh, __half* __restrict__ Kl, float* __restrict__ kv)
{
    GEMM_PROLOGUE();
    gemm_body<2, 3>(Ah, Al, Bh, nullptr, KVLORA, KVLORA >> 6, m0, n0, sb, tid, acc);

    const int base64 = n0 + wn;
    const int blk4 = (base64 / 64) & 3;
    if (blk4 < 2) {
        const int h = base64 / 256;
#pragma unroll
        for (int mt = 0; mt < 2; mt++)
#pragma unroll
            for (int half_i = 0; half_i < 2; half_i++) {
                const int row = m0 + wm + mt * 16 + (lane >> 2) + half_i * 8;
#pragma unroll
                for (int nt = 0; nt < 8; nt++) {
                    const int c = base64 + nt * 8 + (lane & 3) * 2;
                    const int cr = c - h * 256;
                    const size_t o = ((size_t)h * S_LEN + row) * DQK + cr;
                    __half h0, l0, h1, l1;
                    split_h(acc[mt][nt][half_i * 2], h0, l0);
                    split_h(acc[mt][nt][half_i * 2 + 1], h1, l1);
                    *reinterpret_cast<__half2*>(Kh + o) = __half2(h0, h1);
                    *reinterpret_cast<__half2*>(Kl + o) = __half2(l0, l1);
                }
            }
    } else {
#pragma unroll
        for (int mt = 0; mt < 2; mt++) {
            const int row = m0 + wm + mt * 16 + (lane >> 2);
#pragma unroll
            for (int nt = 0; nt < 8; nt++) {
                const int c = base64 + nt * 8 + (lane & 3) * 2;
                *reinterpret_cast<float2*>(kv + (size_t)row * KVD + c) =
                    make_float2(acc[mt][nt][0], acc[mt][nt][1]);
                *reinterpret_cast<float2*>(kv + (size_t)(row + 8) * KVD + c) =
                    make_float2(acc[mt][nt][2], acc[mt][nt][3]);
            }
        }
    }
}

// ---------------- fused flash attention per (head, i-tile) ----------------
// smem: [0,128K) gemm stages (reused for P after S phase), [128K,160K) V tile
__global__ __launch_bounds__(256, 1) void flash_mma(
    const __half* __restrict__ Qh, const __half* __restrict__ Ql,
    const __half* __restrict__ Kh, const __half* __restrict__ Kl,
    const __half* __restrict__ Vth, __half* __restrict__ ch)
{
    extern __shared__ __align__(128) char smem[];
    __shared__ float redM[2][128];
    __shared__ float redS[2][128];
    const uint32_t sb = smem_u32(smem);
    const int tid = threadIdx.x;
    const int lane = tid & 31;
    const int wid = tid >> 5;
    const int h = blockIdx.x;
    const int it = 7 - blockIdx.y;          // heavy tiles first
    const int m0 = it * 128;
    const int wm = (wid & 3) * 32, wn = (wid >> 2) * 64;
    const int ng = wid >> 2;
    const size_t hoff = (size_t)h * S_LEN * DQK;
    const size_t voff = (size_t)h * DV * S_LEN;
    const float scale = 0.07216878364870323f;   // 1/sqrt(192)

    float Oacc[2][8][4];
    float mrow[2][2], lrow[2][2];
#pragma unroll
    for (int mt = 0; mt < 2; mt++)
#pragma unroll
        for (int nt = 0; nt < 8; nt++)
#pragma unroll
            for (int e = 0; e < 4; e++) Oacc[mt][nt][e] = 0.0f;
#pragma unroll
    for (int mt = 0; mt < 2; mt++)
#pragma unroll
        for (int hf = 0; hf < 2; hf++) { mrow[mt][hf] = -3.4e38f; lrow[mt][hf] = 0.0f; }

    for (int jt = 0; jt <= it; jt++) {
        // ---- S = Q @ K^T (3-pass split) ----
        float Sacc[2][8][4];
#pragma unroll
        for (int mt = 0; mt < 2; mt++)
#pragma unroll
            for (int nt = 0; nt < 8; nt++)
#pragma unroll
                for (int e = 0; e < 4; e++) Sacc[mt][nt][e] = 0.0f;

        gemm_body<3, 2>(Qh + hoff, Ql + hoff, Kh + hoff, Kl + hoff,
                        DQK, 3, m0, jt * 128, sb, tid, Sacc);

        // ---- prefetch V tile (2 chunks of [128 d][64 j]) ----
#pragma unroll
        for (int itv = 0; itv < 8; itv++) {
            const int t = tid + itv * 256;
            const int c = t >> 10;
            const int rem = t & 1023;
            const int d = rem >> 3;
            const int seg = rem & 7;
            const __half* sp = Vth + voff + (size_t)d * S_LEN + jt * 128 + c * 64 + seg * 8;
            CP16(sb + 131072 + c * 16384 + SWZ(d * 128 + seg * 16), sp);
        }
        CP_COMMIT();

        // ---- pass A: scale + mask + row max ----
#pragma unroll
        for (int mt = 0; mt < 2; mt++)
#pragma unroll
            for (int hf = 0; hf < 2; hf++) {
                const int rloc = wm + mt * 16 + (lane >> 2) + hf * 8;
                float mx = -3.4e38f;
#pragma unroll
                for (int nt = 0; nt < 8; nt++)
#pragma unroll
                    for (int e = 0; e < 2; e++) {
                        float s = Sacc[mt][nt][hf * 2 + e] * scale;
                        if (jt == it) {
                            const int cg = jt * 128 + wn + nt * 8 + (lane & 3) * 2 + e;
                            if (cg > m0 + rloc) s = -3.4e38f;
                        }
                        Sacc[mt][nt][hf * 2 + e] = s;
                        mx = fmaxf(mx, s);
                    }
                mx = fmaxf(mx, __shfl_xor_sync(0xFFFFFFFFu, mx, 1));
                mx = fmaxf(mx, __shfl_xor_sync(0xFFFFFFFFu, mx, 2));
                if ((lane & 3) == 0) redM[ng][rloc] = mx;
            }
        __syncthreads();

        // ---- pass B: exp, write P (hi/lo) to smem, partial row sums, O rescale ----
#pragma unroll
        for (int mt = 0; mt < 2; mt++)
#pragma unroll
            for (int hf = 0; hf < 2; hf++) {
                const int rloc = wm + mt * 16 + (lane >> 2) + hf * 8;
                const float mnew = fmaxf(mrow[mt][hf],
                                         fmaxf(redM[0][rloc], redM[1][rloc]));
                float ssum = 0.0f;
#pragma unroll
                for (int nt = 0; nt < 8; nt++) {
                    const float p0 = __expf(Sacc[mt][nt][hf * 2] - mnew);
                    const float p1 = __expf(Sacc[mt][nt][hf * 2 + 1] - mnew);
                    ssum += p0 + p1;
                    __half h0, l0, h1, l1;
                    split_h(p0, h0, l0);
                    split_h(p1, h1, l1);
                    const uint32_t off = SWZ(rloc * 128 + (nt * 8 + (lane & 3) * 2) * 2);
                    *reinterpret_cast<__half2*>(smem + ng * 16384 + off) = __half2(h0, h1);
                    *reinterpret_cast<__half2*>(smem + 32768 + ng * 16384 + off) = __half2(l0, l1);
                }
                ssum += __shfl_xor_sync(0xFFFFFFFFu, ssum, 1);
                ssum += __shfl_xor_sync(0xFFFFFFFFu, ssum, 2);
                if ((lane & 3) == 0) redS[ng][rloc] = ssum;
                const float sc = __expf(mrow[mt][hf] - mnew);
#pragma unroll
                for (int nt = 0; nt < 8; nt++) {
                    Oacc[mt][nt][hf * 2] *= sc;
                    Oacc[mt][nt][hf * 2 + 1] *= sc;
                }
                lrow[mt][hf] *= sc;
                mrow[mt][hf] = mnew;
            }
        __syncthreads();

        // ---- pass C: finish l ----
#pragma unroll
        for (int mt = 0; mt < 2; mt++)
#pragma unroll
            for (int hf = 0; hf < 2; hf++) {
                const int rloc = wm + mt * 16 + (lane >> 2) + hf * 8;
                lrow[mt][hf] += redS[0][rloc] + redS[1][rloc];
            }

        // ---- P @ V (2-pass: Ph, Pl), accumulate into Oacc ----
        CP_WAIT0();
        __syncthreads();
        const int rl = lane & 15;
        const int kb = lane >> 4;
#pragma unroll
        for (int c = 0; c < 2; c++) {
#pragma unroll
            for (int k16 = 0; k16 < 4; k16++) {
                const int kbyte = k16 * 32 + kb * 16;
                uint32_t pfh[2][4], pfl[2][4], vf[4][4];
#pragma unroll
                for (int mt = 0; mt < 2; mt++) {
                    const uint32_t off = SWZ((wm + mt * 16 + rl) * 128 + kbyte);
                    LDSM4(pfh[mt], sb + c * 16384 + off);
                    LDSM4(pfl[mt], sb + 32768 + c * 16384 + off);
                }
#pragma unroll
                for (int q = 0; q < 4; q++) {
                    const uint32_t off = SWZ((wn + q * 16 + rl) * 128 + kbyte);
                    LDSM4(vf[q], sb + 131072 + c * 16384 + off);
                }
#pragma unroll
                for (int mt = 0; mt < 2; mt++)
#pragma unroll
                    for (int nt = 0; nt < 8; nt++) {
                        const int q = nt >> 1, s = nt & 1;
                        MMA_F16(Oacc[mt][nt], pfh[mt], vf[q][s], vf[q][s + 2]);
                        MMA_F16(Oacc[mt][nt], pfl[mt], vf[q][s], vf[q][s + 2]);
                    }
            }
        }
        __syncthreads();   // protect P/V smem before next jt's loads
    }

    // ---- epilogue: normalize and write ctx fp16 ----
#pragma unroll
    for (int mt = 0; mt < 2; mt++)
#pragma unroll
        for (int hf = 0; hf < 2; hf++) {
            const int row = m0 + wm + mt * 16 + (lane >> 2) + hf * 8;
            const float inv = 1.0f / lrow[mt][hf];
#pragma unroll
            for (int nt = 0; nt < 8; nt++) {
                const int col = wn + nt * 8 + (lane & 3) * 2;
                const size_t o = (size_t)row * CTX_D + (size_t)h * DV + col;
                *reinterpret_cast<__half2*>(ch + o) =
                    __half2(__float2half_rn(Oacc[mt][nt][hf * 2] * inv),
                            __float2half_rn(Oacc[mt][nt][hf * 2 + 1] * inv));
            }
        }
}

// ---------------- weight converts ----------------
__global__ void conv_w2(const float* __restrict__ W, __half* __restrict__ Th, int K, int N)
{
    __shared__ float t[64][33];
    const int k0 = blockIdx.x * 64, n0 = blockIdx.y * 32;
    const int tx = threadIdx.x, ty = threadIdx.y;
#pragma unroll
    for (int i = 0; i < 8; i++)
        t[ty + i * 8][tx] = W[(size_t)(k0 + ty + i * 8) * N + n0 + tx];
    __syncthreads();
#pragma unroll
    for (int i = 0; i < 4; i++) {
        const int n = n0 + ty + i * 8;
        const int cidx = ty + i * 8;
        __half2 v = __half2(__float2half_rn(t[tx * 2][cidx]),
                            __float2half_rn(t[tx * 2 + 1][cidx]));
        *reinterpret_cast<__half2*>(Th + (size_t)n * K + k0 + tx * 2) = v;
    }
}

__global__ void conv_w_split(const float* __restrict__ W, __half* __restrict__ Th,
                             __half* __restrict__ Tl, int K, int N)
{
    __shared__ float t[32][33];
    const int k0 = blockIdx.x * 32, n0 = blockIdx.y * 32;
    const int tx = threadIdx.x, ty = threadIdx.y;
#pragma unroll
    for (int i = 0; i < 4; i++) {
        const int k = k0 + ty + i * 8;
        const int n = n0 + tx;
        t[ty + i * 8][tx] = (n < N) ? W[(size_t)k * N + n] : 0.0f;
    }
    __syncthreads();
#pragma unroll
    for (int i = 0; i < 4; i++) {
        __half h, l;
        split_h(t[tx][ty + i * 8], h, l);
        Th[(size_t)(n0 + ty + i * 8) * K + k0 + tx] = h;
        Tl[(size_t)(n0 + ty + i * 8) * K + k0 + tx] = l;
    }
}

// ---------------- activation convert ----------------
__global__ void conv_a(const float* __restrict__ A, __half* __restrict__ H,
                       __half* __restrict__ L, int n4)
{
    const int i = blockIdx.x * blockDim.x + threadIdx.x;
    if (i >= n4) return;
    const float4 v = reinterpret_cast<const float4*>(A)[i];
    __half h0, l0, h1, l1, h2, l2, h3, l3;
    split_h(v.x, h0, l0); split_h(v.y, h1, l1);
    split_h(v.z, h2, l2); split_h(v.w, h3, l3);
    __half2* Hp = reinterpret_cast<__half2*>(H) + i * 2;
    __half2* Lp = reinterpret_cast<__half2*>(L) + i * 2;
    Hp[0] = __half2(h0, h1); Hp[1] = __half2(h2, h3);
    Lp[0] = __half2(l0, l1); Lp[1] = __half2(l2, l3);
}

// ---------------- rmsnorm fused to fp16 hi/lo ----------------
__global__ void rmsnorm_h(const float* __restrict__ x, const float* __restrict__ gamma,
                          __half* __restrict__ yh, __half* __restrict__ yl,
                          int D, int xstride)
{
    const int row = blockIdx.x;
    const float* xr = x + (size_t)row * xstride;
    float s = 0.0f;
    for (int i = threadIdx.x; i < D; i += 256) { const float v = xr[i]; s += v * v; }
    __shared__ float red[256];
    red[threadIdx.x] = s;
    __syncthreads();
    for (int o = 128; o > 0; o >>= 1) {
        if (threadIdx.x < o) red[threadIdx.x] += red[threadIdx.x + o];
        __syncthreads();
    }
    const float inv = rsqrtf(red[0] / (float)D + 1e-6f);
    for (int i = threadIdx.x; i < D; i += 256) {
        __half h, l;
        split_h(xr[i] * inv * gamma[i], h, l);
        yh[(size_t)row * D + i] = h;
        yl[(size_t)row * D + i] = l;
    }
}

// ---------------- k_pe RoPE ----------------
__global__ void rope_k_kernel(const float* __restrict__ comp, float* __restrict__ kpe)
{
    const int t = blockIdx.x * blockDim.x + threadIdx.x;
    if (t >= S_LEN * 32) return;
    const int d = t & 31;
    const int s = t >> 5;
    float c, sn;
    rope_cs(s, d, c, sn);
    const float* src = comp + (size_t)s * COMP_D + QLORA + KVLORA;
    const float x1 = src[d], x2 = src[d + 32];
    kpe[s * DR + d]      = x1 * c - x2 * sn;
    kpe[s * DR + d + 32] = x2 * c + x1 * sn;
}

// ---------------- broadcast roped k_pe into per-head K cols 128..191 -----------
__global__ void fill_kpe(const float* __restrict__ kpe,
                         __half* __restrict__ Kh, __half* __restrict__ Kl)
{
    const int t = blockIdx.x * blockDim.x + threadIdx.x;
    if (t >= NH * S_LEN * 32) return;
    const int d2 = t & 31;
    const int j  = (t >> 5) & (S_LEN - 1);
    const int h  = t >> 15;
    const int d = d2 * 2;
    __half h0, l0, h1, l1;
    split_h(kpe[j * DR + d], h0, l0);
    split_h(kpe[j * DR + d + 1], h1, l1);
    const size_t o = ((size_t)h * S_LEN + j) * DQK + 128 + d;
    *reinterpret_cast<__half2*>(Kh + o) = __half2(h0, h1);
    *reinterpret_cast<__half2*>(Kl + o) = __half2(l0, l1);
}

// ---------------- build V^T per head (transpose, single fp16) ----------------
__global__ void build_vt(const float* __restrict__ kv, __half* __restrict__ Vth)
{
    __shared__ float t[32][33];
    const int j0 = blockIdx.x * 32, d0 = blockIdx.y * 32, h = blockIdx.z;
    const int tx = threadIdx.x, ty = threadIdx.y;
#pragma unroll
    for (int i = 0; i < 4; i++)
        t[ty + i * 8][tx] = kv[(size_t)(j0 + ty + i * 8) * KVD + h * 256 + 128 + d0 + tx];
    __syncthreads();
    const size_t base = (size_t)h * DV * S_LEN;
#pragma unroll
    for (int i = 0; i < 4; i++)
        Vth[base + (size_t)(d0 + ty + i * 8) * S_LEN + j0 + tx] =
            __float2half_rn(t[tx][ty + i * 8]);
}

// ---------------- launch ----------------
extern "C" void kernel_launch(void* const* d_in, const int* in_sizes, int n_in,
                              void* d_out, int out_size)
{
    const float* hs       = (const float*)d_in[0];
    const float* w_kv_a   = (const float*)d_in[1];
    const float* q_gamma  = (const float*)d_in[2];
    const float* kv_gamma = (const float*)d_in[3];
    const float* w_q_b    = (const float*)d_in[4];
    const float* w_kv_b   = (const float*)d_in[5];
    const float* w_o      = (const float*)d_in[6];
    float* out = (float*)d_out;

    float *comp, *kv, *kpe, *part;
    __half *ah, *al, *wah, *wal, *wq, *wkv, *wo, *qh, *ql, *kh, *kl, *vth;
    cudaGetSymbolAddress((void**)&comp, g_comp);
    cudaGetSymbolAddress((void**)&ah,   g_ah);
    cudaGetSymbolAddress((void**)&al,   g_al);
    cudaGetSymbolAddress((void**)&wah,  g_wa_h);
    cudaGetSymbolAddress((void**)&wal,  g_wa_l);
    cudaGetSymbolAddress((void**)&wq,   g_wq);
    cudaGetSymbolAddress((void**)&wkv,  g_wkv);
    cudaGetSymbolAddress((void**)&wo,   g_wo);
    cudaGetSymbolAddress((void**)&kv,   g_kv);
    cudaGetSymbolAddress((void**)&kpe,  g_kpe);
    cudaGetSymbolAddress((void**)&part, g_part);
    cudaGetSymbolAddress((void**)&qh,   g_qh);
    cudaGetSymbolAddress((void**)&ql,   g_ql);
    cudaGetSymbolAddress((void**)&kh,   g_kh);
    cudaGetSymbolAddress((void**)&kl,   g_kl);
    cudaGetSymbolAddress((void**)&vth,  g_vth);

    cudaFuncSetAttribute(mma_gemm3, cudaFuncAttributeMaxDynamicSharedMemorySize, 196608);
    cudaFuncSetAttribute(mma_gemm_q, cudaFuncAttributeMaxDynamicSharedMemorySize, 147456);
    cudaFuncSetAttribute(mma_gemm_kv, cudaFuncAttributeMaxDynamicSharedMemorySize, 147456);
    cudaFuncSetAttribute(mma_gemm1, cudaFuncAttributeMaxDynamicSharedMemorySize, 131072);
    cudaFuncSetAttribute(flash_mma, cudaFuncAttributeMaxDynamicSharedMemorySize, 163840);
    const dim3 T256(256);
    const dim3 TW(32, 8);

    // side stream + events (created per call; never destroyed)
    cudaStream_t s2;
    cudaStreamCreateWithFlags(&s2, cudaStreamNonBlocking);
    cudaEvent_t evFork, evA, evQ, evKV, evO, evComp, evKpe;
    cudaEventCreateWithFlags(&evFork, cudaEventDisableTiming);
    cudaEventCreateWithFlags(&evA,    cudaEventDisableTiming);
    cudaEventCreateWithFlags(&evQ,    cudaEventDisableTiming);
    cudaEventCreateWithFlags(&evKV,   cudaEventDisableTiming);
    cudaEventCreateWithFlags(&evO,    cudaEventDisableTiming);
    cudaEventCreateWithFlags(&evComp, cudaEventDisableTiming);
    cudaEventCreateWithFlags(&evKpe,  cudaEventDisableTiming);

    cudaEventRecord(evFork, 0);
    cudaStreamWaitEvent(s2, evFork, 0);

    // side stream: activation split + independent weight conversions
    conv_a<<<(S_LEN * HID_D / 4 + 255) / 256, 256, 0, s2>>>(hs, ah, al, S_LEN * HID_D / 4);
    cudaEventRecord(evA, s2);
    conv_w2<<<dim3(QLORA / 64, QD / 32), TW, 0, s2>>>(w_q_b, wq, QLORA, QD);
    cudaEventRecord(evQ, s2);
    conv_w2<<<dim3(KVLORA / 64, KVD / 32), TW, 0, s2>>>(w_kv_b, wkv, KVLORA, KVD);
    cudaEventRecord(evKV, s2);
    conv_w2<<<dim3(CTX_D / 64, HID_D / 32), TW, 0, s2>>>(w_o, wo, CTX_D, HID_D);
    cudaEventRecord(evO, s2);

    // main stream
    // 1) comp = hs @ w_kv_a  (3-pass; N pad 2176)
    conv_w_split<<<dim3(HID_D / 32, 2176 / 32), TW>>>(w_kv_a, wah, wal, HID_D, COMP_D);
    cudaStreamWaitEvent(0, evA, 0);
    mma_gemm3<<<dim3(17, 8), T256, 196608>>>(ah, al, wah, wal, comp, COMP_D, HID_D);
    cudaEventRecord(evComp, 0);

    // side stream: k_pe RoPE + per-head broadcast (parallel with q GEMM)
    cudaStreamWaitEvent(s2, evComp, 0);
    rope_k_kernel<<<(S_LEN * 32) / 256, 256, 0, s2>>>(comp, kpe);
    fill_kpe<<<(NH * S_LEN * 32) / 256, 256, 0, s2>>>(kpe, kh, kl);
    cudaEventRecord(evKpe, s2);

    // 2) q = rmsnorm(q_c) @ w_q_b, fused RoPE+split -> per-head Qh/Ql
    rmsnorm_h<<<S_LEN, 256>>>(comp, q_gamma, ah, al, QLORA, COMP_D);
    cudaStreamWaitEvent(0, evQ, 0);
    mma_gemm_q<<<dim3(QD / 128, 8), T256, 147456>>>(ah, al, wq, qh, ql);

    // 3) kv = rmsnorm(kv_c) @ w_kv_b, fused split -> Kh/Kl (nope) + kv fp32 (v)
    rmsnorm_h<<<S_LEN, 256>>>(comp + QLORA, kv_gamma, ah, al, KVLORA, COMP_D);
    cudaStreamWaitEvent(0, evKV, 0);
    mma_gemm_kv<<<dim3(KVD / 128, 8), T256, 147456>>>(ah, al, wkv, kh, kl, kv);
    build_vt<<<dim3(32, 4, NH), TW>>>(kv, vth);

    // 4) fused flash attention -> ctx fp16 in ah
    cudaStreamWaitEvent(0, evKpe, 0);
    flash_mma<<<dim3(NH, 8), T256, 163840>>>(qh, ql, kh, kl, vth, ah);

    // 5) out = ctx @ w_o  (1-pass, K-split x2) ; out += part
    cudaStreamWaitEvent(0, evO, 0);
    mma_gemm1<<<dim3(HID_D / 128, 8, 2), T256, 131072>>>(ah, wo, out, part, HID_D, CTX_D);
    add_out<<<S_LEN * HID_D / 4 / 256, 256>>>(out, part);
}

// round 10
// speedup vs baseline: 1.0423x; 1.0423x over previous
#include <cuda_runtime.h>
#include <cuda_fp16.h>
#include <math.h>
#include <stdint.h>

// ---------------- problem constants ----------------
#define S_LEN 1024
#define HID_D 7168
#define NH 128
#define DN 128
#define DR 64
#define DV 128
#define QLORA 1536
#define KVLORA 512
#define COMP_D (QLORA + KVLORA + DR)      // 2112
#define QD (NH * (DN + DR))               // 24576
#define KVD (NH * (DN + DV))              // 32768
#define CTX_D (NH * DV)                   // 16384
#define DQK 192

// ---------------- scratch (device globals) ----------------
__device__ float g_comp[S_LEN * COMP_D];
__device__ __half g_ah[(size_t)S_LEN * 16384];                   // activations hi (also ctx)
__device__ __half g_al[(size_t)S_LEN * 16384];                   // activations lo
__device__ __half g_wa_h[15597568];                              // w_kv_a hi (2176*7168)
__device__ __half g_wa_l[15597568];                              // w_kv_a lo
__device__ __half g_wq[(size_t)QD * QLORA];                      // w_q_b^T
__device__ __half g_wkv[(size_t)KVD * KVLORA];                   // w_kv_b^T
__device__ __half g_wo[(size_t)HID_D * CTX_D];                   // w_o^T
__device__ float g_kv[(size_t)S_LEN * KVD];                      // v half only used
__device__ float g_kpe[S_LEN * DR];
__device__ __half g_qh[(size_t)NH * S_LEN * DQK];
__device__ __half g_ql[(size_t)NH * S_LEN * DQK];
__device__ __half g_kh[(size_t)NH * S_LEN * DQK];
__device__ __half g_kl[(size_t)NH * S_LEN * DQK];
__device__ __half g_vth[(size_t)NH * DV * S_LEN];

// ---------------- PTX helpers ----------------
__device__ __forceinline__ uint32_t smem_u32(const void* p) {
    uint32_t a;
    asm("{ .reg .u64 t; cvta.to.shared.u64 t, %1; cvt.u32.u64 %0, t; }" : "=r"(a) : "l"(p));
    return a;
}
#define CP16(dst, src) \
    asm volatile("cp.async.cg.shared.global [%0], [%1], 16;" :: "r"(dst), "l"(src) : "memory")
#define CP_COMMIT() asm volatile("cp.async.commit_group;" ::: "memory")
#define CP_WAIT1() asm volatile("cp.async.wait_group 1;" ::: "memory")
#define CP_WAIT0() asm volatile("cp.async.wait_group 0;" ::: "memory")

#define LDSM4(r, a) \
    asm volatile("ldmatrix.sync.aligned.m8n8.x4.shared.b16 {%0,%1,%2,%3}, [%4];" \
        : "=r"((r)[0]), "=r"((r)[1]), "=r"((r)[2]), "=r"((r)[3]) : "r"(a))

#define MMA_F16(d, a, b0, b1) \
    asm volatile("mma.sync.aligned.m16n8k16.row.col.f32.f16.f16.f32 " \
        "{%0,%1,%2,%3}, {%4,%5,%6,%7}, {%8,%9}, {%0,%1,%2,%3};" \
        : "+f"((d)[0]), "+f"((d)[1]), "+f"((d)[2]), "+f"((d)[3]) \
        : "r"((a)[0]), "r"((a)[1]), "r"((a)[2]), "r"((a)[3]), "r"(b0), "r"(b1))

#define SWZ(o) ((o) ^ (((o) >> 3) & 0x70))

__device__ __forceinline__ void split_h(float v, __half& h, __half& l) {
    h = __float2half_rn(v);
    l = __float2half_rn(v - __half2float(h));
}

// ---------------- shared GEMM body (R8-proven 2-stage pipeline) ----------------
// NPASS=1: ah*bh        NPASS=2: ah*bh + al*bh        NPASS=3: + ah*bl
template <int NPASS>
__device__ __forceinline__ void gemm_body(
    const __half* __restrict__ Ah, const __half* __restrict__ Al,
    const __half* __restrict__ Bh, const __half* __restrict__ Bl,
    int K, int nch, int m0, int n0, uint32_t sb, int tid, float acc[2][8][4])
{
    constexpr int CA = (NPASS >= 2) ? 2 : 1;
    constexpr int CB = (NPASS == 3) ? 2 : 1;
    constexpr int NT = CA + CB;
    constexpr int STAGE = NT * 16384;
    const int lane = tid & 31;
    const int wid = tid >> 5;
    const int wm = (wid & 3) * 32;
    const int wn = (wid >> 2) * 64;

    auto load_stage = [&](int c, int s) {
        const int kc = c << 6;
#pragma unroll
        for (int it = 0; it < NT * 4; it++) {
            const int t = tid + it * 256;
            const int tensor = t >> 10;
            const int rem = t & 1023;
            const int row = rem >> 3;
            const int ch = rem & 7;
            const __half* src;
            int grow;
            if (tensor < CA) {
                src = (CA == 2 && tensor == 1) ? Al : Ah;
                grow = m0 + row;
            } else {
                src = (CB == 2 && tensor == CA + 1) ? Bl : Bh;
                grow = n0 + row;
            }
            const __half* sp = src + (size_t)grow * K + kc + ch * 8;
            const uint32_t dst = sb + s * STAGE + tensor * 16384 + SWZ(row * 128 + ch * 16);
            CP16(dst, sp);
        }
        CP_COMMIT();
    };

    load_stage(0, 0);

    for (int c = 0; c < nch; c++) {
        const int buf = c & 1;
        if (c + 1 < nch) { load_stage(c + 1, buf ^ 1); CP_WAIT1(); }
        else             { CP_WAIT0(); }
        __syncthreads();

        const uint32_t st = sb + buf * STAGE;
        const uint32_t sA_h = st;
        const uint32_t sA_l = st + 16384;
        const uint32_t sB_h = st + CA * 16384;
        const uint32_t sB_l = sB_h + 16384;
        const int rl = lane & 15;
        const int kb = lane >> 4;

#pragma unroll
        for (int k16 = 0; k16 < 4; k16++) {
            const int kbyte = k16 * 32 + kb * 16;
            uint32_t afh[2][4], afl[2][4], bfh[4][4], bfl[4][4];
#pragma unroll
            for (int mt = 0; mt < 2; mt++) {
                const uint32_t off = SWZ((wm + mt * 16 + rl) * 128 + kbyte);
                LDSM4(afh[mt], sA_h + off);
                if (CA == 2) LDSM4(afl[mt], sA_l + off);
            }
#pragma unroll
            for (int q = 0; q < 4; q++) {
                const uint32_t off = SWZ((wn + q * 16 + rl) * 128 + kbyte);
                LDSM4(bfh[q], sB_h + off);
                if (CB == 2) LDSM4(bfl[q], sB_l + off);
            }
#pragma unroll
            for (int mt = 0; mt < 2; mt++)
#pragma unroll
                for (int nt = 0; nt < 8; nt++) {
                    const int q = nt >> 1, s = nt & 1;
                    MMA_F16(acc[mt][nt], afh[mt], bfh[q][s], bfh[q][s + 2]);
                    if (CA == 2) MMA_F16(acc[mt][nt], afl[mt], bfh[q][s], bfh[q][s + 2]);
                    if (CB == 2) MMA_F16(acc[mt][nt], afh[mt], bfl[q][s], bfl[q][s + 2]);
                }
        }
        __syncthreads();
    }
}

#define GEMM_PROLOGUE() \
    extern __shared__ __align__(128) char smem[]; \
    const uint32_t sb = smem_u32(smem); \
    const int tid = threadIdx.x; \
    const int lane = tid & 31; \
    const int wid = tid >> 5; \
    const int m0 = blockIdx.y * 128, n0 = blockIdx.x * 128; \
    const int wm = (wid & 3) * 32, wn = (wid >> 2) * 64; \
    float acc[2][8][4]; \
    _Pragma("unroll") for (int mt = 0; mt < 2; mt++) \
    _Pragma("unroll") for (int nt = 0; nt < 8; nt++) \
    _Pragma("unroll") for (int e = 0; e < 4; e++) acc[mt][nt][e] = 0.0f;

// ---------------- comp GEMM: 3-pass, fp32 out ----------------
__global__ __launch_bounds__(256, 1) void mma_gemm3(
    const __half* __restrict__ Ah, const __half* __restrict__ Al,
    const __half* __restrict__ Bh, const __half* __restrict__ Bl,
    float* __restrict__ C, int N, int K)
{
    GEMM_PROLOGUE();
    gemm_body<3>(Ah, Al, Bh, Bl, K, K >> 6, m0, n0, sb, tid, acc);
#pragma unroll
    for (int mt = 0; mt < 2; mt++) {
        const int row = m0 + wm + mt * 16 + (lane >> 2);
#pragma unroll
        for (int nt = 0; nt < 8; nt++) {
            const int col = n0 + wn + nt * 8 + (lane & 3) * 2;
            if (col < N) {
                *reinterpret_cast<float2*>(C + (size_t)row * N + col) =
                    make_float2(acc[mt][nt][0], acc[mt][nt][1]);
                *reinterpret_cast<float2*>(C + (size_t)(row + 8) * N + col) =
                    make_float2(acc[mt][nt][2], acc[mt][nt][3]);
            }
        }
    }
}

// ---------------- w_o GEMM: 1-pass, fp32 out ----------------
__global__ __launch_bounds__(256, 1) void mma_gemm1(
    const __half* __restrict__ Ah, const __half* __restrict__ Bh,
    float* __restrict__ C, int N, int K)
{
    GEMM_PROLOGUE();
    gemm_body<1>(Ah, nullptr, Bh, nullptr, K, K >> 6, m0, n0, sb, tid, acc);
#pragma unroll
    for (int mt = 0; mt < 2; mt++) {
        const int row = m0 + wm + mt * 16 + (lane >> 2);
#pragma unroll
        for (int nt = 0; nt < 8; nt++) {
            const int col = n0 + wn + nt * 8 + (lane & 3) * 2;
            *reinterpret_cast<float2*>(C + (size_t)row * N + col) =
                make_float2(acc[mt][nt][0], acc[mt][nt][1]);
            *reinterpret_cast<float2*>(C + (size_t)(row + 8) * N + col) =
                make_float2(acc[mt][nt][2], acc[mt][nt][3]);
        }
    }
}

// ---------------- RoPE angle ----------------
__device__ __forceinline__ void rope_cs(int s, int d, float& c, float& sn)
{
    const float inv = exp2f(-(float)d * (13.287712379549449f / 32.0f));
    sincosf((float)s * inv, &sn, &c);
}

// ---------------- q GEMM: 2-pass, fused RoPE + split, per-head layout -----------
__global__ __launch_bounds__(256, 1) void mma_gemm_q(
    const __half* __restrict__ Ah, const __half* __restrict__ Al,
    const __half* __restrict__ Bh,
    __half* __restrict__ Qh, __half* __restrict__ Ql)
{
    GEMM_PROLOGUE();
    gemm_body<2>(Ah, Al, Bh, nullptr, QLORA, QLORA >> 6, m0, n0, sb, tid, acc);

    const int base64 = n0 + wn;
    if ((base64 / 64) % 3 != 2) {
#pragma unroll
        for (int mt = 0; mt < 2; mt++)
#pragma unroll
            for (int half_i = 0; half_i < 2; half_i++) {
                const int row = m0 + wm + mt * 16 + (lane >> 2) + half_i * 8;
#pragma unroll
                for (int nt = 0; nt < 8; nt++) {
                    const int c = base64 + nt * 8 + (lane & 3) * 2;
                    const int h = c / 192;
                    const int cr = c - h * 192;
                    const size_t o = ((size_t)h * S_LEN + row) * DQK + cr;
                    __half h0, l0, h1, l1;
                    split_h(acc[mt][nt][half_i * 2], h0, l0);
                    split_h(acc[mt][nt][half_i * 2 + 1], h1, l1);
                    *reinterpret_cast<__half2*>(Qh + o) = __half2(h0, h1);
                    *reinterpret_cast<__half2*>(Ql + o) = __half2(l0, l1);
                }
            }
    } else {
        const int h = base64 / 192;
#pragma unroll
        for (int mt = 0; mt < 2; mt++)
#pragma unroll
            for (int half_i = 0; half_i < 2; half_i++) {
                const int row = m0 + wm + mt * 16 + (lane >> 2) + half_i * 8;
                const size_t rb = ((size_t)h * S_LEN + row) * DQK + 128;
#pragma unroll
                for (int ntL = 0; ntL < 4; ntL++) {
                    const int d0 = ntL * 8 + (lane & 3) * 2;
                    float o0[2], o1[2];
#pragma unroll
                    for (int e = 0; e < 2; e++) {
                        float cc, ss;
                        rope_cs(row, d0 + e, cc, ss);
                        const float v1 = acc[mt][ntL][half_i * 2 + e];
                        const float v2 = acc[mt][ntL + 4][half_i * 2 + e];
                        o0[e] = v1 * cc - v2 * ss;
                        o1[e] = v2 * cc + v1 * ss;
                    }
                    __half h0, l0, h1, l1;
                    split_h(o0[0], h0, l0); split_h(o0[1], h1, l1);
                    *reinterpret_cast<__half2*>(Qh + rb + d0) = __half2(h0, h1);
                    *reinterpret_cast<__half2*>(Ql + rb + d0) = __half2(l0, l1);
                    split_h(o1[0], h0, l0); split_h(o1[1], h1, l1);
                    *reinterpret_cast<__half2*>(Qh + rb + d0 + 32) = __half2(h0, h1);
                    *reinterpret_cast<__half2*>(Ql + rb + d0 + 32) = __half2(l0, l1);
                }
            }
    }
}

// ---------------- kv GEMM: 2-pass, k_nope -> split per-head; v -> fp32 ----------
__global__ __launch_bounds__(256, 1) void mma_gemm_kv(
    const __half* __restrict__ Ah, const __half* __restrict__ Al,
    const __half* __restrict__ Bh,
    __half* __restrict__ Kh, __half* __restrict__ Kl, float* __restrict__ kv)
{
    GEMM_PROLOGUE();
    gemm_body<2>(Ah, Al, Bh, nullptr, KVLORA, KVLORA >> 6, m0, n0, sb, tid, acc);

    const int base64 = n0 + wn;
    const int blk4 = (base64 / 64) & 3;
    if (blk4 < 2) {
        const int h = base64 / 256;
#pragma unroll
        for (int mt = 0; mt < 2; mt++)
#pragma unroll
            for (int half_i = 0; half_i < 2; half_i++) {
                const int row = m0 + wm + mt * 16 + (lane >> 2) + half_i * 8;
#pragma unroll
                for (int nt = 0; nt < 8; nt++) {
                    const int c = base64 + nt * 8 + (lane & 3) * 2;
                    const int cr = c - h * 256;
                    const size_t o = ((size_t)h * S_LEN + row) * DQK + cr;
                    __half h0, l0, h1, l1;
                    split_h(acc[mt][nt][half_i * 2], h0, l0);
                    split_h(acc[mt][nt][half_i * 2 + 1], h1, l1);
                    *reinterpret_cast<__half2*>(Kh + o) = __half2(h0, h1);
                    *reinterpret_cast<__half2*>(Kl + o) = __half2(l0, l1);
                }
            }
    } else {
#pragma unroll
        for (int mt = 0; mt < 2; mt++) {
            const int row = m0 + wm + mt * 16 + (lane >> 2);
#pragma unroll
            for (int nt = 0; nt < 8; nt++) {
                const int c = base64 + nt * 8 + (lane & 3) * 2;
                *reinterpret_cast<float2*>(kv + (size_t)row * KVD + c) =
                    make_float2(acc[mt][nt][0], acc[mt][nt][1]);
                *reinterpret_cast<float2*>(kv + (size_t)(row + 8) * KVD + c) =
                    make_float2(acc[mt][nt][2], acc[mt][nt][3]);
            }
        }
    }
}

// ---------------- fused flash attention per (head, i-tile) ----------------
// smem: [0,128K) gemm stages (P hi reuses [0,32K) after S phase), [128K,160K) V
__global__ __launch_bounds__(256, 1) void flash_mma(
    const __half* __restrict__ Qh, const __half* __restrict__ Ql,
    const __half* __restrict__ Kh, const __half* __restrict__ Kl,
    const __half* __restrict__ Vth, __half* __restrict__ ch)
{
    extern __shared__ __align__(128) char smem[];
    __shared__ float redM[2][128];
    __shared__ float redS[2][128];
    const uint32_t sb = smem_u32(smem);
    const int tid = threadIdx.x;
    const int lane = tid & 31;
    const int wid = tid >> 5;
    const int h = blockIdx.x;
    const int it = 7 - blockIdx.y;          // heavy tiles first
    const int m0 = it * 128;
    const int wm = (wid & 3) * 32, wn = (wid >> 2) * 64;
    const int ng = wid >> 2;
    const size_t hoff = (size_t)h * S_LEN * DQK;
    const size_t voff = (size_t)h * DV * S_LEN;
    const float scale = 0.07216878364870323f;   // 1/sqrt(192)

    float Oacc[2][8][4];
    float mrow[2][2], lrow[2][2];
#pragma unroll
    for (int mt = 0; mt < 2; mt++)
#pragma unroll
        for (int nt = 0; nt < 8; nt++)
#pragma unroll
            for (int e = 0; e < 4; e++) Oacc[mt][nt][e] = 0.0f;
#pragma unroll
    for (int mt = 0; mt < 2; mt++)
#pragma unroll
        for (int hf = 0; hf < 2; hf++) { mrow[mt][hf] = -3.4e38f; lrow[mt][hf] = 0.0f; }

    for (int jt = 0; jt <= it; jt++) {
        // ---- S = Q @ K^T (3-pass split) ----
        float Sacc[2][8][4];
#pragma unroll
        for (int mt = 0; mt < 2; mt++)
#pragma unroll
            for (int nt = 0; nt < 8; nt++)
#pragma unroll
                for (int e = 0; e < 4; e++) Sacc[mt][nt][e] = 0.0f;

        gemm_body<3>(Qh + hoff, Ql + hoff, Kh + hoff, Kl + hoff,
                     DQK, 3, m0, jt * 128, sb, tid, Sacc);

        // ---- prefetch V tile (2 chunks of [128 d][64 j]) ----
#pragma unroll
        for (int itv = 0; itv < 8; itv++) {
            const int t = tid + itv * 256;
            const int c = t >> 10;
            const int rem = t & 1023;
            const int d = rem >> 3;
            const int seg = rem & 7;
            const __half* sp = Vth + voff + (size_t)d * S_LEN + jt * 128 + c * 64 + seg * 8;
            CP16(sb + 131072 + c * 16384 + SWZ(d * 128 + seg * 16), sp);
        }
        CP_COMMIT();

        // ---- pass A: scale + mask + row max ----
#pragma unroll
        for (int mt = 0; mt < 2; mt++)
#pragma unroll
            for (int hf = 0; hf < 2; hf++) {
                const int rloc = wm + mt * 16 + (lane >> 2) + hf * 8;
                float mx = -3.4e38f;
#pragma unroll
                for (int nt = 0; nt < 8; nt++)
#pragma unroll
                    for (int e = 0; e < 2; e++) {
                        float s = Sacc[mt][nt][hf * 2 + e] * scale;
                        if (jt == it) {
                            const int cg = jt * 128 + wn + nt * 8 + (lane & 3) * 2 + e;
                            if (cg > m0 + rloc) s = -3.4e38f;
                        }
                        Sacc[mt][nt][hf * 2 + e] = s;
                        mx = fmaxf(mx, s);
                    }
                mx = fmaxf(mx, __shfl_xor_sync(0xFFFFFFFFu, mx, 1));
                mx = fmaxf(mx, __shfl_xor_sync(0xFFFFFFFFu, mx, 2));
                if ((lane & 3) == 0) redM[ng][rloc] = mx;
            }
        __syncthreads();

        // ---- pass B: exp, write P (single fp16) to smem, row sums, O rescale ----
#pragma unroll
        for (int mt = 0; mt < 2; mt++)
#pragma unroll
            for (int hf = 0; hf < 2; hf++) {
                const int rloc = wm + mt * 16 + (lane >> 2) + hf * 8;
                const float mnew = fmaxf(mrow[mt][hf],
                                         fmaxf(redM[0][rloc], redM[1][rloc]));
                float ssum = 0.0f;
#pragma unroll
                for (int nt = 0; nt < 8; nt++) {
                    const float p0 = __expf(Sacc[mt][nt][hf * 2] - mnew);
                    const float p1 = __expf(Sacc[mt][nt][hf * 2 + 1] - mnew);
                    ssum += p0 + p1;
                    const uint32_t off = SWZ(rloc * 128 + (nt * 8 + (lane & 3) * 2) * 2);
                    *reinterpret_cast<__half2*>(smem + ng * 16384 + off) =
                        __half2(__float2half_rn(p0), __float2half_rn(p1));
                }
                ssum += __shfl_xor_sync(0xFFFFFFFFu, ssum, 1);
                ssum += __shfl_xor_sync(0xFFFFFFFFu, ssum, 2);
                if ((lane & 3) == 0) redS[ng][rloc] = ssum;
                const float sc = __expf(mrow[mt][hf] - mnew);
#pragma unroll
                for (int nt = 0; nt < 8; nt++) {
                    Oacc[mt][nt][hf * 2] *= sc;
                    Oacc[mt][nt][hf * 2 + 1] *= sc;
                }
                lrow[mt][hf] *= sc;
                mrow[mt][hf] = mnew;
            }
        __syncthreads();

        // ---- pass C: finish l ----
#pragma unroll
        for (int mt = 0; mt < 2; mt++)
#pragma unroll
            for (int hf = 0; hf < 2; hf++) {
                const int rloc = wm + mt * 16 + (lane >> 2) + hf * 8;
                lrow[mt][hf] += redS[0][rloc] + redS[1][rloc];
            }

        // ---- P @ V (single pass), accumulate into Oacc ----
        CP_WAIT0();
        __syncthreads();
        const int rl = lane & 15;
        const int kb = lane >> 4;
#pragma unroll
        for (int c = 0; c < 2; c++) {
#pragma unroll
            for (int k16 = 0; k16 < 4; k16++) {
                const int kbyte = k16 * 32 + kb * 16;
                uint32_t pfh[2][4], vf[4][4];
#pragma unroll
                for (int mt = 0; mt < 2; mt++) {
                    const uint32_t off = SWZ((wm + mt * 16 + rl) * 128 + kbyte);
                    LDSM4(pfh[mt], sb + c * 16384 + off);
                }
#pragma unroll
                for (int q = 0; q < 4; q++) {
                    const uint32_t off = SWZ((wn + q * 16 + rl) * 128 + kbyte);
                    LDSM4(vf[q], sb + 131072 + c * 16384 + off);
                }
#pragma unroll
                for (int mt = 0; mt < 2; mt++)
#pragma unroll
                    for (int nt = 0; nt < 8; nt++) {
                        const int q = nt >> 1, s = nt & 1;
                        MMA_F16(Oacc[mt][nt], pfh[mt], vf[q][s], vf[q][s + 2]);
                    }
            }
        }
        __syncthreads();   // protect P/V smem before next jt's loads
    }

    // ---- epilogue: normalize and write ctx fp16 ----
#pragma unroll
    for (int mt = 0; mt < 2; mt++)
#pragma unroll
        for (int hf = 0; hf < 2; hf++) {
            const int row = m0 + wm + mt * 16 + (lane >> 2) + hf * 8;
            const float inv = 1.0f / lrow[mt][hf];
#pragma unroll
            for (int nt = 0; nt < 8; nt++) {
                const int col = wn + nt * 8 + (lane & 3) * 2;
                const size_t o = (size_t)row * CTX_D + (size_t)h * DV + col;
                *reinterpret_cast<__half2*>(ch + o) =
                    __half2(__float2half_rn(Oacc[mt][nt][hf * 2] * inv),
                            __float2half_rn(Oacc[mt][nt][hf * 2 + 1] * inv));
            }
        }
}

// ---------------- weight converts ----------------
__global__ void conv_w2(const float* __restrict__ W, __half* __restrict__ Th, int K, int N)
{
    __shared__ float t[64][33];
    const int k0 = blockIdx.x * 64, n0 = blockIdx.y * 32;
    const int tx = threadIdx.x, ty = threadIdx.y;
#pragma unroll
    for (int i = 0; i < 8; i++)
        t[ty + i * 8][tx] = W[(size_t)(k0 + ty + i * 8) * N + n0 + tx];
    __syncthreads();
#pragma unroll
    for (int i = 0; i < 4; i++) {
        const int n = n0 + ty + i * 8;
        const int cidx = ty + i * 8;
        __half2 v = __half2(__float2half_rn(t[tx * 2][cidx]),
                            __float2half_rn(t[tx * 2 + 1][cidx]));
        *reinterpret_cast<__half2*>(Th + (size_t)n * K + k0 + tx * 2) = v;
    }
}

__global__ void conv_w_split(const float* __restrict__ W, __half* __restrict__ Th,
                             __half* __restrict__ Tl, int K, int N)
{
    __shared__ float t[32][33];
    const int k0 = blockIdx.x * 32, n0 = blockIdx.y * 32;
    const int tx = threadIdx.x, ty = threadIdx.y;
#pragma unroll
    for (int i = 0; i < 4; i++) {
        const int k = k0 + ty + i * 8;
        const int n = n0 + tx;
        t[ty + i * 8][tx] = (n < N) ? W[(size_t)k * N + n] : 0.0f;
    }
    __syncthreads();
#pragma unroll
    for (int i = 0; i < 4; i++) {
        __half h, l;
        split_h(t[tx][ty + i * 8], h, l);
        Th[(size_t)(n0 + ty + i * 8) * K + k0 + tx] = h;
        Tl[(size_t)(n0 + ty + i * 8) * K + k0 + tx] = l;
    }
}

// ---------------- activation convert ----------------
__global__ void conv_a(const float* __restrict__ A, __half* __restrict__ H,
                       __half* __restrict__ L, int n4)
{
    const int i = blockIdx.x * blockDim.x + threadIdx.x;
    if (i >= n4) return;
    const float4 v = reinterpret_cast<const float4*>(A)[i];
    __half h0, l0, h1, l1, h2, l2, h3, l3;
    split_h(v.x, h0, l0); split_h(v.y, h1, l1);
    split_h(v.z, h2, l2); split_h(v.w, h3, l3);
    __half2* Hp = reinterpret_cast<__half2*>(H) + i * 2;
    __half2* Lp = reinterpret_cast<__half2*>(L) + i * 2;
    Hp[0] = __half2(h0, h1); Hp[1] = __half2(h2, h3);
    Lp[0] = __half2(l0, l1); Lp[1] = __half2(l2, l3);
}

// ---------------- rmsnorm fused to fp16 hi/lo ----------------
__global__ void rmsnorm_h(const float* __restrict__ x, const float* __restrict__ gamma,
                          __half* __restrict__ yh, __half* __restrict__ yl,
                          int D, int xstride)
{
    const int row = blockIdx.x;
    const float* xr = x + (size_t)row * xstride;
    float s = 0.0f;
    for (int i = threadIdx.x; i < D; i += 256) { const float v = xr[i]; s += v * v; }
    __shared__ float red[256];
    red[threadIdx.x] = s;
    __syncthreads();
    for (int o = 128; o > 0; o >>= 1) {
        if (threadIdx.x < o) red[threadIdx.x] += red[threadIdx.x + o];
        __syncthreads();
    }
    const float inv = rsqrtf(red[0] / (float)D + 1e-6f);
    for (int i = threadIdx.x; i < D; i += 256) {
        __half h, l;
        split_h(xr[i] * inv * gamma[i], h, l);
        yh[(size_t)row * D + i] = h;
        yl[(size_t)row * D + i] = l;
    }
}

// ---------------- k_pe RoPE ----------------
__global__ void rope_k_kernel(const float* __restrict__ comp, float* __restrict__ kpe)
{
    const int t = blockIdx.x * blockDim.x + threadIdx.x;
    if (t >= S_LEN * 32) return;
    const int d = t & 31;
    const int s = t >> 5;
    float c, sn;
    rope_cs(s, d, c, sn);
    const float* src = comp + (size_t)s * COMP_D + QLORA + KVLORA;
    const float x1 = src[d], x2 = src[d + 32];
    kpe[s * DR + d]      = x1 * c - x2 * sn;
    kpe[s * DR + d + 32] = x2 * c + x1 * sn;
}

// ---------------- broadcast roped k_pe into per-head K cols 128..191 -----------
__global__ void fill_kpe(const float* __restrict__ kpe,
                         __half* __restrict__ Kh, __half* __restrict__ Kl)
{
    const int t = blockIdx.x * blockDim.x + threadIdx.x;
    if (t >= NH * S_LEN * 32) return;
    const int d2 = t & 31;
    const int j  = (t >> 5) & (S_LEN - 1);
    const int h  = t >> 15;
    const int d = d2 * 2;
    __half h0, l0, h1, l1;
    split_h(kpe[j * DR + d], h0, l0);
    split_h(kpe[j * DR + d + 1], h1, l1);
    const size_t o = ((size_t)h * S_LEN + j) * DQK + 128 + d;
    *reinterpret_cast<__half2*>(Kh + o) = __half2(h0, h1);
    *reinterpret_cast<__half2*>(Kl + o) = __half2(l0, l1);
}

// ---------------- build V^T per head (transpose, single fp16) ----------------
__global__ void build_vt(const float* __restrict__ kv, __half* __restrict__ Vth)
{
    __shared__ float t[32][33];
    const int j0 = blockIdx.x * 32, d0 = blockIdx.y * 32, h = blockIdx.z;
    const int tx = threadIdx.x, ty = threadIdx.y;
#pragma unroll
    for (int i = 0; i < 4; i++)
        t[ty + i * 8][tx] = kv[(size_t)(j0 + ty + i * 8) * KVD + h * 256 + 128 + d0 + tx];
    __syncthreads();
    const size_t base = (size_t)h * DV * S_LEN;
#pragma unroll
    for (int i = 0; i < 4; i++)
        Vth[base + (size_t)(d0 + ty + i * 8) * S_LEN + j0 + tx] =
            __float2half_rn(t[tx][ty + i * 8]);
}

// ---------------- launch ----------------
extern "C" void kernel_launch(void* const* d_in, const int* in_sizes, int n_in,
                              void* d_out, int out_size)
{
    const float* hs       = (const float*)d_in[0];
    const float* w_kv_a   = (const float*)d_in[1];
    const float* q_gamma  = (const float*)d_in[2];
    const float* kv_gamma = (const float*)d_in[3];
    const float* w_q_b    = (const float*)d_in[4];
    const float* w_kv_b   = (const float*)d_in[5];
    const float* w_o      = (const float*)d_in[6];
    float* out = (float*)d_out;

    float *comp, *kv, *kpe;
    __half *ah, *al, *wah, *wal, *wq, *wkv, *wo, *qh, *ql, *kh, *kl, *vth;
    cudaGetSymbolAddress((void**)&comp, g_comp);
    cudaGetSymbolAddress((void**)&ah,   g_ah);
    cudaGetSymbolAddress((void**)&al,   g_al);
    cudaGetSymbolAddress((void**)&wah,  g_wa_h);
    cudaGetSymbolAddress((void**)&wal,  g_wa_l);
    cudaGetSymbolAddress((void**)&wq,   g_wq);
    cudaGetSymbolAddress((void**)&wkv,  g_wkv);
    cudaGetSymbolAddress((void**)&wo,   g_wo);
    cudaGetSymbolAddress((void**)&kv,   g_kv);
    cudaGetSymbolAddress((void**)&kpe,  g_kpe);
    cudaGetSymbolAddress((void**)&qh,   g_qh);
    cudaGetSymbolAddress((void**)&ql,   g_ql);
    cudaGetSymbolAddress((void**)&kh,   g_kh);
    cudaGetSymbolAddress((void**)&kl,   g_kl);
    cudaGetSymbolAddress((void**)&vth,  g_vth);

    cudaFuncSetAttribute(mma_gemm3, cudaFuncAttributeMaxDynamicSharedMemorySize, 131072);
    cudaFuncSetAttribute(mma_gemm_q, cudaFuncAttributeMaxDynamicSharedMemorySize, 98304);
    cudaFuncSetAttribute(mma_gemm_kv, cudaFuncAttributeMaxDynamicSharedMemorySize, 98304);
    cudaFuncSetAttribute(mma_gemm1, cudaFuncAttributeMaxDynamicSharedMemorySize, 65536);
    cudaFuncSetAttribute(flash_mma, cudaFuncAttributeMaxDynamicSharedMemorySize, 163840);
    const dim3 T256(256);
    const dim3 TW(32, 8);

    // side stream + events (created per call; never destroyed)
    cudaStream_t s2;
    cudaStreamCreateWithFlags(&s2, cudaStreamNonBlocking);
    cudaEvent_t evFork, evA, evQ, evKV, evO, evComp, evKpe;
    cudaEventCreateWithFlags(&evFork, cudaEventDisableTiming);
    cudaEventCreateWithFlags(&evA,    cudaEventDisableTiming);
    cudaEventCreateWithFlags(&evQ,    cudaEventDisableTiming);
    cudaEventCreateWithFlags(&evKV,   cudaEventDisableTiming);
    cudaEventCreateWithFlags(&evO,    cudaEventDisableTiming);
    cudaEventCreateWithFlags(&evComp, cudaEventDisableTiming);
    cudaEventCreateWithFlags(&evKpe,  cudaEventDisableTiming);

    cudaEventRecord(evFork, 0);
    cudaStreamWaitEvent(s2, evFork, 0);

    // side stream: activation split + independent weight conversions
    conv_a<<<(S_LEN * HID_D / 4 + 255) / 256, 256, 0, s2>>>(hs, ah, al, S_LEN * HID_D / 4);
    cudaEventRecord(evA, s2);
    conv_w2<<<dim3(QLORA / 64, QD / 32), TW, 0, s2>>>(w_q_b, wq, QLORA, QD);
    cudaEventRecord(evQ, s2);
    conv_w2<<<dim3(KVLORA / 64, KVD / 32), TW, 0, s2>>>(w_kv_b, wkv, KVLORA, KVD);
    cudaEventRecord(evKV, s2);
    conv_w2<<<dim3(CTX_D / 64, HID_D / 32), TW, 0, s2>>>(w_o, wo, CTX_D, HID_D);
    cudaEventRecord(evO, s2);

    // main stream
    // 1) comp = hs @ w_kv_a  (3-pass; N pad 2176)
    conv_w_split<<<dim3(HID_D / 32, 2176 / 32), TW>>>(w_kv_a, wah, wal, HID_D, COMP_D);
    cudaStreamWaitEvent(0, evA, 0);
    mma_gemm3<<<dim3(17, 8), T256, 131072>>>(ah, al, wah, wal, comp, COMP_D, HID_D);
    cudaEventRecord(evComp, 0);

    // side stream: k_pe RoPE + per-head broadcast (parallel with q GEMM)
    cudaStreamWaitEvent(s2, evComp, 0);
    rope_k_kernel<<<(S_LEN * 32) / 256, 256, 0, s2>>>(comp, kpe);
    fill_kpe<<<(NH * S_LEN * 32) / 256, 256, 0, s2>>>(kpe, kh, kl);
    cudaEventRecord(evKpe, s2);

    // 2) q = rmsnorm(q_c) @ w_q_b, fused RoPE+split -> per-head Qh/Ql
    rmsnorm_h<<<S_LEN, 256>>>(comp, q_gamma, ah, al, QLORA, COMP_D);
    cudaStreamWaitEvent(0, evQ, 0);
    mma_gemm_q<<<dim3(QD / 128, 8), T256, 98304>>>(ah, al, wq, qh, ql);

    // 3) kv = rmsnorm(kv_c) @ w_kv_b, fused split -> Kh/Kl (nope) + kv fp32 (v)
    rmsnorm_h<<<S_LEN, 256>>>(comp + QLORA, kv_gamma, ah, al, KVLORA, COMP_D);
    cudaStreamWaitEvent(0, evKV, 0);
    mma_gemm_kv<<<dim3(KVD / 128, 8), T256, 98304>>>(ah, al, wkv, kh, kl, kv);
    build_vt<<<dim3(32, 4, NH), TW>>>(kv, vth);

    // 4) fused flash attention -> ctx fp16 in ah
    cudaStreamWaitEvent(0, evKpe, 0);
    flash_mma<<<dim3(NH, 8), T256, 163840>>>(qh, ql, kh, kl, vth, ah);

    // 5) out = ctx @ w_o  (1-pass)
    cudaStreamWaitEvent(0, evO, 0);
    mma_gemm1<<<dim3(HID_D / 128, 8), T256, 65536>>>(ah, wo, out, HID_D, CTX_D);
}

// round 11
// speedup vs baseline: 1.0963x; 1.0519x over previous
#include <cuda_runtime.h>
#include <cuda_fp16.h>
#include <math.h>
#include <stdint.h>

// ---------------- problem constants ----------------
#define S_LEN 1024
#define HID_D 7168
#define NH 128
#define DN 128
#define DR 64
#define DV 128
#define QLORA 1536
#define KVLORA 512
#define COMP_D (QLORA + KVLORA + DR)      // 2112
#define QD (NH * (DN + DR))               // 24576
#define KVD (NH * (DN + DV))              // 32768
#define CTX_D (NH * DV)                   // 16384
#define DQK 192

// ---------------- scratch (device globals) ----------------
__device__ float g_comp[S_LEN * COMP_D];
__device__ __half g_ah[(size_t)S_LEN * 16384];                   // activations hi (also ctx)
__device__ __half g_al[(size_t)S_LEN * 16384];                   // activations lo
__device__ __half g_wa_h[15597568];                              // w_kv_a hi (2176*7168)
__device__ __half g_wa_l[15597568];                              // w_kv_a lo
__device__ __half g_wq[(size_t)QD * QLORA];                      // w_q_b^T
__device__ __half g_wkv[(size_t)KVD * KVLORA];                   // w_kv_b^T
__device__ __half g_wo[(size_t)HID_D * CTX_D];                   // w_o^T
__device__ float g_kv[(size_t)S_LEN * KVD];                      // v half only used
__device__ float g_kpe[S_LEN * DR];
__device__ __half g_qh[(size_t)NH * S_LEN * DQK];
__device__ __half g_ql[(size_t)NH * S_LEN * DQK];
__device__ __half g_kh[(size_t)NH * S_LEN * DQK];
__device__ __half g_kl[(size_t)NH * S_LEN * DQK];
__device__ __half g_vth[(size_t)NH * DV * S_LEN];

// ---------------- PTX helpers ----------------
__device__ __forceinline__ uint32_t smem_u32(const void* p) {
    uint32_t a;
    asm("{ .reg .u64 t; cvta.to.shared.u64 t, %1; cvt.u32.u64 %0, t; }" : "=r"(a) : "l"(p));
    return a;
}
#define CP16(dst, src) \
    asm volatile("cp.async.cg.shared.global [%0], [%1], 16;" :: "r"(dst), "l"(src) : "memory")
#define CP_COMMIT() asm volatile("cp.async.commit_group;" ::: "memory")
#define CP_WAIT1() asm volatile("cp.async.wait_group 1;" ::: "memory")
#define CP_WAIT0() asm volatile("cp.async.wait_group 0;" ::: "memory")

#define LDSM4(r, a) \
    asm volatile("ldmatrix.sync.aligned.m8n8.x4.shared.b16 {%0,%1,%2,%3}, [%4];" \
        : "=r"((r)[0]), "=r"((r)[1]), "=r"((r)[2]), "=r"((r)[3]) : "r"(a))

#define MMA_F16(d, a, b0, b1) \
    asm volatile("mma.sync.aligned.m16n8k16.row.col.f32.f16.f16.f32 " \
        "{%0,%1,%2,%3}, {%4,%5,%6,%7}, {%8,%9}, {%0,%1,%2,%3};" \
        : "+f"((d)[0]), "+f"((d)[1]), "+f"((d)[2]), "+f"((d)[3]) \
        : "r"((a)[0]), "r"((a)[1]), "r"((a)[2]), "r"((a)[3]), "r"(b0), "r"(b1))

#define SWZ(o) ((o) ^ (((o) >> 3) & 0x70))

__device__ __forceinline__ void split_h(float v, __half& h, __half& l) {
    h = __float2half_rn(v);
    l = __float2half_rn(v - __half2float(h));
}

// ---------------- shared GEMM body (2-stage pipeline, R8-proven) ----------------
// NPASS=1: ah*bh        NPASS=2: ah*bh + al*bh        NPASS=3: + ah*bl
template <int NPASS>
__device__ __forceinline__ void gemm_body(
    const __half* __restrict__ Ah, const __half* __restrict__ Al,
    const __half* __restrict__ Bh, const __half* __restrict__ Bl,
    int K, int nch, int m0, int n0, uint32_t sb, int tid, float acc[2][8][4])
{
    constexpr int CA = (NPASS >= 2) ? 2 : 1;
    constexpr int CB = (NPASS == 3) ? 2 : 1;
    constexpr int NT = CA + CB;
    constexpr int STAGE = NT * 16384;
    const int lane = tid & 31;
    const int wid = tid >> 5;
    const int wm = (wid & 3) * 32;
    const int wn = (wid >> 2) * 64;

    auto load_stage = [&](int c, int s) {
        const int kc = c << 6;
#pragma unroll
        for (int it = 0; it < NT * 4; it++) {
            const int t = tid + it * 256;
            const int tensor = t >> 10;
            const int rem = t & 1023;
            const int row = rem >> 3;
            const int ch = rem & 7;
            const __half* src;
            int grow;
            if (tensor < CA) {
                src = (CA == 2 && tensor == 1) ? Al : Ah;
                grow = m0 + row;
            } else {
                src = (CB == 2 && tensor == CA + 1) ? Bl : Bh;
                grow = n0 + row;
            }
            const __half* sp = src + (size_t)grow * K + kc + ch * 8;
            const uint32_t dst = sb + s * STAGE + tensor * 16384 + SWZ(row * 128 + ch * 16);
            CP16(dst, sp);
        }
        CP_COMMIT();
    };

    load_stage(0, 0);

    for (int c = 0; c < nch; c++) {
        const int buf = c & 1;
        if (c + 1 < nch) { load_stage(c + 1, buf ^ 1); CP_WAIT1(); }
        else             { CP_WAIT0(); }
        __syncthreads();

        const uint32_t st = sb + buf * STAGE;
        const uint32_t sA_h = st;
        const uint32_t sA_l = st + 16384;
        const uint32_t sB_h = st + CA * 16384;
        const uint32_t sB_l = sB_h + 16384;
        const int rl = lane & 15;
        const int kb = lane >> 4;

#pragma unroll
        for (int k16 = 0; k16 < 4; k16++) {
            const int kbyte = k16 * 32 + kb * 16;
            uint32_t afh[2][4], afl[2][4], bfh[4][4], bfl[4][4];
#pragma unroll
            for (int mt = 0; mt < 2; mt++) {
                const uint32_t off = SWZ((wm + mt * 16 + rl) * 128 + kbyte);
                LDSM4(afh[mt], sA_h + off);
                if (CA == 2) LDSM4(afl[mt], sA_l + off);
            }
#pragma unroll
            for (int q = 0; q < 4; q++) {
                const uint32_t off = SWZ((wn + q * 16 + rl) * 128 + kbyte);
                LDSM4(bfh[q], sB_h + off);
                if (CB == 2) LDSM4(bfl[q], sB_l + off);
            }
#pragma unroll
            for (int mt = 0; mt < 2; mt++)
#pragma unroll
                for (int nt = 0; nt < 8; nt++) {
                    const int q = nt >> 1, s = nt & 1;
                    MMA_F16(acc[mt][nt], afh[mt], bfh[q][s], bfh[q][s + 2]);
                    if (CA == 2) MMA_F16(acc[mt][nt], afl[mt], bfh[q][s], bfh[q][s + 2]);
                    if (CB == 2) MMA_F16(acc[mt][nt], afh[mt], bfl[q][s], bfl[q][s + 2]);
                }
        }
        __syncthreads();
    }
}

#define GEMM_PROLOGUE() \
    extern __shared__ __align__(128) char smem[]; \
    const uint32_t sb = smem_u32(smem); \
    const int tid = threadIdx.x; \
    const int lane = tid & 31; \
    const int wid = tid >> 5; \
    const int m0 = blockIdx.y * 128, n0 = blockIdx.x * 128; \
    const int wm = (wid & 3) * 32, wn = (wid >> 2) * 64; \
    float acc[2][8][4]; \
    _Pragma("unroll") for (int mt = 0; mt < 2; mt++) \
    _Pragma("unroll") for (int nt = 0; nt < 8; nt++) \
    _Pragma("unroll") for (int e = 0; e < 4; e++) acc[mt][nt][e] = 0.0f;

// ---------------- comp GEMM: 3-pass, fp32 out (128KB smem -> 1 CTA/SM) ----------
__global__ __launch_bounds__(256, 1) void mma_gemm3(
    const __half* __restrict__ Ah, const __half* __restrict__ Al,
    const __half* __restrict__ Bh, const __half* __restrict__ Bl,
    float* __restrict__ C, int N, int K)
{
    GEMM_PROLOGUE();
    gemm_body<3>(Ah, Al, Bh, Bl, K, K >> 6, m0, n0, sb, tid, acc);
#pragma unroll
    for (int mt = 0; mt < 2; mt++) {
        const int row = m0 + wm + mt * 16 + (lane >> 2);
#pragma unroll
        for (int nt = 0; nt < 8; nt++) {
            const int col = n0 + wn + nt * 8 + (lane & 3) * 2;
            if (col < N) {
                *reinterpret_cast<float2*>(C + (size_t)row * N + col) =
                    make_float2(acc[mt][nt][0], acc[mt][nt][1]);
                *reinterpret_cast<float2*>(C + (size_t)(row + 8) * N + col) =
                    make_float2(acc[mt][nt][2], acc[mt][nt][3]);
            }
        }
    }
}

// ---------------- w_o GEMM: 1-pass, fp32 out (64KB, force 2 CTA/SM) ----------
__global__ __launch_bounds__(256, 2) void mma_gemm1(
    const __half* __restrict__ Ah, const __half* __restrict__ Bh,
    float* __restrict__ C, int N, int K)
{
    GEMM_PROLOGUE();
    gemm_body<1>(Ah, nullptr, Bh, nullptr, K, K >> 6, m0, n0, sb, tid, acc);
#pragma unroll
    for (int mt = 0; mt < 2; mt++) {
        const int row = m0 + wm + mt * 16 + (lane >> 2);
#pragma unroll
        for (int nt = 0; nt < 8; nt++) {
            const int col = n0 + wn + nt * 8 + (lane & 3) * 2;
            *reinterpret_cast<float2*>(C + (size_t)row * N + col) =
                make_float2(acc[mt][nt][0], acc[mt][nt][1]);
            *reinterpret_cast<float2*>(C + (size_t)(row + 8) * N + col) =
                make_float2(acc[mt][nt][2], acc[mt][nt][3]);
        }
    }
}

// ---------------- RoPE angle ----------------
__device__ __forceinline__ void rope_cs(int s, int d, float& c, float& sn)
{
    const float inv = exp2f(-(float)d * (13.287712379549449f / 32.0f));
    sincosf((float)s * inv, &sn, &c);
}

// ---------------- q GEMM: 2-pass, fused RoPE + split (96KB, force 2 CTA/SM) -----
__global__ __launch_bounds__(256, 2) void mma_gemm_q(
    const __half* __restrict__ Ah, const __half* __restrict__ Al,
    const __half* __restrict__ Bh,
    __half* __restrict__ Qh, __half* __restrict__ Ql)
{
    GEMM_PROLOGUE();
    gemm_body<2>(Ah, Al, Bh, nullptr, QLORA, QLORA >> 6, m0, n0, sb, tid, acc);

    const int base64 = n0 + wn;
    if ((base64 / 64) % 3 != 2) {
#pragma unroll
        for (int mt = 0; mt < 2; mt++)
#pragma unroll
            for (int half_i = 0; half_i < 2; half_i++) {
                const int row = m0 + wm + mt * 16 + (lane >> 2) + half_i * 8;
#pragma unroll
                for (int nt = 0; nt < 8; nt++) {
                    const int c = base64 + nt * 8 + (lane & 3) * 2;
                    const int h = c / 192;
                    const int cr = c - h * 192;
                    const size_t o = ((size_t)h * S_LEN + row) * DQK + cr;
                    __half h0, l0, h1, l1;
                    split_h(acc[mt][nt][half_i * 2], h0, l0);
                    split_h(acc[mt][nt][half_i * 2 + 1], h1, l1);
                    *reinterpret_cast<__half2*>(Qh + o) = __half2(h0, h1);
                    *reinterpret_cast<__half2*>(Ql + o) = __half2(l0, l1);
                }
            }
    } else {
        const int h = base64 / 192;
#pragma unroll
        for (int mt = 0; mt < 2; mt++)
#pragma unroll
            for (int half_i = 0; half_i < 2; half_i++) {
                const int row = m0 + wm + mt * 16 + (lane >> 2) + half_i * 8;
                const size_t rb = ((size_t)h * S_LEN + row) * DQK + 128;
#pragma unroll
                for (int ntL = 0; ntL < 4; ntL++) {
                    const int d0 = ntL * 8 + (lane & 3) * 2;
                    float o0[2], o1[2];
#pragma unroll
                    for (int e = 0; e < 2; e++) {
                        float cc, ss;
                        rope_cs(row, d0 + e, cc, ss);
                        const float v1 = acc[mt][ntL][half_i * 2 + e];
                        const float v2 = acc[mt][ntL + 4][half_i * 2 + e];
                        o0[e] = v1 * cc - v2 * ss;
                        o1[e] = v2 * cc + v1 * ss;
                    }
                    __half h0, l0, h1, l1;
                    split_h(o0[0], h0, l0); split_h(o0[1], h1, l1);
                    *reinterpret_cast<__half2*>(Qh + rb + d0) = __half2(h0, h1);
                    *reinterpret_cast<__half2*>(Ql + rb + d0) = __half2(l0, l1);
                    split_h(o1[0], h0, l0); split_h(o1[1], h1, l1);
                    *reinterpret_cast<__half2*>(Qh + rb + d0 + 32) = __half2(h0, h1);
                    *reinterpret_cast<__half2*>(Ql + rb + d0 + 32) = __half2(l0, l1);
                }
            }
    }
}

// ---------------- kv GEMM: 2-pass, split per-head (96KB, force 2 CTA/SM) --------
__global__ __launch_bounds__(256, 2) void mma_gemm_kv(
    const __half* __restrict__ Ah, const __half* __restrict__ Al,
    const __half* __restrict__ Bh,
    __half* __restrict__ Kh, __half* __restrict__ Kl, float* __restrict__ kv)
{
    GEMM_PROLOGUE();
    gemm_body<2>(Ah, Al, Bh, nullptr, KVLORA, KVLORA >> 6, m0, n0, sb, tid, acc);

    const int base64 = n0 + wn;
    const int blk4 = (base64 / 64) & 3;
    if (blk4 < 2) {
        const int h = base64 / 256;
#pragma unroll
        for (int mt = 0; mt < 2; mt++)
#pragma unroll
            for (int half_i = 0; half_i < 2; half_i++) {
                const int row = m0 + wm + mt * 16 + (lane >> 2) + half_i * 8;
#pragma unroll
                for (int nt = 0; nt < 8; nt++) {
                    const int c = base64 + nt * 8 + (lane & 3) * 2;
                    const int cr = c - h * 256;
                    const size_t o = ((size_t)h * S_LEN + row) * DQK + cr;
                    __half h0, l0, h1, l1;
                    split_h(acc[mt][nt][half_i * 2], h0, l0);
                    split_h(acc[mt][nt][half_i * 2 + 1], h1, l1);
                    *reinterpret_cast<__half2*>(Kh + o) = __half2(h0, h1);
                    *reinterpret_cast<__half2*>(Kl + o) = __half2(l0, l1);
                }
            }
    } else {
#pragma unroll
        for (int mt = 0; mt < 2; mt++) {
            const int row = m0 + wm + mt * 16 + (lane >> 2);
#pragma unroll
            for (int nt = 0; nt < 8; nt++) {
                const int c = base64 + nt * 8 + (lane & 3) * 2;
                *reinterpret_cast<float2*>(kv + (size_t)row * KVD + c) =
                    make_float2(acc[mt][nt][0], acc[mt][nt][1]);
                *reinterpret_cast<float2*>(kv + (size_t)(row + 8) * KVD + c) =
                    make_float2(acc[mt][nt][2], acc[mt][nt][3]);
            }
        }
    }
}

// ---------------- fused flash attention per (head, i-tile) ----------------
// smem: [0,128K) gemm stages (P hi reuses [0,32K) after S phase), [128K,160K) V
__global__ __launch_bounds__(256, 1) void flash_mma(
    const __half* __restrict__ Qh, const __half* __restrict__ Ql,
    const __half* __restrict__ Kh, const __half* __restrict__ Kl,
    const __half* __restrict__ Vth, __half* __restrict__ ch)
{
    extern __shared__ __align__(128) char smem[];
    __shared__ float redM[2][128];
    __shared__ float redS[2][128];
    const uint32_t sb = smem_u32(smem);
    const int tid = threadIdx.x;
    const int lane = tid & 31;
    const int wid = tid >> 5;
    const int h = blockIdx.x;
    const int it = 7 - blockIdx.y;          // heavy tiles first
    const int m0 = it * 128;
    const int wm = (wid & 3) * 32, wn = (wid >> 2) * 64;
    const int ng = wid >> 2;
    const size_t hoff = (size_t)h * S_LEN * DQK;
    const size_t voff = (size_t)h * DV * S_LEN;
    const float scale = 0.07216878364870323f;   // 1/sqrt(192)

    float Oacc[2][8][4];
    float mrow[2][2], lrow[2][2];
#pragma unroll
    for (int mt = 0; mt < 2; mt++)
#pragma unroll
        for (int nt = 0; nt < 8; nt++)
#pragma unroll
            for (int e = 0; e < 4; e++) Oacc[mt][nt][e] = 0.0f;
#pragma unroll
    for (int mt = 0; mt < 2; mt++)
#pragma unroll
        for (int hf = 0; hf < 2; hf++) { mrow[mt][hf] = -3.4e38f; lrow[mt][hf] = 0.0f; }

    for (int jt = 0; jt <= it; jt++) {
        // ---- S = Q @ K^T (3-pass split) ----
        float Sacc[2][8][4];
#pragma unroll
        for (int mt = 0; mt < 2; mt++)
#pragma unroll
            for (int nt = 0; nt < 8; nt++)
#pragma unroll
                for (int e = 0; e < 4; e++) Sacc[mt][nt][e] = 0.0f;

        gemm_body<3>(Qh + hoff, Ql + hoff, Kh + hoff, Kl + hoff,
                     DQK, 3, m0, jt * 128, sb, tid, Sacc);

        // ---- prefetch V tile (2 chunks of [128 d][64 j]) ----
#pragma unroll
        for (int itv = 0; itv < 8; itv++) {
            const int t = tid + itv * 256;
            const int c = t >> 10;
            const int rem = t & 1023;
            const int d = rem >> 3;
            const int seg = rem & 7;
            const __half* sp = Vth + voff + (size_t)d * S_LEN + jt * 128 + c * 64 + seg * 8;
            CP16(sb + 131072 + c * 16384 + SWZ(d * 128 + seg * 16), sp);
        }
        CP_COMMIT();

        // ---- pass A: scale + mask + row max ----
#pragma unroll
        for (int mt = 0; mt < 2; mt++)
#pragma unroll
            for (int hf = 0; hf < 2; hf++) {
                const int rloc = wm + mt * 16 + (lane >> 2) + hf * 8;
                float mx = -3.4e38f;
#pragma unroll
                for (int nt = 0; nt < 8; nt++)
#pragma unroll
                    for (int e = 0; e < 2; e++) {
                        float s = Sacc[mt][nt][hf * 2 + e] * scale;
                        if (jt == it) {
                            const int cg = jt * 128 + wn + nt * 8 + (lane & 3) * 2 + e;
                            if (cg > m0 + rloc) s = -3.4e38f;
                        }
                        Sacc[mt][nt][hf * 2 + e] = s;
                        mx = fmaxf(mx, s);
                    }
                mx = fmaxf(mx, __shfl_xor_sync(0xFFFFFFFFu, mx, 1));
                mx = fmaxf(mx, __shfl_xor_sync(0xFFFFFFFFu, mx, 2));
                if ((lane & 3) == 0) redM[ng][rloc] = mx;
            }
        __syncthreads();

        // ---- pass B: exp, write P (single fp16) to smem, row sums, O rescale ----
#pragma unroll
        for (int mt = 0; mt < 2; mt++)
#pragma unroll
            for (int hf = 0; hf < 2; hf++) {
                const int rloc = wm + mt * 16 + (lane >> 2) + hf * 8;
                const float mnew = fmaxf(mrow[mt][hf],
                                         fmaxf(redM[0][rloc], redM[1][rloc]));
                float ssum = 0.0f;
#pragma unroll
                for (int nt = 0; nt < 8; nt++) {
                    const float p0 = __expf(Sacc[mt][nt][hf * 2] - mnew);
                    const float p1 = __expf(Sacc[mt][nt][hf * 2 + 1] - mnew);
                    ssum += p0 + p1;
                    const uint32_t off = SWZ(rloc * 128 + (nt * 8 + (lane & 3) * 2) * 2);
                    *reinterpret_cast<__half2*>(smem + ng * 16384 + off) =
                        __half2(__float2half_rn(p0), __float2half_rn(p1));
                }
                ssum += __shfl_xor_sync(0xFFFFFFFFu, ssum, 1);
                ssum += __shfl_xor_sync(0xFFFFFFFFu, ssum, 2);
                if ((lane & 3) == 0) redS[ng][rloc] = ssum;
                const float sc = __expf(mrow[mt][hf] - mnew);
#pragma unroll
                for (int nt = 0; nt < 8; nt++) {
                    Oacc[mt][nt][hf * 2] *= sc;
                    Oacc[mt][nt][hf * 2 + 1] *= sc;
                }
                lrow[mt][hf] *= sc;
                mrow[mt][hf] = mnew;
            }
        __syncthreads();

        // ---- pass C: finish l ----
#pragma unroll
        for (int mt = 0; mt < 2; mt++)
#pragma unroll
            for (int hf = 0; hf < 2; hf++) {
                const int rloc = wm + mt * 16 + (lane >> 2) + hf * 8;
                lrow[mt][hf] += redS[0][rloc] + redS[1][rloc];
            }

        // ---- P @ V (single pass), accumulate into Oacc ----
        CP_WAIT0();
        __syncthreads();
        const int rl = lane & 15;
        const int kb = lane >> 4;
#pragma unroll
        for (int c = 0; c < 2; c++) {
#pragma unroll
            for (int k16 = 0; k16 < 4; k16++) {
                const int kbyte = k16 * 32 + kb * 16;
                uint32_t pfh[2][4], vf[4][4];
#pragma unroll
                for (int mt = 0; mt < 2; mt++) {
                    const uint32_t off = SWZ((wm + mt * 16 + rl) * 128 + kbyte);
                    LDSM4(pfh[mt], sb + c * 16384 + off);
                }
#pragma unroll
                for (int q = 0; q < 4; q++) {
                    const uint32_t off = SWZ((wn + q * 16 + rl) * 128 + kbyte);
                    LDSM4(vf[q], sb + 131072 + c * 16384 + off);
                }
#pragma unroll
                for (int mt = 0; mt < 2; mt++)
#pragma unroll
                    for (int nt = 0; nt < 8; nt++) {
                        const int q = nt >> 1, s = nt & 1;
                        MMA_F16(Oacc[mt][nt], pfh[mt], vf[q][s], vf[q][s + 2]);
                    }
            }
        }
        __syncthreads();   // protect P/V smem before next jt's loads
    }

    // ---- epilogue: normalize and write ctx fp16 ----
#pragma unroll
    for (int mt = 0; mt < 2; mt++)
#pragma unroll
        for (int hf = 0; hf < 2; hf++) {
            const int row = m0 + wm + mt * 16 + (lane >> 2) + hf * 8;
            const float inv = 1.0f / lrow[mt][hf];
#pragma unroll
            for (int nt = 0; nt < 8; nt++) {
                const int col = wn + nt * 8 + (lane & 3) * 2;
                const size_t o = (size_t)row * CTX_D + (size_t)h * DV + col;
                *reinterpret_cast<__half2*>(ch + o) =
                    __half2(__float2half_rn(Oacc[mt][nt][hf * 2] * inv),
                            __float2half_rn(Oacc[mt][nt][hf * 2 + 1] * inv));
            }
        }
}

// ---------------- weight converts ----------------
__global__ void conv_w2(const float* __restrict__ W, __half* __restrict__ Th, int K, int N)
{
    __shared__ float t[64][33];
    const int k0 = blockIdx.x * 64, n0 = blockIdx.y * 32;
    const int tx = threadIdx.x, ty = threadIdx.y;
#pragma unroll
    for (int i = 0; i < 8; i++)
        t[ty + i * 8][tx] = W[(size_t)(k0 + ty + i * 8) * N + n0 + tx];
    __syncthreads();
#pragma unroll
    for (int i = 0; i < 4; i++) {
        const int n = n0 + ty + i * 8;
        const int cidx = ty + i * 8;
        __half2 v = __half2(__float2half_rn(t[tx * 2][cidx]),
                            __float2half_rn(t[tx * 2 + 1][cidx]));
        *reinterpret_cast<__half2*>(Th + (size_t)n * K + k0 + tx * 2) = v;
    }
}

// vectorized hi/lo split convert: 64k x 32n tile, __half2 stores, n guarded
__global__ void conv_w_split2(const float* __restrict__ W, __half* __restrict__ Th,
                              __half* __restrict__ Tl, int K, int N)
{
    __shared__ float t[64][33];
    const int k0 = blockIdx.x * 64, n0 = blockIdx.y * 32;
    const int tx = threadIdx.x, ty = threadIdx.y;
#pragma unroll
    for (int i = 0; i < 8; i++) {
        const int n = n0 + tx;
        t[ty + i * 8][tx] = (n < N) ? W[(size_t)(k0 + ty + i * 8) * N + n] : 0.0f;
    }
    __syncthreads();
#pragma unroll
    for (int i = 0; i < 4; i++) {
        const int n = n0 + ty + i * 8;
        const int cidx = ty + i * 8;
        __half h0, l0, h1, l1;
        split_h(t[tx * 2][cidx], h0, l0);
        split_h(t[tx * 2 + 1][cidx], h1, l1);
        const size_t o = (size_t)n * K + k0 + tx * 2;
        *reinterpret_cast<__half2*>(Th + o) = __half2(h0, h1);
        *reinterpret_cast<__half2*>(Tl + o) = __half2(l0, l1);
    }
}

// ---------------- activation convert ----------------
__global__ void conv_a(const float* __restrict__ A, __half* __restrict__ H,
                       __half* __restrict__ L, int n4)
{
    const int i = blockIdx.x * blockDim.x + threadIdx.x;
    if (i >= n4) return;
    const float4 v = reinterpret_cast<const float4*>(A)[i];
    __half h0, l0, h1, l1, h2, l2, h3, l3;
    split_h(v.x, h0, l0); split_h(v.y, h1, l1);
    split_h(v.z, h2, l2); split_h(v.w, h3, l3);
    __half2* Hp = reinterpret_cast<__half2*>(H) + i * 2;
    __half2* Lp = reinterpret_cast<__half2*>(L) + i * 2;
    Hp[0] = __half2(h0, h1); Hp[1] = __half2(h2, h3);
    Lp[0] = __half2(l0, l1); Lp[1] = __half2(l2, l3);
}

// ---------------- rmsnorm fused to fp16 hi/lo ----------------
__global__ void rmsnorm_h(const float* __restrict__ x, const float* __restrict__ gamma,
                          __half* __restrict__ yh, __half* __restrict__ yl,
                          int D, int xstride)
{
    const int row = blockIdx.x;
    const float* xr = x + (size_t)row * xstride;
    float s = 0.0f;
    for (int i = threadIdx.x; i < D; i += 256) { const float v = xr[i]; s += v * v; }
    __shared__ float red[256];
    red[threadIdx.x] = s;
    __syncthreads();
    for (int o = 128; o > 0; o >>= 1) {
        if (threadIdx.x < o) red[threadIdx.x] += red[threadIdx.x + o];
        __syncthreads();
    }
    const float inv = rsqrtf(red[0] / (float)D + 1e-6f);
    for (int i = threadIdx.x; i < D; i += 256) {
        __half h, l;
        split_h(xr[i] * inv * gamma[i], h, l);
        yh[(size_t)row * D + i] = h;
        yl[(size_t)row * D + i] = l;
    }
}

// ---------------- k_pe RoPE ----------------
__global__ void rope_k_kernel(const float* __restrict__ comp, float* __restrict__ kpe)
{
    const int t = blockIdx.x * blockDim.x + threadIdx.x;
    if (t >= S_LEN * 32) return;
    const int d = t & 31;
    const int s = t >> 5;
    float c, sn;
    rope_cs(s, d, c, sn);
    const float* src = comp + (size_t)s * COMP_D + QLORA + KVLORA;
    const float x1 = src[d], x2 = src[d + 32];
    kpe[s * DR + d]      = x1 * c - x2 * sn;
    kpe[s * DR + d + 32] = x2 * c + x1 * sn;
}

// ---------------- broadcast roped k_pe into per-head K cols 128..191 -----------
__global__ void fill_kpe(const float* __restrict__ kpe,
                         __half* __restrict__ Kh, __half* __restrict__ Kl)
{
    const int t = blockIdx.x * blockDim.x + threadIdx.x;
    if (t >= NH * S_LEN * 32) return;
    const int d2 = t & 31;
    const int j  = (t >> 5) & (S_LEN - 1);
    const int h  = t >> 15;
    const int d = d2 * 2;
    __half h0, l0, h1, l1;
    split_h(kpe[j * DR + d], h0, l0);
    split_h(kpe[j * DR + d + 1], h1, l1);
    const size_t o = ((size_t)h * S_LEN + j) * DQK + 128 + d;
    *reinterpret_cast<__half2*>(Kh + o) = __half2(h0, h1);
    *reinterpret_cast<__half2*>(Kl + o) = __half2(l0, l1);
}

// ---------------- build V^T per head (transpose, single fp16) ----------------
__global__ void build_vt(const float* __restrict__ kv, __half* __restrict__ Vth)
{
    __shared__ float t[32][33];
    const int j0 = blockIdx.x * 32, d0 = blockIdx.y * 32, h = blockIdx.z;
    const int tx = threadIdx.x, ty = threadIdx.y;
#pragma unroll
    for (int i = 0; i < 4; i++)
        t[ty + i * 8][tx] = kv[(size_t)(j0 + ty + i * 8) * KVD + h * 256 + 128 + d0 + tx];
    __syncthreads();
    const size_t base = (size_t)h * DV * S_LEN;
#pragma unroll
    for (int i = 0; i < 4; i++)
        Vth[base + (size_t)(d0 + ty + i * 8) * S_LEN + j0 + tx] =
            __float2half_rn(t[tx][ty + i * 8]);
}

// ---------------- launch ----------------
extern "C" void kernel_launch(void* const* d_in, const int* in_sizes, int n_in,
                              void* d_out, int out_size)
{
    const float* hs       = (const float*)d_in[0];
    const float* w_kv_a   = (const float*)d_in[1];
    const float* q_gamma  = (const float*)d_in[2];
    const float* kv_gamma = (const float*)d_in[3];
    const float* w_q_b    = (const float*)d_in[4];
    const float* w_kv_b   = (const float*)d_in[5];
    const float* w_o      = (const float*)d_in[6];
    float* out = (float*)d_out;

    float *comp, *kv, *kpe;
    __half *ah, *al, *wah, *wal, *wq, *wkv, *wo, *qh, *ql, *kh, *kl, *vth;
    cudaGetSymbolAddress((void**)&comp, g_comp);
    cudaGetSymbolAddress((void**)&ah,   g_ah);
    cudaGetSymbolAddress((void**)&al,   g_al);
    cudaGetSymbolAddress((void**)&wah,  g_wa_h);
    cudaGetSymbolAddress((void**)&wal,  g_wa_l);
    cudaGetSymbolAddress((void**)&wq,   g_wq);
    cudaGetSymbolAddress((void**)&wkv,  g_wkv);
    cudaGetSymbolAddress((void**)&wo,   g_wo);
    cudaGetSymbolAddress((void**)&kv,   g_kv);
    cudaGetSymbolAddress((void**)&kpe,  g_kpe);
    cudaGetSymbolAddress((void**)&qh,   g_qh);
    cudaGetSymbolAddress((void**)&ql,   g_ql);
    cudaGetSymbolAddress((void**)&kh,   g_kh);
    cudaGetSymbolAddress((void**)&kl,   g_kl);
    cudaGetSymbolAddress((void**)&vth,  g_vth);

    cudaFuncSetAttribute(mma_gemm3, cudaFuncAttributeMaxDynamicSharedMemorySize, 131072);
    cudaFuncSetAttribute(mma_gemm_q, cudaFuncAttributeMaxDynamicSharedMemorySize, 98304);
    cudaFuncSetAttribute(mma_gemm_kv, cudaFuncAttributeMaxDynamicSharedMemorySize, 98304);
    cudaFuncSetAttribute(mma_gemm1, cudaFuncAttributeMaxDynamicSharedMemorySize, 65536);
    cudaFuncSetAttribute(flash_mma, cudaFuncAttributeMaxDynamicSharedMemorySize, 163840);
    const dim3 T256(256);
    const dim3 TW(32, 8);

    // side stream + events (created per call; never destroyed)
    cudaStream_t s2;
    cudaStreamCreateWithFlags(&s2, cudaStreamNonBlocking);
    cudaEvent_t evFork, evA, evQ, evKV, evO, evComp, evKpe;
    cudaEventCreateWithFlags(&evFork, cudaEventDisableTiming);
    cudaEventCreateWithFlags(&evA,    cudaEventDisableTiming);
    cudaEventCreateWithFlags(&evQ,    cudaEventDisableTiming);
    cudaEventCreateWithFlags(&evKV,   cudaEventDisableTiming);
    cudaEventCreateWithFlags(&evO,    cudaEventDisableTiming);
    cudaEventCreateWithFlags(&evComp, cudaEventDisableTiming);
    cudaEventCreateWithFlags(&evKpe,  cudaEventDisableTiming);

    cudaEventRecord(evFork, 0);
    cudaStreamWaitEvent(s2, evFork, 0);

    // side stream: activation split + independent weight conversions
    conv_a<<<(S_LEN * HID_D / 4 + 255) / 256, 256, 0, s2>>>(hs, ah, al, S_LEN * HID_D / 4);
    cudaEventRecord(evA, s2);
    conv_w2<<<dim3(QLORA / 64, QD / 32), TW, 0, s2>>>(w_q_b, wq, QLORA, QD);
    cudaEventRecord(evQ, s2);
    conv_w2<<<dim3(KVLORA / 64, KVD / 32), TW, 0, s2>>>(w_kv_b, wkv, KVLORA, KVD);
    cudaEventRecord(evKV, s2);
    conv_w2<<<dim3(CTX_D / 64, HID_D / 32), TW, 0, s2>>>(w_o, wo, CTX_D, HID_D);
    cudaEventRecord(evO, s2);

    // main stream
    // 1) comp = hs @ w_kv_a  (3-pass; N pad 2176)
    conv_w_split2<<<dim3(HID_D / 64, 2176 / 32), TW>>>(w_kv_a, wah, wal, HID_D, COMP_D);
    cudaStreamWaitEvent(0, evA, 0);
    mma_gemm3<<<dim3(17, 8), T256, 131072>>>(ah, al, wah, wal, comp, COMP_D, HID_D);
    cudaEventRecord(evComp, 0);

    // side stream: k_pe RoPE + per-head broadcast (parallel with q GEMM)
    cudaStreamWaitEvent(s2, evComp, 0);
    rope_k_kernel<<<(S_LEN * 32) / 256, 256, 0, s2>>>(comp, kpe);
    fill_kpe<<<(NH * S_LEN * 32) / 256, 256, 0, s2>>>(kpe, kh, kl);
    cudaEventRecord(evKpe, s2);

    // 2) q = rmsnorm(q_c) @ w_q_b, fused RoPE+split -> per-head Qh/Ql
    rmsnorm_h<<<S_LEN, 256>>>(comp, q_gamma, ah, al, QLORA, COMP_D);
    cudaStreamWaitEvent(0, evQ, 0);
    mma_gemm_q<<<dim3(QD / 128, 8), T256, 98304>>>(ah, al, wq, qh, ql);

    // 3) kv = rmsnorm(kv_c) @ w_kv_b, fused split -> Kh/Kl (nope) + kv fp32 (v)
    rmsnorm_h<<<S_LEN, 256>>>(comp + QLORA, kv_gamma, ah, al, KVLORA, COMP_D);
    cudaStreamWaitEvent(0, evKV, 0);
    mma_gemm_kv<<<dim3(KVD / 128, 8), T256, 98304>>>(ah, al, wkv, kh, kl, kv);
    build_vt<<<dim3(32, 4, NH), TW>>>(kv, vth);

    // 4) fused flash attention -> ctx fp16 in ah
    cudaStreamWaitEvent(0, evKpe, 0);
    flash_mma<<<dim3(NH, 8), T256, 163840>>>(qh, ql, kh, kl, vth, ah);

    // 5) out = ctx @ w_o  (1-pass)
    cudaStreamWaitEvent(0, evO, 0);
    mma_gemm1<<<dim3(HID_D / 128, 8), T256, 65536>>>(ah, wo, out, HID_D, CTX_D);
}

// round 12
// speedup vs baseline: 1.1777x; 1.0742x over previous
#include <cuda_runtime.h>
#include <cuda_fp16.h>
#include <math.h>
#include <stdint.h>

// ---------------- problem constants ----------------
#define S_LEN 1024
#define HID_D 7168
#define NH 128
#define DN 128
#define DR 64
#define DV 128
#define QLORA 1536
#define KVLORA 512
#define COMP_D (QLORA + KVLORA + DR)      // 2112
#define QD (NH * (DN + DR))               // 24576
#define KVD (NH * (DN + DV))              // 32768
#define CTX_D (NH * DV)                   // 16384
#define DQK 192

// ---------------- scratch (device globals) ----------------
__device__ float g_comp[S_LEN * COMP_D];
__device__ __half g_ah[(size_t)S_LEN * 16384];                   // activations hi (also ctx)
__device__ __half g_al[(size_t)S_LEN * 16384];                   // activations lo
__device__ __half g_wa_h[15597568];                              // w_kv_a hi (2176*7168)
__device__ __half g_wa_l[15597568];                              // w_kv_a lo
__device__ __half g_wq[(size_t)QD * QLORA];                      // w_q_b^T
__device__ __half g_wkv[(size_t)KVD * KVLORA];                   // w_kv_b^T
__device__ __half g_wo[(size_t)HID_D * CTX_D];                   // w_o^T
__device__ float g_kv[(size_t)S_LEN * KVD];                      // v half only used
__device__ float g_kpe[S_LEN * DR];
__device__ __half g_qh[(size_t)NH * S_LEN * DQK];
__device__ __half g_ql[(size_t)NH * S_LEN * DQK];
__device__ __half g_kh[(size_t)NH * S_LEN * DQK];
__device__ __half g_vth[(size_t)NH * DV * S_LEN];

// ---------------- PTX helpers ----------------
__device__ __forceinline__ uint32_t smem_u32(const void* p) {
    uint32_t a;
    asm("{ .reg .u64 t; cvta.to.shared.u64 t, %1; cvt.u32.u64 %0, t; }" : "=r"(a) : "l"(p));
    return a;
}
#define CP16(dst, src) \
    asm volatile("cp.async.cg.shared.global [%0], [%1], 16;" :: "r"(dst), "l"(src) : "memory")
#define CP_COMMIT() asm volatile("cp.async.commit_group;" ::: "memory")
#define CP_WAIT1() asm volatile("cp.async.wait_group 1;" ::: "memory")
#define CP_WAIT0() asm volatile("cp.async.wait_group 0;" ::: "memory")

#define LDSM4(r, a) \
    asm volatile("ldmatrix.sync.aligned.m8n8.x4.shared.b16 {%0,%1,%2,%3}, [%4];" \
        : "=r"((r)[0]), "=r"((r)[1]), "=r"((r)[2]), "=r"((r)[3]) : "r"(a))

#define MMA_F16(d, a, b0, b1) \
    asm volatile("mma.sync.aligned.m16n8k16.row.col.f32.f16.f16.f32 " \
        "{%0,%1,%2,%3}, {%4,%5,%6,%7}, {%8,%9}, {%0,%1,%2,%3};" \
        : "+f"((d)[0]), "+f"((d)[1]), "+f"((d)[2]), "+f"((d)[3]) \
        : "r"((a)[0]), "r"((a)[1]), "r"((a)[2]), "r"((a)[3]), "r"(b0), "r"(b1))

#define SWZ(o) ((o) ^ (((o) >> 3) & 0x70))

__device__ __forceinline__ void split_h(float v, __half& h, __half& l) {
    h = __float2half_rn(v);
    l = __float2half_rn(v - __half2float(h));
}

// ---------------- shared GEMM body (2-stage pipeline, R8-proven) ----------------
// NPASS=1: ah*bh        NPASS=2: ah*bh + al*bh        NPASS=3: + ah*bl
template <int NPASS>
__device__ __forceinline__ void gemm_body(
    const __half* __restrict__ Ah, const __half* __restrict__ Al,
    const __half* __restrict__ Bh, const __half* __restrict__ Bl,
    int K, int nch, int m0, int n0, uint32_t sb, int tid, float acc[2][8][4])
{
    constexpr int CA = (NPASS >= 2) ? 2 : 1;
    constexpr int CB = (NPASS == 3) ? 2 : 1;
    constexpr int NT = CA + CB;
    constexpr int STAGE = NT * 16384;
    const int lane = tid & 31;
    const int wid = tid >> 5;
    const int wm = (wid & 3) * 32;
    const int wn = (wid >> 2) * 64;

    auto load_stage = [&](int c, int s) {
        const int kc = c << 6;
#pragma unroll
        for (int it = 0; it < NT * 4; it++) {
            const int t = tid + it * 256;
            const int tensor = t >> 10;
            const int rem = t & 1023;
            const int row = rem >> 3;
            const int ch = rem & 7;
            const __half* src;
            int grow;
            if (tensor < CA) {
                src = (CA == 2 && tensor == 1) ? Al : Ah;
                grow = m0 + row;
            } else {
                src = (CB == 2 && tensor == CA + 1) ? Bl : Bh;
                grow = n0 + row;
            }
            const __half* sp = src + (size_t)grow * K + kc + ch * 8;
            const uint32_t dst = sb + s * STAGE + tensor * 16384 + SWZ(row * 128 + ch * 16);
            CP16(dst, sp);
        }
        CP_COMMIT();
    };

    load_stage(0, 0);

    for (int c = 0; c < nch; c++) {
        const int buf = c & 1;
        if (c + 1 < nch) { load_stage(c + 1, buf ^ 1); CP_WAIT1(); }
        else             { CP_WAIT0(); }
        __syncthreads();

        const uint32_t st = sb + buf * STAGE;
        const uint32_t sA_h = st;
        const uint32_t sA_l = st + 16384;
        const uint32_t sB_h = st + CA * 16384;
        const uint32_t sB_l = sB_h + 16384;
        const int rl = lane & 15;
        const int kb = lane >> 4;

#pragma unroll
        for (int k16 = 0; k16 < 4; k16++) {
            const int kbyte = k16 * 32 + kb * 16;
            uint32_t afh[2][4], afl[2][4], bfh[4][4], bfl[4][4];
#pragma unroll
            for (int mt = 0; mt < 2; mt++) {
                const uint32_t off = SWZ((wm + mt * 16 + rl) * 128 + kbyte);
                LDSM4(afh[mt], sA_h + off);
                if (CA == 2) LDSM4(afl[mt], sA_l + off);
            }
#pragma unroll
            for (int q = 0; q < 4; q++) {
                const uint32_t off = SWZ((wn + q * 16 + rl) * 128 + kbyte);
                LDSM4(bfh[q], sB_h + off);
                if (CB == 2) LDSM4(bfl[q], sB_l + off);
            }
#pragma unroll
            for (int mt = 0; mt < 2; mt++)
#pragma unroll
                for (int nt = 0; nt < 8; nt++) {
                    const int q = nt >> 1, s = nt & 1;
                    MMA_F16(acc[mt][nt], afh[mt], bfh[q][s], bfh[q][s + 2]);
                    if (CA == 2) MMA_F16(acc[mt][nt], afl[mt], bfh[q][s], bfh[q][s + 2]);
                    if (CB == 2) MMA_F16(acc[mt][nt], afh[mt], bfl[q][s], bfl[q][s + 2]);
                }
        }
        __syncthreads();
    }
}

#define GEMM_PROLOGUE() \
    extern __shared__ __align__(128) char smem[]; \
    const uint32_t sb = smem_u32(smem); \
    const int tid = threadIdx.x; \
    const int lane = tid & 31; \
    const int wid = tid >> 5; \
    const int m0 = blockIdx.y * 128, n0 = blockIdx.x * 128; \
    const int wm = (wid & 3) * 32, wn = (wid >> 2) * 64; \
    float acc[2][8][4]; \
    _Pragma("unroll") for (int mt = 0; mt < 2; mt++) \
    _Pragma("unroll") for (int nt = 0; nt < 8; nt++) \
    _Pragma("unroll") for (int e = 0; e < 4; e++) acc[mt][nt][e] = 0.0f;

// ---------------- comp GEMM: 3-pass, fp32 out (128KB smem -> 1 CTA/SM) ----------
__global__ __launch_bounds__(256, 1) void mma_gemm3(
    const __half* __restrict__ Ah, const __half* __restrict__ Al,
    const __half* __restrict__ Bh, const __half* __restrict__ Bl,
    float* __restrict__ C, int N, int K)
{
    GEMM_PROLOGUE();
    gemm_body<3>(Ah, Al, Bh, Bl, K, K >> 6, m0, n0, sb, tid, acc);
#pragma unroll
    for (int mt = 0; mt < 2; mt++) {
        const int row = m0 + wm + mt * 16 + (lane >> 2);
#pragma unroll
        for (int nt = 0; nt < 8; nt++) {
            const int col = n0 + wn + nt * 8 + (lane & 3) * 2;
            if (col < N) {
                *reinterpret_cast<float2*>(C + (size_t)row * N + col) =
                    make_float2(acc[mt][nt][0], acc[mt][nt][1]);
                *reinterpret_cast<float2*>(C + (size_t)(row + 8) * N + col) =
                    make_float2(acc[mt][nt][2], acc[mt][nt][3]);
            }
        }
    }
}

// ---------------- w_o GEMM: 1-pass, fp32 out (64KB, 2 CTA/SM) ----------
__global__ __launch_bounds__(256, 2) void mma_gemm1(
    const __half* __restrict__ Ah, const __half* __restrict__ Bh,
    float* __restrict__ C, int N, int K)
{
    GEMM_PROLOGUE();
    gemm_body<1>(Ah, nullptr, Bh, nullptr, K, K >> 6, m0, n0, sb, tid, acc);
#pragma unroll
    for (int mt = 0; mt < 2; mt++) {
        const int row = m0 + wm + mt * 16 + (lane >> 2);
#pragma unroll
        for (int nt = 0; nt < 8; nt++) {
            const int col = n0 + wn + nt * 8 + (lane & 3) * 2;
            *reinterpret_cast<float2*>(C + (size_t)row * N + col) =
                make_float2(acc[mt][nt][0], acc[mt][nt][1]);
            *reinterpret_cast<float2*>(C + (size_t)(row + 8) * N + col) =
                make_float2(acc[mt][nt][2], acc[mt][nt][3]);
        }
    }
}

// ---------------- RoPE angle ----------------
__device__ __forceinline__ void rope_cs(int s, int d, float& c, float& sn)
{
    const float inv = exp2f(-(float)d * (13.287712379549449f / 32.0f));
    sincosf((float)s * inv, &sn, &c);
}

// ---------------- q GEMM: 2-pass, fused RoPE + split (96KB, 2 CTA/SM) -----
__global__ __launch_bounds__(256, 2) void mma_gemm_q(
    const __half* __restrict__ Ah, const __half* __restrict__ Al,
    const __half* __restrict__ Bh,
    __half* __restrict__ Qh, __half* __restrict__ Ql)
{
    GEMM_PROLOGUE();
    gemm_body<2>(Ah, Al, Bh, nullptr, QLORA, QLORA >> 6, m0, n0, sb, tid, acc);

    const int base64 = n0 + wn;
    if ((base64 / 64) % 3 != 2) {
#pragma unroll
        for (int mt = 0; mt < 2; mt++)
#pragma unroll
            for (int half_i = 0; half_i < 2; half_i++) {
                const int row = m0 + wm + mt * 16 + (lane >> 2) + half_i * 8;
#pragma unroll
                for (int nt = 0; nt < 8; nt++) {
                    const int c = base64 + nt * 8 + (lane & 3) * 2;
                    const int h = c / 192;
                    const int cr = c - h * 192;
                    const size_t o = ((size_t)h * S_LEN + row) * DQK + cr;
                    __half h0, l0, h1, l1;
                    split_h(acc[mt][nt][half_i * 2], h0, l0);
                    split_h(acc[mt][nt][half_i * 2 + 1], h1, l1);
                    *reinterpret_cast<__half2*>(Qh + o) = __half2(h0, h1);
                    *reinterpret_cast<__half2*>(Ql + o) = __half2(l0, l1);
                }
            }
    } else {
        const int h = base64 / 192;
#pragma unroll
        for (int mt = 0; mt < 2; mt++)
#pragma unroll
            for (int half_i = 0; half_i < 2; half_i++) {
                const int row = m0 + wm + mt * 16 + (lane >> 2) + half_i * 8;
                const size_t rb = ((size_t)h * S_LEN + row) * DQK + 128;
#pragma unroll
                for (int ntL = 0; ntL < 4; ntL++) {
                    const int d0 = ntL * 8 + (lane & 3) * 2;
                    float o0[2], o1[2];
#pragma unroll
                    for (int e = 0; e < 2; e++) {
                        float cc, ss;
                        rope_cs(row, d0 + e, cc, ss);
                        const float v1 = acc[mt][ntL][half_i * 2 + e];
                        const float v2 = acc[mt][ntL + 4][half_i * 2 + e];
                        o0[e] = v1 * cc - v2 * ss;
                        o1[e] = v2 * cc + v1 * ss;
                    }
                    __half h0, l0, h1, l1;
                    split_h(o0[0], h0, l0); split_h(o0[1], h1, l1);
                    *reinterpret_cast<__half2*>(Qh + rb + d0) = __half2(h0, h1);
                    *reinterpret_cast<__half2*>(Ql + rb + d0) = __half2(l0, l1);
                    split_h(o1[0], h0, l0); split_h(o1[1], h1, l1);
                    *reinterpret_cast<__half2*>(Qh + rb + d0 + 32) = __half2(h0, h1);
                    *reinterpret_cast<__half2*>(Ql + rb + d0 + 32) = __half2(l0, l1);
                }
            }
    }
}

// ---------------- kv GEMM: 2-pass, k_nope -> Kh only; v -> fp32 (96KB, 2 CTA/SM)
__global__ __launch_bounds__(256, 2) void mma_gemm_kv(
    const __half* __restrict__ Ah, const __half* __restrict__ Al,
    const __half* __restrict__ Bh,
    __half* __restrict__ Kh, float* __restrict__ kv)
{
    GEMM_PROLOGUE();
    gemm_body<2>(Ah, Al, Bh, nullptr, KVLORA, KVLORA >> 6, m0, n0, sb, tid, acc);

    const int base64 = n0 + wn;
    const int blk4 = (base64 / 64) & 3;
    if (blk4 < 2) {
        const int h = base64 / 256;
#pragma unroll
        for (int mt = 0; mt < 2; mt++)
#pragma unroll
            for (int half_i = 0; half_i < 2; half_i++) {
                const int row = m0 + wm + mt * 16 + (lane >> 2) + half_i * 8;
#pragma unroll
                for (int nt = 0; nt < 8; nt++) {
                    const int c = base64 + nt * 8 + (lane & 3) * 2;
                    const int cr = c - h * 256;
                    const size_t o = ((size_t)h * S_LEN + row) * DQK + cr;
                    *reinterpret_cast<__half2*>(Kh + o) =
                        __half2(__float2half_rn(acc[mt][nt][half_i * 2]),
                                __float2half_rn(acc[mt][nt][half_i * 2 + 1]));
                }
            }
    } else {
#pragma unroll
        for (int mt = 0; mt < 2; mt++) {
            const int row = m0 + wm + mt * 16 + (lane >> 2);
#pragma unroll
            for (int nt = 0; nt < 8; nt++) {
                const int c = base64 + nt * 8 + (lane & 3) * 2;
                *reinterpret_cast<float2*>(kv + (size_t)row * KVD + c) =
                    make_float2(acc[mt][nt][0], acc[mt][nt][1]);
                *reinterpret_cast<float2*>(kv + (size_t)(row + 8) * KVD + c) =
                    make_float2(acc[mt][nt][2], acc[mt][nt][3]);
            }
        }
    }
}

// ---------------- fused flash attention per (head, i-tile) ----------------
// S phase: 2-pass (Qh+Ql) x Kh. smem: [0,96K) stages (P reuses [0,32K)), [96K,128K) V
__global__ __launch_bounds__(256, 1) void flash_mma(
    const __half* __restrict__ Qh, const __half* __restrict__ Ql,
    const __half* __restrict__ Kh,
    const __half* __restrict__ Vth, __half* __restrict__ ch)
{
    extern __shared__ __align__(128) char smem[];
    __shared__ float redM[2][128];
    __shared__ float redS[2][128];
    const uint32_t sb = smem_u32(smem);
    const int tid = threadIdx.x;
    const int lane = tid & 31;
    const int wid = tid >> 5;
    const int h = blockIdx.x;
    const int it = 7 - blockIdx.y;          // heavy tiles first
    const int m0 = it * 128;
    const int wm = (wid & 3) * 32, wn = (wid >> 2) * 64;
    const int ng = wid >> 2;
    const size_t hoff = (size_t)h * S_LEN * DQK;
    const size_t voff = (size_t)h * DV * S_LEN;
    const float scale = 0.07216878364870323f;   // 1/sqrt(192)

    float Oacc[2][8][4];
    float mrow[2][2], lrow[2][2];
#pragma unroll
    for (int mt = 0; mt < 2; mt++)
#pragma unroll
        for (int nt = 0; nt < 8; nt++)
#pragma unroll
            for (int e = 0; e < 4; e++) Oacc[mt][nt][e] = 0.0f;
#pragma unroll
    for (int mt = 0; mt < 2; mt++)
#pragma unroll
        for (int hf = 0; hf < 2; hf++) { mrow[mt][hf] = -3.4e38f; lrow[mt][hf] = 0.0f; }

    for (int jt = 0; jt <= it; jt++) {
        // ---- S = (Qh+Ql) @ Kh^T (2-pass) ----
        float Sacc[2][8][4];
#pragma unroll
        for (int mt = 0; mt < 2; mt++)
#pragma unroll
            for (int nt = 0; nt < 8; nt++)
#pragma unroll
                for (int e = 0; e < 4; e++) Sacc[mt][nt][e] = 0.0f;

        gemm_body<2>(Qh + hoff, Ql + hoff, Kh + hoff, nullptr,
                     DQK, 3, m0, jt * 128, sb, tid, Sacc);

        // ---- prefetch V tile (2 chunks of [128 d][64 j]) at [96K,128K) ----
#pragma unroll
        for (int itv = 0; itv < 8; itv++) {
            const int t = tid + itv * 256;
            const int c = t >> 10;
            const int rem = t & 1023;
            const int d = rem >> 3;
            const int seg = rem & 7;
            const __half* sp = Vth + voff + (size_t)d * S_LEN + jt * 128 + c * 64 + seg * 8;
            CP16(sb + 98304 + c * 16384 + SWZ(d * 128 + seg * 16), sp);
        }
        CP_COMMIT();

        // ---- pass A: scale + mask + row max ----
#pragma unroll
        for (int mt = 0; mt < 2; mt++)
#pragma unroll
            for (int hf = 0; hf < 2; hf++) {
                const int rloc = wm + mt * 16 + (lane >> 2) + hf * 8;
                float mx = -3.4e38f;
#pragma unroll
                for (int nt = 0; nt < 8; nt++)
#pragma unroll
                    for (int e = 0; e < 2; e++) {
                        float s = Sacc[mt][nt][hf * 2 + e] * scale;
                        if (jt == it) {
                            const int cg = jt * 128 + wn + nt * 8 + (lane & 3) * 2 + e;
                            if (cg > m0 + rloc) s = -3.4e38f;
                        }
                        Sacc[mt][nt][hf * 2 + e] = s;
                        mx = fmaxf(mx, s);
                    }
                mx = fmaxf(mx, __shfl_xor_sync(0xFFFFFFFFu, mx, 1));
                mx = fmaxf(mx, __shfl_xor_sync(0xFFFFFFFFu, mx, 2));
                if ((lane & 3) == 0) redM[ng][rloc] = mx;
            }
        __syncthreads();

        // ---- pass B: exp, write P (single fp16) to smem, row sums, O rescale ----
#pragma unroll
        for (int mt = 0; mt < 2; mt++)
#pragma unroll
            for (int hf = 0; hf < 2; hf++) {
                const int rloc = wm + mt * 16 + (lane >> 2) + hf * 8;
                const float mnew = fmaxf(mrow[mt][hf],
                                         fmaxf(redM[0][rloc], redM[1][rloc]));
                float ssum = 0.0f;
#pragma unroll
                for (int nt = 0; nt < 8; nt++) {
                    const float p0 = __expf(Sacc[mt][nt][hf * 2] - mnew);
                    const float p1 = __expf(Sacc[mt][nt][hf * 2 + 1] - mnew);
                    ssum += p0 + p1;
                    const uint32_t off = SWZ(rloc * 128 + (nt * 8 + (lane & 3) * 2) * 2);
                    *reinterpret_cast<__half2*>(smem + ng * 16384 + off) =
                        __half2(__float2half_rn(p0), __float2half_rn(p1));
                }
                ssum += __shfl_xor_sync(0xFFFFFFFFu, ssum, 1);
                ssum += __shfl_xor_sync(0xFFFFFFFFu, ssum, 2);
                if ((lane & 3) == 0) redS[ng][rloc] = ssum;
                const float sc = __expf(mrow[mt][hf] - mnew);
#pragma unroll
                for (int nt = 0; nt < 8; nt++) {
                    Oacc[mt][nt][hf * 2] *= sc;
                    Oacc[mt][nt][hf * 2 + 1] *= sc;
                }
                lrow[mt][hf] *= sc;
                mrow[mt][hf] = mnew;
            }
        __syncthreads();

        // ---- pass C: finish l ----
#pragma unroll
        for (int mt = 0; mt < 2; mt++)
#pragma unroll
            for (int hf = 0; hf < 2; hf++) {
                const int rloc = wm + mt * 16 + (lane >> 2) + hf * 8;
                lrow[mt][hf] += redS[0][rloc] + redS[1][rloc];
            }

        // ---- P @ V (single pass), accumulate into Oacc ----
        CP_WAIT0();
        __syncthreads();
        const int rl = lane & 15;
        const int kb = lane >> 4;
#pragma unroll
        for (int c = 0; c < 2; c++) {
#pragma unroll
            for (int k16 = 0; k16 < 4; k16++) {
                const int kbyte = k16 * 32 + kb * 16;
                uint32_t pfh[2][4], vf[4][4];
#pragma unroll
                for (int mt = 0; mt < 2; mt++) {
                    const uint32_t off = SWZ((wm + mt * 16 + rl) * 128 + kbyte);
                    LDSM4(pfh[mt], sb + c * 16384 + off);
                }
#pragma unroll
                for (int q = 0; q < 4; q++) {
                    const uint32_t off = SWZ((wn + q * 16 + rl) * 128 + kbyte);
                    LDSM4(vf[q], sb + 98304 + c * 16384 + off);
                }
#pragma unroll
                for (int mt = 0; mt < 2; mt++)
#pragma unroll
                    for (int nt = 0; nt < 8; nt++) {
                        const int q = nt >> 1, s = nt & 1;
                        MMA_F16(Oacc[mt][nt], pfh[mt], vf[q][s], vf[q][s + 2]);
                    }
            }
        }
        __syncthreads();   // protect P/V smem before next jt's loads
    }

    // ---- epilogue: normalize and write ctx fp16 ----
#pragma unroll
    for (int mt = 0; mt < 2; mt++)
#pragma unroll
        for (int hf = 0; hf < 2; hf++) {
            const int row = m0 + wm + mt * 16 + (lane >> 2) + hf * 8;
            const float inv = 1.0f / lrow[mt][hf];
#pragma unroll
            for (int nt = 0; nt < 8; nt++) {
                const int col = wn + nt * 8 + (lane & 3) * 2;
                const size_t o = (size_t)row * CTX_D + (size_t)h * DV + col;
                *reinterpret_cast<__half2*>(ch + o) =
                    __half2(__float2half_rn(Oacc[mt][nt][hf * 2] * inv),
                            __float2half_rn(Oacc[mt][nt][hf * 2 + 1] * inv));
            }
        }
}

// ---------------- weight converts ----------------
__global__ void conv_w2(const float* __restrict__ W, __half* __restrict__ Th, int K, int N)
{
    __shared__ float t[64][33];
    const int k0 = blockIdx.x * 64, n0 = blockIdx.y * 32;
    const int tx = threadIdx.x, ty = threadIdx.y;
#pragma unroll
    for (int i = 0; i < 8; i++)
        t[ty + i * 8][tx] = W[(size_t)(k0 + ty + i * 8) * N + n0 + tx];
    __syncthreads();
#pragma unroll
    for (int i = 0; i < 4; i++) {
        const int n = n0 + ty + i * 8;
        const int cidx = ty + i * 8;
        __half2 v = __half2(__float2half_rn(t[tx * 2][cidx]),
                            __float2half_rn(t[tx * 2 + 1][cidx]));
        *reinterpret_cast<__half2*>(Th + (size_t)n * K + k0 + tx * 2) = v;
    }
}

// vectorized hi/lo split convert: 64k x 32n tile, __half2 stores, n guarded
__global__ void conv_w_split2(const float* __restrict__ W, __half* __restrict__ Th,
                              __half* __restrict__ Tl, int K, int N)
{
    __shared__ float t[64][33];
    const int k0 = blockIdx.x * 64, n0 = blockIdx.y * 32;
    const int tx = threadIdx.x, ty = threadIdx.y;
#pragma unroll
    for (int i = 0; i < 8; i++) {
        const int n = n0 + tx;
        t[ty + i * 8][tx] = (n < N) ? W[(size_t)(k0 + ty + i * 8) * N + n] : 0.0f;
    }
    __syncthreads();
#pragma unroll
    for (int i = 0; i < 4; i++) {
        const int n = n0 + ty + i * 8;
        const int cidx = ty + i * 8;
        __half h0, l0, h1, l1;
        split_h(t[tx * 2][cidx], h0, l0);
        split_h(t[tx * 2 + 1][cidx], h1, l1);
        const size_t o = (size_t)n * K + k0 + tx * 2;
        *reinterpret_cast<__half2*>(Th + o) = __half2(h0, h1);
        *reinterpret_cast<__half2*>(Tl + o) = __half2(l0, l1);
    }
}

// ---------------- activation convert ----------------
__global__ void conv_a(const float* __restrict__ A, __half* __restrict__ H,
                       __half* __restrict__ L, int n4)
{
    const int i = blockIdx.x * blockDim.x + threadIdx.x;
    if (i >= n4) return;
    const float4 v = reinterpret_cast<const float4*>(A)[i];
    __half h0, l0, h1, l1, h2, l2, h3, l3;
    split_h(v.x, h0, l0); split_h(v.y, h1, l1);
    split_h(v.z, h2, l2); split_h(v.w, h3, l3);
    __half2* Hp = reinterpret_cast<__half2*>(H) + i * 2;
    __half2* Lp = reinterpret_cast<__half2*>(L) + i * 2;
    Hp[0] = __half2(h0, h1); Hp[1] = __half2(h2, h3);
    Lp[0] = __half2(l0, l1); Lp[1] = __half2(l2, l3);
}

// ---------------- rmsnorm fused to fp16 hi/lo ----------------
__global__ void rmsnorm_h(const float* __restrict__ x, const float* __restrict__ gamma,
                          __half* __restrict__ yh, __half* __restrict__ yl,
                          int D, int xstride)
{
    const int row = blockIdx.x;
    const float* xr = x + (size_t)row * xstride;
    float s = 0.0f;
    for (int i = threadIdx.x; i < D; i += 256) { const float v = xr[i]; s += v * v; }
    __shared__ float red[256];
    red[threadIdx.x] = s;
    __syncthreads();
    for (int o = 128; o > 0; o >>= 1) {
        if (threadIdx.x < o) red[threadIdx.x] += red[threadIdx.x + o];
        __syncthreads();
    }
    const float inv = rsqrtf(red[0] / (float)D + 1e-6f);
    for (int i = threadIdx.x; i < D; i += 256) {
        __half h, l;
        split_h(xr[i] * inv * gamma[i], h, l);
        yh[(size_t)row * D + i] = h;
        yl[(size_t)row * D + i] = l;
    }
}

// ---------------- k_pe RoPE ----------------
__global__ void rope_k_kernel(const float* __restrict__ comp, float* __restrict__ kpe)
{
    const int t = blockIdx.x * blockDim.x + threadIdx.x;
    if (t >= S_LEN * 32) return;
    const int d = t & 31;
    const int s = t >> 5;
    float c, sn;
    rope_cs(s, d, c, sn);
    const float* src = comp + (size_t)s * COMP_D + QLORA + KVLORA;
    const float x1 = src[d], x2 = src[d + 32];
    kpe[s * DR + d]      = x1 * c - x2 * sn;
    kpe[s * DR + d + 32] = x2 * c + x1 * sn;
}

// ---------------- broadcast roped k_pe into per-head K cols 128..191 (hi only) --
__global__ void fill_kpe(const float* __restrict__ kpe, __half* __restrict__ Kh)
{
    const int t = blockIdx.x * blockDim.x + threadIdx.x;
    if (t >= NH * S_LEN * 32) return;
    const int d2 = t & 31;
    const int j  = (t >> 5) & (S_LEN - 1);
    const int h  = t >> 15;
    const int d = d2 * 2;
    const size_t o = ((size_t)h * S_LEN + j) * DQK + 128 + d;
    *reinterpret_cast<__half2*>(Kh + o) =
        __half2(__float2half_rn(kpe[j * DR + d]),
                __float2half_rn(kpe[j * DR + d + 1]));
}

// ---------------- build V^T per head (transpose, single fp16) ----------------
__global__ void build_vt(const float* __restrict__ kv, __half* __restrict__ Vth)
{
    __shared__ float t[32][33];
    const int j0 = blockIdx.x * 32, d0 = blockIdx.y * 32, h = blockIdx.z;
    const int tx = threadIdx.x, ty = threadIdx.y;
#pragma unroll
    for (int i = 0; i < 4; i++)
        t[ty + i * 8][tx] = kv[(size_t)(j0 + ty + i * 8) * KVD + h * 256 + 128 + d0 + tx];
    __syncthreads();
    const size_t base = (size_t)h * DV * S_LEN;
#pragma unroll
    for (int i = 0; i < 4; i++)
        Vth[base + (size_t)(d0 + ty + i * 8) * S_LEN + j0 + tx] =
            __float2half_rn(t[tx][ty + i * 8]);
}

// ---------------- launch ----------------
extern "C" void kernel_launch(void* const* d_in, const int* in_sizes, int n_in,
                              void* d_out, int out_size)
{
    const float* hs       = (const float*)d_in[0];
    const float* w_kv_a   = (const float*)d_in[1];
    const float* q_gamma  = (const float*)d_in[2];
    const float* kv_gamma = (const float*)d_in[3];
    const float* w_q_b    = (const float*)d_in[4];
    const float* w_kv_b   = (const float*)d_in[5];
    const float* w_o      = (const float*)d_in[6];
    float* out = (float*)d_out;

    float *comp, *kv, *kpe;
    __half *ah, *al, *wah, *wal, *wq, *wkv, *wo, *qh, *ql, *kh, *vth;
    cudaGetSymbolAddress((void**)&comp, g_comp);
    cudaGetSymbolAddress((void**)&ah,   g_ah);
    cudaGetSymbolAddress((void**)&al,   g_al);
    cudaGetSymbolAddress((void**)&wah,  g_wa_h);
    cudaGetSymbolAddress((void**)&wal,  g_wa_l);
    cudaGetSymbolAddress((void**)&wq,   g_wq);
    cudaGetSymbolAddress((void**)&wkv,  g_wkv);
    cudaGetSymbolAddress((void**)&wo,   g_wo);
    cudaGetSymbolAddress((void**)&kv,   g_kv);
    cudaGetSymbolAddress((void**)&kpe,  g_kpe);
    cudaGetSymbolAddress((void**)&qh,   g_qh);
    cudaGetSymbolAddress((void**)&ql,   g_ql);
    cudaGetSymbolAddress((void**)&kh,   g_kh);
    cudaGetSymbolAddress((void**)&vth,  g_vth);

    cudaFuncSetAttribute(mma_gemm3, cudaFuncAttributeMaxDynamicSharedMemorySize, 131072);
    cudaFuncSetAttribute(mma_gemm_q, cudaFuncAttributeMaxDynamicSharedMemorySize, 98304);
    cudaFuncSetAttribute(mma_gemm_kv, cudaFuncAttributeMaxDynamicSharedMemorySize, 98304);
    cudaFuncSetAttribute(mma_gemm1, cudaFuncAttributeMaxDynamicSharedMemorySize, 65536);
    cudaFuncSetAttribute(flash_mma, cudaFuncAttributeMaxDynamicSharedMemorySize, 131072);
    const dim3 T256(256);
    const dim3 TW(32, 8);

    // side stream + events (created per call; never destroyed)
    cudaStream_t s2;
    cudaStreamCreateWithFlags(&s2, cudaStreamNonBlocking);
    cudaEvent_t evFork, evA, evQ, evKV, evO, evComp, evKpe;
    cudaEventCreateWithFlags(&evFork, cudaEventDisableTiming);
    cudaEventCreateWithFlags(&evA,    cudaEventDisableTiming);
    cudaEventCreateWithFlags(&evQ,    cudaEventDisableTiming);
    cudaEventCreateWithFlags(&evKV,   cudaEventDisableTiming);
    cudaEventCreateWithFlags(&evO,    cudaEventDisableTiming);
    cudaEventCreateWithFlags(&evComp, cudaEventDisableTiming);
    cudaEventCreateWithFlags(&evKpe,  cudaEventDisableTiming);

    cudaEventRecord(evFork, 0);
    cudaStreamWaitEvent(s2, evFork, 0);

    // side stream: activation split + independent weight conversions
    conv_a<<<(S_LEN * HID_D / 4 + 255) / 256, 256, 0, s2>>>(hs, ah, al, S_LEN * HID_D / 4);
    cudaEventRecord(evA, s2);
    conv_w2<<<dim3(QLORA / 64, QD / 32), TW, 0, s2>>>(w_q_b, wq, QLORA, QD);
    cudaEventRecord(evQ, s2);
    conv_w2<<<dim3(KVLORA / 64, KVD / 32), TW, 0, s2>>>(w_kv_b, wkv, KVLORA, KVD);
    cudaEventRecord(evKV, s2);
    conv_w2<<<dim3(CTX_D / 64, HID_D / 32), TW, 0, s2>>>(w_o, wo, CTX_D, HID_D);
    cudaEventRecord(evO, s2);

    // main stream
    // 1) comp = hs @ w_kv_a  (3-pass; N pad 2176)
    conv_w_split2<<<dim3(HID_D / 64, 2176 / 32), TW>>>(w_kv_a, wah, wal, HID_D, COMP_D);
    cudaStreamWaitEvent(0, evA, 0);
    mma_gemm3<<<dim3(17, 8), T256, 131072>>>(ah, al, wah, wal, comp, COMP_D, HID_D);
    cudaEventRecord(evComp, 0);

    // side stream: k_pe RoPE + per-head broadcast (parallel with q GEMM)
    cudaStreamWaitEvent(s2, evComp, 0);
    rope_k_kernel<<<(S_LEN * 32) / 256, 256, 0, s2>>>(comp, kpe);
    fill_kpe<<<(NH * S_LEN * 32) / 256, 256, 0, s2>>>(kpe, kh);
    cudaEventRecord(evKpe, s2);

    // 2) q = rmsnorm(q_c) @ w_q_b, fused RoPE+split -> per-head Qh/Ql
    rmsnorm_h<<<S_LEN, 256>>>(comp, q_gamma, ah, al, QLORA, COMP_D);
    cudaStreamWaitEvent(0, evQ, 0);
    mma_gemm_q<<<dim3(QD / 128, 8), T256, 98304>>>(ah, al, wq, qh, ql);

    // 3) kv = rmsnorm(kv_c) @ w_kv_b, fused -> Kh (nope) + kv fp32 (v)
    rmsnorm_h<<<S_LEN, 256>>>(comp + QLORA, kv_gamma, ah, al, KVLORA, COMP_D);
    cudaStreamWaitEvent(0, evKV, 0);
    mma_gemm_kv<<<dim3(KVD / 128, 8), T256, 98304>>>(ah, al, wkv, kh, kv);
    build_vt<<<dim3(32, 4, NH), TW>>>(kv, vth);

    // 4) fused flash attention -> ctx fp16 in ah
    cudaStreamWaitEvent(0, evKpe, 0);
    flash_mma<<<dim3(NH, 8), T256, 131072>>>(qh, ql, kh, vth, ah);

    // 5) out = ctx @ w_o  (1-pass)
    cudaStreamWaitEvent(0, evO, 0);
    mma_gemm1<<<dim3(HID_D / 128, 8), T256, 65536>>>(ah, wo, out, HID_D, CTX_D);
}

// round 13
// speedup vs baseline: 1.3129x; 1.1148x over previous
#include <cuda_runtime.h>
#include <cuda_fp16.h>
#include <math.h>
#include <stdint.h>

// ---------------- problem constants ----------------
#define S_LEN 1024
#define HID_D 7168
#define NH 128
#define DN 128
#define DR 64
#define DV 128
#define QLORA 1536
#define KVLORA 512
#define COMP_D (QLORA + KVLORA + DR)      // 2112
#define QD (NH * (DN + DR))               // 24576
#define KVD (NH * (DN + DV))              // 32768
#define CTX_D (NH * DV)                   // 16384
#define DQK 192

// ---------------- scratch (device globals) ----------------
__device__ float g_comp[S_LEN * COMP_D];
__device__ __half g_ah[(size_t)S_LEN * 16384];                   // activations hi (also ctx)
__device__ __half g_al[(size_t)S_LEN * 16384];                   // activations lo
__device__ __half g_wa_h[15597568];                              // w_kv_a hi (2176*7168)
__device__ __half g_wa_l[15597568];                              // w_kv_a lo
__device__ __half g_wq[(size_t)QD * QLORA];                      // w_q_b^T
__device__ __half g_wkv[(size_t)KVD * KVLORA];                   // w_kv_b^T
__device__ __half g_wo[(size_t)HID_D * CTX_D];                   // w_o^T
__device__ float g_kv[(size_t)S_LEN * KVD];                      // v half only used
__device__ float g_kpe[S_LEN * DR];
__device__ __half g_qh[(size_t)NH * S_LEN * DQK];
__device__ __half g_ql[(size_t)NH * S_LEN * DQK];
__device__ __half g_kh[(size_t)NH * S_LEN * DQK];
__device__ __half g_vth[(size_t)NH * DV * S_LEN];

// ---------------- PTX helpers ----------------
__device__ __forceinline__ uint32_t smem_u32(const void* p) {
    uint32_t a;
    asm("{ .reg .u64 t; cvta.to.shared.u64 t, %1; cvt.u32.u64 %0, t; }" : "=r"(a) : "l"(p));
    return a;
}
#define CP16(dst, src) \
    asm volatile("cp.async.cg.shared.global [%0], [%1], 16;" :: "r"(dst), "l"(src) : "memory")
#define CP_COMMIT() asm volatile("cp.async.commit_group;" ::: "memory")
#define CP_WAIT1() asm volatile("cp.async.wait_group 1;" ::: "memory")
#define CP_WAIT0() asm volatile("cp.async.wait_group 0;" ::: "memory")

#define LDSM4(r, a) \
    asm volatile("ldmatrix.sync.aligned.m8n8.x4.shared.b16 {%0,%1,%2,%3}, [%4];" \
        : "=r"((r)[0]), "=r"((r)[1]), "=r"((r)[2]), "=r"((r)[3]) : "r"(a))

#define MMA_F16(d, a, b0, b1) \
    asm volatile("mma.sync.aligned.m16n8k16.row.col.f32.f16.f16.f32 " \
        "{%0,%1,%2,%3}, {%4,%5,%6,%7}, {%8,%9}, {%0,%1,%2,%3};" \
        : "+f"((d)[0]), "+f"((d)[1]), "+f"((d)[2]), "+f"((d)[3]) \
        : "r"((a)[0]), "r"((a)[1]), "r"((a)[2]), "r"((a)[3]), "r"(b0), "r"(b1))

#define SWZ(o) ((o) ^ (((o) >> 3) & 0x70))

__device__ __forceinline__ void split_h(float v, __half& h, __half& l) {
    h = __float2half_rn(v);
    l = __float2half_rn(v - __half2float(h));
}

// ---------------- shared GEMM body (2-stage pipeline, R8-proven) ----------------
// NPASS=1: ah*bh        NPASS=2: ah*bh + al*bh        NPASS=3: + ah*bl
template <int NPASS>
__device__ __forceinline__ void gemm_body(
    const __half* __restrict__ Ah, const __half* __restrict__ Al,
    const __half* __restrict__ Bh, const __half* __restrict__ Bl,
    int K, int nch, int m0, int n0, uint32_t sb, int tid, float acc[2][8][4])
{
    constexpr int CA = (NPASS >= 2) ? 2 : 1;
    constexpr int CB = (NPASS == 3) ? 2 : 1;
    constexpr int NT = CA + CB;
    constexpr int STAGE = NT * 16384;
    const int lane = tid & 31;
    const int wid = tid >> 5;
    const int wm = (wid & 3) * 32;
    const int wn = (wid >> 2) * 64;

    auto load_stage = [&](int c, int s) {
        const int kc = c << 6;
#pragma unroll
        for (int it = 0; it < NT * 4; it++) {
            const int t = tid + it * 256;
            const int tensor = t >> 10;
            const int rem = t & 1023;
            const int row = rem >> 3;
            const int ch = rem & 7;
            const __half* src;
            int grow;
            if (tensor < CA) {
                src = (CA == 2 && tensor == 1) ? Al : Ah;
                grow = m0 + row;
            } else {
                src = (CB == 2 && tensor == CA + 1) ? Bl : Bh;
                grow = n0 + row;
            }
            const __half* sp = src + (size_t)grow * K + kc + ch * 8;
            const uint32_t dst = sb + s * STAGE + tensor * 16384 + SWZ(row * 128 + ch * 16);
            CP16(dst, sp);
        }
        CP_COMMIT();
    };

    load_stage(0, 0);

    for (int c = 0; c < nch; c++) {
        const int buf = c & 1;
        if (c + 1 < nch) { load_stage(c + 1, buf ^ 1); CP_WAIT1(); }
        else             { CP_WAIT0(); }
        __syncthreads();

        const uint32_t st = sb + buf * STAGE;
        const uint32_t sA_h = st;
        const uint32_t sA_l = st + 16384;
        const uint32_t sB_h = st + CA * 16384;
        const uint32_t sB_l = sB_h + 16384;
        const int rl = lane & 15;
        const int kb = lane >> 4;

#pragma unroll
        for (int k16 = 0; k16 < 4; k16++) {
            const int kbyte = k16 * 32 + kb * 16;
            uint32_t afh[2][4], afl[2][4], bfh[4][4], bfl[4][4];
#pragma unroll
            for (int mt = 0; mt < 2; mt++) {
                const uint32_t off = SWZ((wm + mt * 16 + rl) * 128 + kbyte);
                LDSM4(afh[mt], sA_h + off);
                if (CA == 2) LDSM4(afl[mt], sA_l + off);
            }
#pragma unroll
            for (int q = 0; q < 4; q++) {
                const uint32_t off = SWZ((wn + q * 16 + rl) * 128 + kbyte);
                LDSM4(bfh[q], sB_h + off);
                if (CB == 2) LDSM4(bfl[q], sB_l + off);
            }
#pragma unroll
            for (int mt = 0; mt < 2; mt++)
#pragma unroll
                for (int nt = 0; nt < 8; nt++) {
                    const int q = nt >> 1, s = nt & 1;
                    MMA_F16(acc[mt][nt], afh[mt], bfh[q][s], bfh[q][s + 2]);
                    if (CA == 2) MMA_F16(acc[mt][nt], afl[mt], bfh[q][s], bfh[q][s + 2]);
                    if (CB == 2) MMA_F16(acc[mt][nt], afh[mt], bfl[q][s], bfl[q][s + 2]);
                }
        }
        __syncthreads();
    }
}

#define GEMM_PROLOGUE() \
    extern __shared__ __align__(128) char smem[]; \
    const uint32_t sb = smem_u32(smem); \
    const int tid = threadIdx.x; \
    const int lane = tid & 31; \
    const int wid = tid >> 5; \
    const int m0 = blockIdx.y * 128, n0 = blockIdx.x * 128; \
    const int wm = (wid & 3) * 32, wn = (wid >> 2) * 64; \
    float acc[2][8][4]; \
    _Pragma("unroll") for (int mt = 0; mt < 2; mt++) \
    _Pragma("unroll") for (int nt = 0; nt < 8; nt++) \
    _Pragma("unroll") for (int e = 0; e < 4; e++) acc[mt][nt][e] = 0.0f;

// ---------------- comp GEMM: 3-pass, fp32 out (128KB smem -> 1 CTA/SM) ----------
__global__ __launch_bounds__(256, 1) void mma_gemm3(
    const __half* __restrict__ Ah, const __half* __restrict__ Al,
    const __half* __restrict__ Bh, const __half* __restrict__ Bl,
    float* __restrict__ C, int N, int K)
{
    GEMM_PROLOGUE();
    gemm_body<3>(Ah, Al, Bh, Bl, K, K >> 6, m0, n0, sb, tid, acc);
#pragma unroll
    for (int mt = 0; mt < 2; mt++) {
        const int row = m0 + wm + mt * 16 + (lane >> 2);
#pragma unroll
        for (int nt = 0; nt < 8; nt++) {
            const int col = n0 + wn + nt * 8 + (lane & 3) * 2;
            if (col < N) {
                *reinterpret_cast<float2*>(C + (size_t)row * N + col) =
                    make_float2(acc[mt][nt][0], acc[mt][nt][1]);
                *reinterpret_cast<float2*>(C + (size_t)(row + 8) * N + col) =
                    make_float2(acc[mt][nt][2], acc[mt][nt][3]);
            }
        }
    }
}

// ---------------- w_o GEMM: 1-pass, fp32 out (64KB, 2 CTA/SM) ----------
__global__ __launch_bounds__(256, 2) void mma_gemm1(
    const __half* __restrict__ Ah, const __half* __restrict__ Bh,
    float* __restrict__ C, int N, int K)
{
    GEMM_PROLOGUE();
    gemm_body<1>(Ah, nullptr, Bh, nullptr, K, K >> 6, m0, n0, sb, tid, acc);
#pragma unroll
    for (int mt = 0; mt < 2; mt++) {
        const int row = m0 + wm + mt * 16 + (lane >> 2);
#pragma unroll
        for (int nt = 0; nt < 8; nt++) {
            const int col = n0 + wn + nt * 8 + (lane & 3) * 2;
            *reinterpret_cast<float2*>(C + (size_t)row * N + col) =
                make_float2(acc[mt][nt][0], acc[mt][nt][1]);
            *reinterpret_cast<float2*>(C + (size_t)(row + 8) * N + col) =
                make_float2(acc[mt][nt][2], acc[mt][nt][3]);
        }
    }
}

// ---------------- RoPE angle ----------------
__device__ __forceinline__ void rope_cs(int s, int d, float& c, float& sn)
{
    const float inv = exp2f(-(float)d * (13.287712379549449f / 32.0f));
    sincosf((float)s * inv, &sn, &c);
}

// ---------------- q GEMM: 1-pass (ah x wq), fused RoPE + split (64KB, 2 CTA/SM) -
__global__ __launch_bounds__(256, 2) void mma_gemm_q(
    const __half* __restrict__ Ah, const __half* __restrict__ Bh,
    __half* __restrict__ Qh, __half* __restrict__ Ql)
{
    GEMM_PROLOGUE();
    gemm_body<1>(Ah, nullptr, Bh, nullptr, QLORA, QLORA >> 6, m0, n0, sb, tid, acc);

    const int base64 = n0 + wn;
    if ((base64 / 64) % 3 != 2) {
#pragma unroll
        for (int mt = 0; mt < 2; mt++)
#pragma unroll
            for (int half_i = 0; half_i < 2; half_i++) {
                const int row = m0 + wm + mt * 16 + (lane >> 2) + half_i * 8;
#pragma unroll
                for (int nt = 0; nt < 8; nt++) {
                    const int c = base64 + nt * 8 + (lane & 3) * 2;
                    const int h = c / 192;
                    const int cr = c - h * 192;
                    const size_t o = ((size_t)h * S_LEN + row) * DQK + cr;
                    __half h0, l0, h1, l1;
                    split_h(acc[mt][nt][half_i * 2], h0, l0);
                    split_h(acc[mt][nt][half_i * 2 + 1], h1, l1);
                    *reinterpret_cast<__half2*>(Qh + o) = __half2(h0, h1);
                    *reinterpret_cast<__half2*>(Ql + o) = __half2(l0, l1);
                }
            }
    } else {
        const int h = base64 / 192;
#pragma unroll
        for (int mt = 0; mt < 2; mt++)
#pragma unroll
            for (int half_i = 0; half_i < 2; half_i++) {
                const int row = m0 + wm + mt * 16 + (lane >> 2) + half_i * 8;
                const size_t rb = ((size_t)h * S_LEN + row) * DQK + 128;
#pragma unroll
                for (int ntL = 0; ntL < 4; ntL++) {
                    const int d0 = ntL * 8 + (lane & 3) * 2;
                    float o0[2], o1[2];
#pragma unroll
                    for (int e = 0; e < 2; e++) {
                        float cc, ss;
                        rope_cs(row, d0 + e, cc, ss);
                        const float v1 = acc[mt][ntL][half_i * 2 + e];
                        const float v2 = acc[mt][ntL + 4][half_i * 2 + e];
                        o0[e] = v1 * cc - v2 * ss;
                        o1[e] = v2 * cc + v1 * ss;
                    }
                    __half h0, l0, h1, l1;
                    split_h(o0[0], h0, l0); split_h(o0[1], h1, l1);
                    *reinterpret_cast<__half2*>(Qh + rb + d0) = __half2(h0, h1);
                    *reinterpret_cast<__half2*>(Ql + rb + d0) = __half2(l0, l1);
                    split_h(o1[0], h0, l0); split_h(o1[1], h1, l1);
                    *reinterpret_cast<__half2*>(Qh + rb + d0 + 32) = __half2(h0, h1);
                    *reinterpret_cast<__half2*>(Ql + rb + d0 + 32) = __half2(l0, l1);
                }
            }
    }
}

// ---------------- kv GEMM: 2-pass, k_nope -> Kh only; v -> fp32 (96KB, 2 CTA/SM)
__global__ __launch_bounds__(256, 2) void mma_gemm_kv(
    const __half* __restrict__ Ah, const __half* __restrict__ Al,
    const __half* __restrict__ Bh,
    __half* __restrict__ Kh, float* __restrict__ kv)
{
    GEMM_PROLOGUE();
    gemm_body<2>(Ah, Al, Bh, nullptr, KVLORA, KVLORA >> 6, m0, n0, sb, tid, acc);

    const int base64 = n0 + wn;
    const int blk4 = (base64 / 64) & 3;
    if (blk4 < 2) {
        const int h = base64 / 256;
#pragma unroll
        for (int mt = 0; mt < 2; mt++)
#pragma unroll
            for (int half_i = 0; half_i < 2; half_i++) {
                const int row = m0 + wm + mt * 16 + (lane >> 2) + half_i * 8;
#pragma unroll
                for (int nt = 0; nt < 8; nt++) {
                    const int c = base64 + nt * 8 + (lane & 3) * 2;
                    const int cr = c - h * 256;
                    const size_t o = ((size_t)h * S_LEN + row) * DQK + cr;
                    *reinterpret_cast<__half2*>(Kh + o) =
                        __half2(__float2half_rn(acc[mt][nt][half_i * 2]),
                                __float2half_rn(acc[mt][nt][half_i * 2 + 1]));
                }
            }
    } else {
#pragma unroll
        for (int mt = 0; mt < 2; mt++) {
            const int row = m0 + wm + mt * 16 + (lane >> 2);
#pragma unroll
            for (int nt = 0; nt < 8; nt++) {
                const int c = base64 + nt * 8 + (lane & 3) * 2;
                *reinterpret_cast<float2*>(kv + (size_t)row * KVD + c) =
                    make_float2(acc[mt][nt][0], acc[mt][nt][1]);
                *reinterpret_cast<float2*>(kv + (size_t)(row + 8) * KVD + c) =
                    make_float2(acc[mt][nt][2], acc[mt][nt][3]);
            }
        }
    }
}

// ---------------- fused flash attention per (head, i-tile) ----------------
// S phase: 2-pass (Qh+Ql) x Kh. smem: [0,96K) stages (P reuses [0,32K)), [96K,128K) V
__global__ __launch_bounds__(256, 1) void flash_mma(
    const __half* __restrict__ Qh, const __half* __restrict__ Ql,
    const __half* __restrict__ Kh,
    const __half* __restrict__ Vth, __half* __restrict__ ch)
{
    extern __shared__ __align__(128) char smem[];
    __shared__ float redM[2][128];
    __shared__ float redS[2][128];
    const uint32_t sb = smem_u32(smem);
    const int tid = threadIdx.x;
    const int lane = tid & 31;
    const int wid = tid >> 5;
    const int h = blockIdx.x;
    const int it = 7 - blockIdx.y;          // heavy tiles first
    const int m0 = it * 128;
    const int wm = (wid & 3) * 32, wn = (wid >> 2) * 64;
    const int ng = wid >> 2;
    const size_t hoff = (size_t)h * S_LEN * DQK;
    const size_t voff = (size_t)h * DV * S_LEN;
    const float scale = 0.07216878364870323f;   // 1/sqrt(192)

    float Oacc[2][8][4];
    float mrow[2][2], lrow[2][2];
#pragma unroll
    for (int mt = 0; mt < 2; mt++)
#pragma unroll
        for (int nt = 0; nt < 8; nt++)
#pragma unroll
            for (int e = 0; e < 4; e++) Oacc[mt][nt][e] = 0.0f;
#pragma unroll
    for (int mt = 0; mt < 2; mt++)
#pragma unroll
        for (int hf = 0; hf < 2; hf++) { mrow[mt][hf] = -3.4e38f; lrow[mt][hf] = 0.0f; }

    for (int jt = 0; jt <= it; jt++) {
        // ---- S = (Qh+Ql) @ Kh^T (2-pass) ----
        float Sacc[2][8][4];
#pragma unroll
        for (int mt = 0; mt < 2; mt++)
#pragma unroll
            for (int nt = 0; nt < 8; nt++)
#pragma unroll
                for (int e = 0; e < 4; e++) Sacc[mt][nt][e] = 0.0f;

        gemm_body<2>(Qh + hoff, Ql + hoff, Kh + hoff, nullptr,
                     DQK, 3, m0, jt * 128, sb, tid, Sacc);

        // ---- prefetch V tile (2 chunks of [128 d][64 j]) at [96K,128K) ----
#pragma unroll
        for (int itv = 0; itv < 8; itv++) {
            const int t = tid + itv * 256;
            const int c = t >> 10;
            const int rem = t & 1023;
            const int d = rem >> 3;
            const int seg = rem & 7;
            const __half* sp = Vth + voff + (size_t)d * S_LEN + jt * 128 + c * 64 + seg * 8;
            CP16(sb + 98304 + c * 16384 + SWZ(d * 128 + seg * 16), sp);
        }
        CP_COMMIT();

        // ---- pass A: scale + mask + row max ----
#pragma unroll
        for (int mt = 0; mt < 2; mt++)
#pragma unroll
            for (int hf = 0; hf < 2; hf++) {
                const int rloc = wm + mt * 16 + (lane >> 2) + hf * 8;
                float mx = -3.4e38f;
#pragma unroll
                for (int nt = 0; nt < 8; nt++)
#pragma unroll
                    for (int e = 0; e < 2; e++) {
                        float s = Sacc[mt][nt][hf * 2 + e] * scale;
                        if (jt == it) {
                            const int cg = jt * 128 + wn + nt * 8 + (lane & 3) * 2 + e;
                            if (cg > m0 + rloc) s = -3.4e38f;
                        }
                        Sacc[mt][nt][hf * 2 + e] = s;
                        mx = fmaxf(mx, s);
                    }
                mx = fmaxf(mx, __shfl_xor_sync(0xFFFFFFFFu, mx, 1));
                mx = fmaxf(mx, __shfl_xor_sync(0xFFFFFFFFu, mx, 2));
                if ((lane & 3) == 0) redM[ng][rloc] = mx;
            }
        __syncthreads();

        // ---- pass B: exp, write P (single fp16) to smem, row sums, O rescale ----
#pragma unroll
        for (int mt = 0; mt < 2; mt++)
#pragma unroll
            for (int hf = 0; hf < 2; hf++) {
                const int rloc = wm + mt * 16 + (lane >> 2) + hf * 8;
                const float mnew = fmaxf(mrow[mt][hf],
                                         fmaxf(redM[0][rloc], redM[1][rloc]));
                float ssum = 0.0f;
#pragma unroll
                for (int nt = 0; nt < 8; nt++) {
                    const float p0 = __expf(Sacc[mt][nt][hf * 2] - mnew);
                    const float p1 = __expf(Sacc[mt][nt][hf * 2 + 1] - mnew);
                    ssum += p0 + p1;
                    const uint32_t off = SWZ(rloc * 128 + (nt * 8 + (lane & 3) * 2) * 2);
                    *reinterpret_cast<__half2*>(smem + ng * 16384 + off) =
                        __half2(__float2half_rn(p0), __float2half_rn(p1));
                }
                ssum += __shfl_xor_sync(0xFFFFFFFFu, ssum, 1);
                ssum += __shfl_xor_sync(0xFFFFFFFFu, ssum, 2);
                if ((lane & 3) == 0) redS[ng][rloc] = ssum;
                const float sc = __expf(mrow[mt][hf] - mnew);
#pragma unroll
                for (int nt = 0; nt < 8; nt++) {
                    Oacc[mt][nt][hf * 2] *= sc;
                    Oacc[mt][nt][hf * 2 + 1] *= sc;
                }
                lrow[mt][hf] *= sc;
                mrow[mt][hf] = mnew;
            }
        __syncthreads();

        // ---- pass C: finish l ----
#pragma unroll
        for (int mt = 0; mt < 2; mt++)
#pragma unroll
            for (int hf = 0; hf < 2; hf++) {
                const int rloc = wm + mt * 16 + (lane >> 2) + hf * 8;
                lrow[mt][hf] += redS[0][rloc] + redS[1][rloc];
            }

        // ---- P @ V (single pass), accumulate into Oacc ----
        CP_WAIT0();
        __syncthreads();
        const int rl = lane & 15;
        const int kb = lane >> 4;
#pragma unroll
        for (int c = 0; c < 2; c++) {
#pragma unroll
            for (int k16 = 0; k16 < 4; k16++) {
                const int kbyte = k16 * 32 + kb * 16;
                uint32_t pfh[2][4], vf[4][4];
#pragma unroll
                for (int mt = 0; mt < 2; mt++) {
                    const uint32_t off = SWZ((wm + mt * 16 + rl) * 128 + kbyte);
                    LDSM4(pfh[mt], sb + c * 16384 + off);
                }
#pragma unroll
                for (int q = 0; q < 4; q++) {
                    const uint32_t off = SWZ((wn + q * 16 + rl) * 128 + kbyte);
                    LDSM4(vf[q], sb + 98304 + c * 16384 + off);
                }
#pragma unroll
                for (int mt = 0; mt < 2; mt++)
#pragma unroll
                    for (int nt = 0; nt < 8; nt++) {
                        const int q = nt >> 1, s = nt & 1;
                        MMA_F16(Oacc[mt][nt], pfh[mt], vf[q][s], vf[q][s + 2]);
                    }
            }
        }
        __syncthreads();   // protect P/V smem before next jt's loads
    }

    // ---- epilogue: normalize and write ctx fp16 ----
#pragma unroll
    for (int mt = 0; mt < 2; mt++)
#pragma unroll
        for (int hf = 0; hf < 2; hf++) {
            const int row = m0 + wm + mt * 16 + (lane >> 2) + hf * 8;
            const float inv = 1.0f / lrow[mt][hf];
#pragma unroll
            for (int nt = 0; nt < 8; nt++) {
                const int col = wn + nt * 8 + (lane & 3) * 2;
                const size_t o = (size_t)row * CTX_D + (size_t)h * DV + col;
                *reinterpret_cast<__half2*>(ch + o) =
                    __half2(__float2half_rn(Oacc[mt][nt][hf * 2] * inv),
                            __float2half_rn(Oacc[mt][nt][hf * 2 + 1] * inv));
            }
        }
}

// ---------------- weight converts ----------------
__global__ void conv_w2(const float* __restrict__ W, __half* __restrict__ Th, int K, int N)
{
    __shared__ float t[64][33];
    const int k0 = blockIdx.x * 64, n0 = blockIdx.y * 32;
    const int tx = threadIdx.x, ty = threadIdx.y;
#pragma unroll
    for (int i = 0; i < 8; i++)
        t[ty + i * 8][tx] = W[(size_t)(k0 + ty + i * 8) * N + n0 + tx];
    __syncthreads();
#pragma unroll
    for (int i = 0; i < 4; i++) {
        const int n = n0 + ty + i * 8;
        const int cidx = ty + i * 8;
        __half2 v = __half2(__float2half_rn(t[tx * 2][cidx]),
                            __float2half_rn(t[tx * 2 + 1][cidx]));
        *reinterpret_cast<__half2*>(Th + (size_t)n * K + k0 + tx * 2) = v;
    }
}

// vectorized hi/lo split convert: 64k x 32n tile, __half2 stores, n guarded
__global__ void conv_w_split2(const float* __restrict__ W, __half* __restrict__ Th,
                              __half* __restrict__ Tl, int K, int N)
{
    __shared__ float t[64][33];
    const int k0 = blockIdx.x * 64, n0 = blockIdx.y * 32;
    const int tx = threadIdx.x, ty = threadIdx.y;
#pragma unroll
    for (int i = 0; i < 8; i++) {
        const int n = n0 + tx;
        t[ty + i * 8][tx] = (n < N) ? W[(size_t)(k0 + ty + i * 8) * N + n] : 0.0f;
    }
    __syncthreads();
#pragma unroll
    for (int i = 0; i < 4; i++) {
        const int n = n0 + ty + i * 8;
        const int cidx = ty + i * 8;
        __half h0, l0, h1, l1;
        split_h(t[tx * 2][cidx], h0, l0);
        split_h(t[tx * 2 + 1][cidx], h1, l1);
        const size_t o = (size_t)n * K + k0 + tx * 2;
        *reinterpret_cast<__half2*>(Th + o) = __half2(h0, h1);
        *reinterpret_cast<__half2*>(Tl + o) = __half2(l0, l1);
    }
}

// ---------------- activation convert ----------------
__global__ void conv_a(const float* __restrict__ A, __half* __restrict__ H,
                       __half* __restrict__ L, int n4)
{
    const int i = blockIdx.x * blockDim.x + threadIdx.x;
    if (i >= n4) return;
    const float4 v = reinterpret_cast<const float4*>(A)[i];
    __half h0, l0, h1, l1, h2, l2, h3, l3;
    split_h(v.x, h0, l0); split_h(v.y, h1, l1);
    split_h(v.z, h2, l2); split_h(v.w, h3, l3);
    __half2* Hp = reinterpret_cast<__half2*>(H) + i * 2;
    __half2* Lp = reinterpret_cast<__half2*>(L) + i * 2;
    Hp[0] = __half2(h0, h1); Hp[1] = __half2(h2, h3);
    Lp[0] = __half2(l0, l1); Lp[1] = __half2(l2, l3);
}

// ---------------- rmsnorm fused to fp16 hi/lo ----------------
__global__ void rmsnorm_h(const float* __restrict__ x, const float* __restrict__ gamma,
                          __half* __restrict__ yh, __half* __restrict__ yl,
                          int D, int xstride)
{
    const int row = blockIdx.x;
    const float* xr = x + (size_t)row * xstride;
    float s = 0.0f;
    for (int i = threadIdx.x; i < D; i += 256) { const float v = xr[i]; s += v * v; }
    __shared__ float red[256];
    red[threadIdx.x] = s;
    __syncthreads();
    for (int o = 128; o > 0; o >>= 1) {
        if (threadIdx.x < o) red[threadIdx.x] += red[threadIdx.x + o];
        __syncthreads();
    }
    const float inv = rsqrtf(red[0] / (float)D + 1e-6f);
    for (int i = threadIdx.x; i < D; i += 256) {
        __half h, l;
        split_h(xr[i] * inv * gamma[i], h, l);
        yh[(size_t)row * D + i] = h;
        yl[(size_t)row * D + i] = l;
    }
}

// ---------------- k_pe RoPE ----------------
__global__ void rope_k_kernel(const float* __restrict__ comp, float* __restrict__ kpe)
{
    const int t = blockIdx.x * blockDim.x + threadIdx.x;
    if (t >= S_LEN * 32) return;
    const int d = t & 31;
    const int s = t >> 5;
    float c, sn;
    rope_cs(s, d, c, sn);
    const float* src = comp + (size_t)s * COMP_D + QLORA + KVLORA;
    const float x1 = src[d], x2 = src[d + 32];
    kpe[s * DR + d]      = x1 * c - x2 * sn;
    kpe[s * DR + d + 32] = x2 * c + x1 * sn;
}

// ---------------- broadcast roped k_pe into per-head K cols 128..191 (hi only) --
__global__ void fill_kpe(const float* __restrict__ kpe, __half* __restrict__ Kh)
{
    const int t = blockIdx.x * blockDim.x + threadIdx.x;
    if (t >= NH * S_LEN * 32) return;
    const int d2 = t & 31;
    const int j  = (t >> 5) & (S_LEN - 1);
    const int h  = t >> 15;
    const int d = d2 * 2;
    const size_t o = ((size_t)h * S_LEN + j) * DQK + 128 + d;
    *reinterpret_cast<__half2*>(Kh + o) =
        __half2(__float2half_rn(kpe[j * DR + d]),
                __float2half_rn(kpe[j * DR + d + 1]));
}

// ---------------- build V^T per head (transpose, single fp16) ----------------
__global__ void build_vt(const float* __restrict__ kv, __half* __restrict__ Vth)
{
    __shared__ float t[32][33];
    const int j0 = blockIdx.x * 32, d0 = blockIdx.y * 32, h = blockIdx.z;
    const int tx = threadIdx.x, ty = threadIdx.y;
#pragma unroll
    for (int i = 0; i < 4; i++)
        t[ty + i * 8][tx] = kv[(size_t)(j0 + ty + i * 8) * KVD + h * 256 + 128 + d0 + tx];
    __syncthreads();
    const size_t base = (size_t)h * DV * S_LEN;
#pragma unroll
    for (int i = 0; i < 4; i++)
        Vth[base + (size_t)(d0 + ty + i * 8) * S_LEN + j0 + tx] =
            __float2half_rn(t[tx][ty + i * 8]);
}

// ---------------- launch ----------------
extern "C" void kernel_launch(void* const* d_in, const int* in_sizes, int n_in,
                              void* d_out, int out_size)
{
    const float* hs       = (const float*)d_in[0];
    const float* w_kv_a   = (const float*)d_in[1];
    const float* q_gamma  = (const float*)d_in[2];
    const float* kv_gamma = (const float*)d_in[3];
    const float* w_q_b    = (const float*)d_in[4];
    const float* w_kv_b   = (const float*)d_in[5];
    const float* w_o      = (const float*)d_in[6];
    float* out = (float*)d_out;

    float *comp, *kv, *kpe;
    __half *ah, *al, *wah, *wal, *wq, *wkv, *wo, *qh, *ql, *kh, *vth;
    cudaGetSymbolAddress((void**)&comp, g_comp);
    cudaGetSymbolAddress((void**)&ah,   g_ah);
    cudaGetSymbolAddress((void**)&al,   g_al);
    cudaGetSymbolAddress((void**)&wah,  g_wa_h);
    cudaGetSymbolAddress((void**)&wal,  g_wa_l);
    cudaGetSymbolAddress((void**)&wq,   g_wq);
    cudaGetSymbolAddress((void**)&wkv,  g_wkv);
    cudaGetSymbolAddress((void**)&wo,   g_wo);
    cudaGetSymbolAddress((void**)&kv,   g_kv);
    cudaGetSymbolAddress((void**)&kpe,  g_kpe);
    cudaGetSymbolAddress((void**)&qh,   g_qh);
    cudaGetSymbolAddress((void**)&ql,   g_ql);
    cudaGetSymbolAddress((void**)&kh,   g_kh);
    cudaGetSymbolAddress((void**)&vth,  g_vth);

    cudaFuncSetAttribute(mma_gemm3, cudaFuncAttributeMaxDynamicSharedMemorySize, 131072);
    cudaFuncSetAttribute(mma_gemm_q, cudaFuncAttributeMaxDynamicSharedMemorySize, 65536);
    cudaFuncSetAttribute(mma_gemm_kv, cudaFuncAttributeMaxDynamicSharedMemorySize, 98304);
    cudaFuncSetAttribute(mma_gemm1, cudaFuncAttributeMaxDynamicSharedMemorySize, 65536);
    cudaFuncSetAttribute(flash_mma, cudaFuncAttributeMaxDynamicSharedMemorySize, 131072);
    const dim3 T256(256);
    const dim3 TW(32, 8);

    // side stream + events (created per call; never destroyed)
    cudaStream_t s2;
    cudaStreamCreateWithFlags(&s2, cudaStreamNonBlocking);
    cudaEvent_t evFork, evA, evQ, evKV, evO, evComp, evKpe;
    cudaEventCreateWithFlags(&evFork, cudaEventDisableTiming);
    cudaEventCreateWithFlags(&evA,    cudaEventDisableTiming);
    cudaEventCreateWithFlags(&evQ,    cudaEventDisableTiming);
    cudaEventCreateWithFlags(&evKV,   cudaEventDisableTiming);
    cudaEventCreateWithFlags(&evO,    cudaEventDisableTiming);
    cudaEventCreateWithFlags(&evComp, cudaEventDisableTiming);
    cudaEventCreateWithFlags(&evKpe,  cudaEventDisableTiming);

    cudaEventRecord(evFork, 0);
    cudaStreamWaitEvent(s2, evFork, 0);

    // side stream: activation split + independent weight conversions
    conv_a<<<(S_LEN * HID_D / 4 + 255) / 256, 256, 0, s2>>>(hs, ah, al, S_LEN * HID_D / 4);
    cudaEventRecord(evA, s2);
    conv_w2<<<dim3(QLORA / 64, QD / 32), TW, 0, s2>>>(w_q_b, wq, QLORA, QD);
    cudaEventRecord(evQ, s2);
    conv_w2<<<dim3(KVLORA / 64, KVD / 32), TW, 0, s2>>>(w_kv_b, wkv, KVLORA, KVD);
    cudaEventRecord(evKV, s2);
    conv_w2<<<dim3(CTX_D / 64, HID_D / 32), TW, 0, s2>>>(w_o, wo, CTX_D, HID_D);
    cudaEventRecord(evO, s2);

    // main stream
    // 1) comp = hs @ w_kv_a  (3-pass; N pad 2176)
    conv_w_split2<<<dim3(HID_D / 64, 2176 / 32), TW>>>(w_kv_a, wah, wal, HID_D, COMP_D);
    cudaStreamWaitEvent(0, evA, 0);
    mma_gemm3<<<dim3(17, 8), T256, 131072>>>(ah, al, wah, wal, comp, COMP_D, HID_D);
    cudaEventRecord(evComp, 0);

    // side stream: k_pe RoPE + per-head broadcast (parallel with q GEMM)
    cudaStreamWaitEvent(s2, evComp, 0);
    rope_k_kernel<<<(S_LEN * 32) / 256, 256, 0, s2>>>(comp, kpe);
    fill_kpe<<<(NH * S_LEN * 32) / 256, 256, 0, s2>>>(kpe, kh);
    cudaEventRecord(evKpe, s2);

    // 2) q = rmsnorm(q_c) @ w_q_b (1-pass), fused RoPE + hi/lo split
    rmsnorm_h<<<S_LEN, 256>>>(comp, q_gamma, ah, al, QLORA, COMP_D);
    cudaStreamWaitEvent(0, evQ, 0);
    mma_gemm_q<<<dim3(QD / 128, 8), T256, 65536>>>(ah, wq, qh, ql);

    // 3) kv = rmsnorm(kv_c) @ w_kv_b (2-pass), fused -> Kh (nope) + kv fp32 (v)
    rmsnorm_h<<<S_LEN, 256>>>(comp + QLORA, kv_gamma, ah, al, KVLORA, COMP_D);
    cudaStreamWaitEvent(0, evKV, 0);
    mma_gemm_kv<<<dim3(KVD / 128, 8), T256, 98304>>>(ah, al, wkv, kh, kv);
    build_vt<<<dim3(32, 4, NH), TW>>>(kv, vth);

    // 4) fused flash attention -> ctx fp16 in ah
    cudaStreamWaitEvent(0, evKpe, 0);
    flash_mma<<<dim3(NH, 8), T256, 131072>>>(qh, ql, kh, vth, ah);

    // 5) out = ctx @ w_o  (1-pass)
    cudaStreamWaitEvent(0, evO, 0);
    mma_gemm1<<<dim3(HID_D / 128, 8), T256, 65536>>>(ah, wo, out, HID_D, CTX_D);
}

// round 14
// speedup vs baseline: 1.3226x; 1.0074x over previous
#include <cuda_runtime.h>
#include <cuda_fp16.h>
#include <math.h>
#include <stdint.h>

// ---------------- problem constants ----------------
#define S_LEN 1024
#define HID_D 7168
#define NH 128
#define DN 128
#define DR 64
#define DV 128
#define QLORA 1536
#define KVLORA 512
#define COMP_D (QLORA + KVLORA + DR)      // 2112
#define QD (NH * (DN + DR))               // 24576
#define KVD (NH * (DN + DV))              // 32768
#define CTX_D (NH * DV)                   // 16384
#define DQK 192

// ---------------- scratch (device globals) ----------------
__device__ float g_comp[S_LEN * COMP_D];
__device__ __half g_ah[(size_t)S_LEN * 16384];                   // activations hi (also ctx)
__device__ __half g_al[(size_t)S_LEN * 16384];                   // activations lo
__device__ __half g_bh[S_LEN * KVLORA];                          // kv-chain activations hi
__device__ __half g_bl[S_LEN * KVLORA];                          // kv-chain activations lo
__device__ __half g_wa_h[15597568];                              // w_kv_a hi (2176*7168)
__device__ __half g_wa_l[15597568];                              // w_kv_a lo
__device__ __half g_wq[(size_t)QD * QLORA];                      // w_q_b^T
__device__ __half g_wkv[(size_t)KVD * KVLORA];                   // w_kv_b^T
__device__ __half g_wo[(size_t)HID_D * CTX_D];                   // w_o^T
__device__ float g_kv[(size_t)S_LEN * KVD];                      // v half only used
__device__ float g_kpe[S_LEN * DR];
__device__ __half g_qh[(size_t)NH * S_LEN * DQK];
__device__ __half g_ql[(size_t)NH * S_LEN * DQK];
__device__ __half g_kh[(size_t)NH * S_LEN * DQK];
__device__ __half g_vth[(size_t)NH * DV * S_LEN];

// ---------------- PTX helpers ----------------
__device__ __forceinline__ uint32_t smem_u32(const void* p) {
    uint32_t a;
    asm("{ .reg .u64 t; cvta.to.shared.u64 t, %1; cvt.u32.u64 %0, t; }" : "=r"(a) : "l"(p));
    return a;
}
#define CP16(dst, src) \
    asm volatile("cp.async.cg.shared.global [%0], [%1], 16;" :: "r"(dst), "l"(src) : "memory")
#define CP_COMMIT() asm volatile("cp.async.commit_group;" ::: "memory")
#define CP_WAIT1() asm volatile("cp.async.wait_group 1;" ::: "memory")
#define CP_WAIT0() asm volatile("cp.async.wait_group 0;" ::: "memory")

#define LDSM4(r, a) \
    asm volatile("ldmatrix.sync.aligned.m8n8.x4.shared.b16 {%0,%1,%2,%3}, [%4];" \
        : "=r"((r)[0]), "=r"((r)[1]), "=r"((r)[2]), "=r"((r)[3]) : "r"(a))

#define MMA_F16(d, a, b0, b1) \
    asm volatile("mma.sync.aligned.m16n8k16.row.col.f32.f16.f16.f32 " \
        "{%0,%1,%2,%3}, {%4,%5,%6,%7}, {%8,%9}, {%0,%1,%2,%3};" \
        : "+f"((d)[0]), "+f"((d)[1]), "+f"((d)[2]), "+f"((d)[3]) \
        : "r"((a)[0]), "r"((a)[1]), "r"((a)[2]), "r"((a)[3]), "r"(b0), "r"(b1))

#define SWZ(o) ((o) ^ (((o) >> 3) & 0x70))

__device__ __forceinline__ void split_h(float v, __half& h, __half& l) {
    h = __float2half_rn(v);
    l = __float2half_rn(v - __half2float(h));
}

// ---------------- shared GEMM body (2-stage pipeline, R8-proven) ----------------
// NPASS=1: ah*bh        NPASS=2: ah*bh + al*bh        NPASS=3: + ah*bl
template <int NPASS>
__device__ __forceinline__ void gemm_body(
    const __half* __restrict__ Ah, const __half* __restrict__ Al,
    const __half* __restrict__ Bh, const __half* __restrict__ Bl,
    int K, int nch, int m0, int n0, uint32_t sb, int tid, float acc[2][8][4])
{
    constexpr int CA = (NPASS >= 2) ? 2 : 1;
    constexpr int CB = (NPASS == 3) ? 2 : 1;
    constexpr int NT = CA + CB;
    constexpr int STAGE = NT * 16384;
    const int lane = tid & 31;
    const int wid = tid >> 5;
    const int wm = (wid & 3) * 32;
    const int wn = (wid >> 2) * 64;

    auto load_stage = [&](int c, int s) {
        const int kc = c << 6;
#pragma unroll
        for (int it = 0; it < NT * 4; it++) {
            const int t = tid + it * 256;
            const int tensor = t >> 10;
            const int rem = t & 1023;
            const int row = rem >> 3;
            const int ch = rem & 7;
            const __half* src;
            int grow;
            if (tensor < CA) {
                src = (CA == 2 && tensor == 1) ? Al : Ah;
                grow = m0 + row;
            } else {
                src = (CB == 2 && tensor == CA + 1) ? Bl : Bh;
                grow = n0 + row;
            }
            const __half* sp = src + (size_t)grow * K + kc + ch * 8;
            const uint32_t dst = sb + s * STAGE + tensor * 16384 + SWZ(row * 128 + ch * 16);
            CP16(dst, sp);
        }
        CP_COMMIT();
    };

    load_stage(0, 0);

    for (int c = 0; c < nch; c++) {
        const int buf = c & 1;
        if (c + 1 < nch) { load_stage(c + 1, buf ^ 1); CP_WAIT1(); }
        else             { CP_WAIT0(); }
        __syncthreads();

        const uint32_t st = sb + buf * STAGE;
        const uint32_t sA_h = st;
        const uint32_t sA_l = st + 16384;
        const uint32_t sB_h = st + CA * 16384;
        const uint32_t sB_l = sB_h + 16384;
        const int rl = lane & 15;
        const int kb = lane >> 4;

#pragma unroll
        for (int k16 = 0; k16 < 4; k16++) {
            const int kbyte = k16 * 32 + kb * 16;
            uint32_t afh[2][4], afl[2][4], bfh[4][4], bfl[4][4];
#pragma unroll
            for (int mt = 0; mt < 2; mt++) {
                const uint32_t off = SWZ((wm + mt * 16 + rl) * 128 + kbyte);
                LDSM4(afh[mt], sA_h + off);
                if (CA == 2) LDSM4(afl[mt], sA_l + off);
            }
#pragma unroll
            for (int q = 0; q < 4; q++) {
                const uint32_t off = SWZ((wn + q * 16 + rl) * 128 + kbyte);
                LDSM4(bfh[q], sB_h + off);
                if (CB == 2) LDSM4(bfl[q], sB_l + off);
            }
#pragma unroll
            for (int mt = 0; mt < 2; mt++)
#pragma unroll
                for (int nt = 0; nt < 8; nt++) {
                    const int q = nt >> 1, s = nt & 1;
                    MMA_F16(acc[mt][nt], afh[mt], bfh[q][s], bfh[q][s + 2]);
                    if (CA == 2) MMA_F16(acc[mt][nt], afl[mt], bfh[q][s], bfh[q][s + 2]);
                    if (CB == 2) MMA_F16(acc[mt][nt], afh[mt], bfl[q][s], bfl[q][s + 2]);
                }
        }
        __syncthreads();
    }
}

#define GEMM_PROLOGUE() \
    extern __shared__ __align__(128) char smem[]; \
    const uint32_t sb = smem_u32(smem); \
    const int tid = threadIdx.x; \
    const int lane = tid & 31; \
    const int wid = tid >> 5; \
    const int m0 = blockIdx.y * 128, n0 = blockIdx.x * 128; \
    const int wm = (wid & 3) * 32, wn = (wid >> 2) * 64; \
    float acc[2][8][4]; \
    _Pragma("unroll") for (int mt = 0; mt < 2; mt++) \
    _Pragma("unroll") for (int nt = 0; nt < 8; nt++) \
    _Pragma("unroll") for (int e = 0; e < 4; e++) acc[mt][nt][e] = 0.0f;

// ---------------- comp GEMM: 3-pass, fp32 out (128KB smem -> 1 CTA/SM) ----------
__global__ __launch_bounds__(256, 1) void mma_gemm3(
    const __half* __restrict__ Ah, const __half* __restrict__ Al,
    const __half* __restrict__ Bh, const __half* __restrict__ Bl,
    float* __restrict__ C, int N, int K)
{
    GEMM_PROLOGUE();
    gemm_body<3>(Ah, Al, Bh, Bl, K, K >> 6, m0, n0, sb, tid, acc);
#pragma unroll
    for (int mt = 0; mt < 2; mt++) {
        const int row = m0 + wm + mt * 16 + (lane >> 2);
#pragma unroll
        for (int nt = 0; nt < 8; nt++) {
            const int col = n0 + wn + nt * 8 + (lane & 3) * 2;
            if (col < N) {
                *reinterpret_cast<float2*>(C + (size_t)row * N + col) =
                    make_float2(acc[mt][nt][0], acc[mt][nt][1]);
                *reinterpret_cast<float2*>(C + (size_t)(row + 8) * N + col) =
                    make_float2(acc[mt][nt][2], acc[mt][nt][3]);
            }
        }
    }
}

// ---------------- w_o GEMM: 1-pass, fp32 out (64KB, 2 CTA/SM) ----------
__global__ __launch_bounds__(256, 2) void mma_gemm1(
    const __half* __restrict__ Ah, const __half* __restrict__ Bh,
    float* __restrict__ C, int N, int K)
{
    GEMM_PROLOGUE();
    gemm_body<1>(Ah, nullptr, Bh, nullptr, K, K >> 6, m0, n0, sb, tid, acc);
#pragma unroll
    for (int mt = 0; mt < 2; mt++) {
        const int row = m0 + wm + mt * 16 + (lane >> 2);
#pragma unroll
        for (int nt = 0; nt < 8; nt++) {
            const int col = n0 + wn + nt * 8 + (lane & 3) * 2;
            *reinterpret_cast<float2*>(C + (size_t)row * N + col) =
                make_float2(acc[mt][nt][0], acc[mt][nt][1]);
            *reinterpret_cast<float2*>(C + (size_t)(row + 8) * N + col) =
                make_float2(acc[mt][nt][2], acc[mt][nt][3]);
        }
    }
}

// ---------------- RoPE angle ----------------
__device__ __forceinline__ void rope_cs(int s, int d, float& c, float& sn)
{
    const float inv = exp2f(-(float)d * (13.287712379549449f / 32.0f));
    sincosf((float)s * inv, &sn, &c);
}

// ---------------- q GEMM: 1-pass, fused RoPE + split (64KB, 2 CTA/SM) -----------
__global__ __launch_bounds__(256, 2) void mma_gemm_q(
    const __half* __restrict__ Ah, const __half* __restrict__ Bh,
    __half* __restrict__ Qh, __half* __restrict__ Ql)
{
    GEMM_PROLOGUE();
    gemm_body<1>(Ah, nullptr, Bh, nullptr, QLORA, QLORA >> 6, m0, n0, sb, tid, acc);

    const int base64 = n0 + wn;
    if ((base64 / 64) % 3 != 2) {
#pragma unroll
        for (int mt = 0; mt < 2; mt++)
#pragma unroll
            for (int half_i = 0; half_i < 2; half_i++) {
                const int row = m0 + wm + mt * 16 + (lane >> 2) + half_i * 8;
#pragma unroll
                for (int nt = 0; nt < 8; nt++) {
                    const int c = base64 + nt * 8 + (lane & 3) * 2;
                    const int h = c / 192;
                    const int cr = c - h * 192;
                    const size_t o = ((size_t)h * S_LEN + row) * DQK + cr;
                    __half h0, l0, h1, l1;
                    split_h(acc[mt][nt][half_i * 2], h0, l0);
                    split_h(acc[mt][nt][half_i * 2 + 1], h1, l1);
                    *reinterpret_cast<__half2*>(Qh + o) = __half2(h0, h1);
                    *reinterpret_cast<__half2*>(Ql + o) = __half2(l0, l1);
                }
            }
    } else {
        const int h = base64 / 192;
#pragma unroll
        for (int mt = 0; mt < 2; mt++)
#pragma unroll
            for (int half_i = 0; half_i < 2; half_i++) {
                const int row = m0 + wm + mt * 16 + (lane >> 2) + half_i * 8;
                const size_t rb = ((size_t)h * S_LEN + row) * DQK + 128;
#pragma unroll
                for (int ntL = 0; ntL < 4; ntL++) {
                    const int d0 = ntL * 8 + (lane & 3) * 2;
                    float o0[2], o1[2];
#pragma unroll
                    for (int e = 0; e < 2; e++) {
                        float cc, ss;
                        rope_cs(row, d0 + e, cc, ss);
                        const float v1 = acc[mt][ntL][half_i * 2 + e];
                        const float v2 = acc[mt][ntL + 4][half_i * 2 + e];
                        o0[e] = v1 * cc - v2 * ss;
                        o1[e] = v2 * cc + v1 * ss;
                    }
                    __half h0, l0, h1, l1;
                    split_h(o0[0], h0, l0); split_h(o0[1], h1, l1);
                    *reinterpret_cast<__half2*>(Qh + rb + d0) = __half2(h0, h1);
                    *reinterpret_cast<__half2*>(Ql + rb + d0) = __half2(l0, l1);
                    split_h(o1[0], h0, l0); split_h(o1[1], h1, l1);
                    *reinterpret_cast<__half2*>(Qh + rb + d0 + 32) = __half2(h0, h1);
                    *reinterpret_cast<__half2*>(Ql + rb + d0 + 32) = __half2(l0, l1);
                }
            }
    }
}

// ---------------- kv GEMM: 2-pass, k_nope -> Kh only; v -> fp32 (96KB, 2 CTA/SM)
__global__ __launch_bounds__(256, 2) void mma_gemm_kv(
    const __half* __restrict__ Ah, const __half* __restrict__ Al,
    const __half* __restrict__ Bh,
    __half* __restrict__ Kh, float* __restrict__ kv)
{
    GEMM_PROLOGUE();
    gemm_body<2>(Ah, Al, Bh, nullptr, KVLORA, KVLORA >> 6, m0, n0, sb, tid, acc);

    const int base64 = n0 + wn;
    const int blk4 = (base64 / 64) & 3;
    if (blk4 < 2) {
        const int h = base64 / 256;
#pragma unroll
        for (int mt = 0; mt < 2; mt++)
#pragma unroll
            for (int half_i = 0; half_i < 2; half_i++) {
                const int row = m0 + wm + mt * 16 + (lane >> 2) + half_i * 8;
#pragma unroll
                for (int nt = 0; nt < 8; nt++) {
                    const int c = base64 + nt * 8 + (lane & 3) * 2;
                    const int cr = c - h * 256;
                    const size_t o = ((size_t)h * S_LEN + row) * DQK + cr;
                    *reinterpret_cast<__half2*>(Kh + o) =
                        __half2(__float2half_rn(acc[mt][nt][half_i * 2]),
                                __float2half_rn(acc[mt][nt][half_i * 2 + 1]));
                }
            }
    } else {
#pragma unroll
        for (int mt = 0; mt < 2; mt++) {
            const int row = m0 + wm + mt * 16 + (lane >> 2);
#pragma unroll
            for (int nt = 0; nt < 8; nt++) {
                const int c = base64 + nt * 8 + (lane & 3) * 2;
                *reinterpret_cast<float2*>(kv + (size_t)row * KVD + c) =
                    make_float2(acc[mt][nt][0], acc[mt][nt][1]);
                *reinterpret_cast<float2*>(kv + (size_t)(row + 8) * KVD + c) =
                    make_float2(acc[mt][nt][2], acc[mt][nt][3]);
            }
        }
    }
}

// ---------------- fused flash attention per (head, i-tile) ----------------
// S phase: 2-pass (Qh+Ql) x Kh. smem: [0,96K) stages (P reuses [0,32K)), [96K,128K) V
__global__ __launch_bounds__(256, 1) void flash_mma(
    const __half* __restrict__ Qh, const __half* __restrict__ Ql,
    const __half* __restrict__ Kh,
    const __half* __restrict__ Vth, __half* __restrict__ ch)
{
    extern __shared__ __align__(128) char smem[];
    __shared__ float redM[2][128];
    __shared__ float redS[2][128];
    const uint32_t sb = smem_u32(smem);
    const int tid = threadIdx.x;
    const int lane = tid & 31;
    const int wid = tid >> 5;
    const int h = blockIdx.x;
    const int it = 7 - blockIdx.y;          // heavy tiles first
    const int m0 = it * 128;
    const int wm = (wid & 3) * 32, wn = (wid >> 2) * 64;
    const int ng = wid >> 2;
    const size_t hoff = (size_t)h * S_LEN * DQK;
    const size_t voff = (size_t)h * DV * S_LEN;
    const float scale = 0.07216878364870323f;   // 1/sqrt(192)

    float Oacc[2][8][4];
    float mrow[2][2], lrow[2][2];
#pragma unroll
    for (int mt = 0; mt < 2; mt++)
#pragma unroll
        for (int nt = 0; nt < 8; nt++)
#pragma unroll
            for (int e = 0; e < 4; e++) Oacc[mt][nt][e] = 0.0f;
#pragma unroll
    for (int mt = 0; mt < 2; mt++)
#pragma unroll
        for (int hf = 0; hf < 2; hf++) { mrow[mt][hf] = -3.4e38f; lrow[mt][hf] = 0.0f; }

    for (int jt = 0; jt <= it; jt++) {
        // ---- S = (Qh+Ql) @ Kh^T (2-pass) ----
        float Sacc[2][8][4];
#pragma unroll
        for (int mt = 0; mt < 2; mt++)
#pragma unroll
            for (int nt = 0; nt < 8; nt++)
#pragma unroll
                for (int e = 0; e < 4; e++) Sacc[mt][nt][e] = 0.0f;

        gemm_body<2>(Qh + hoff, Ql + hoff, Kh + hoff, nullptr,
                     DQK, 3, m0, jt * 128, sb, tid, Sacc);

        // ---- prefetch V tile (2 chunks of [128 d][64 j]) at [96K,128K) ----
#pragma unroll
        for (int itv = 0; itv < 8; itv++) {
            const int t = tid + itv * 256;
            const int c = t >> 10;
            const int rem = t & 1023;
            const int d = rem >> 3;
            const int seg = rem & 7;
            const __half* sp = Vth + voff + (size_t)d * S_LEN + jt * 128 + c * 64 + seg * 8;
            CP16(sb + 98304 + c * 16384 + SWZ(d * 128 + seg * 16), sp);
        }
        CP_COMMIT();

        // ---- pass A: scale + mask + row max ----
#pragma unroll
        for (int mt = 0; mt < 2; mt++)
#pragma unroll
            for (int hf = 0; hf < 2; hf++) {
                const int rloc = wm + mt * 16 + (lane >> 2) + hf * 8;
                float mx = -3.4e38f;
#pragma unroll
                for (int nt = 0; nt < 8; nt++)
#pragma unroll
                    for (int e = 0; e < 2; e++) {
                        float s = Sacc[mt][nt][hf * 2 + e] * scale;
                        if (jt == it) {
                            const int cg = jt * 128 + wn + nt * 8 + (lane & 3) * 2 + e;
                            if (cg > m0 + rloc) s = -3.4e38f;
                        }
                        Sacc[mt][nt][hf * 2 + e] = s;
                        mx = fmaxf(mx, s);
                    }
                mx = fmaxf(mx, __shfl_xor_sync(0xFFFFFFFFu, mx, 1));
                mx = fmaxf(mx, __shfl_xor_sync(0xFFFFFFFFu, mx, 2));
                if ((lane & 3) == 0) redM[ng][rloc] = mx;
            }
        __syncthreads();

        // ---- pass B: exp, write P (single fp16) to smem, row sums, O rescale ----
#pragma unroll
        for (int mt = 0; mt < 2; mt++)
#pragma unroll
            for (int hf = 0; hf < 2; hf++) {
                const int rloc = wm + mt * 16 + (lane >> 2) + hf * 8;
                const float mnew = fmaxf(mrow[mt][hf],
                                         fmaxf(redM[0][rloc], redM[1][rloc]));
                float ssum = 0.0f;
#pragma unroll
                for (int nt = 0; nt < 8; nt++) {
                    const float p0 = __expf(Sacc[mt][nt][hf * 2] - mnew);
                    const float p1 = __expf(Sacc[mt][nt][hf * 2 + 1] - mnew);
                    ssum += p0 + p1;
                    const uint32_t off = SWZ(rloc * 128 + (nt * 8 + (lane & 3) * 2) * 2);
                    *reinterpret_cast<__half2*>(smem + ng * 16384 + off) =
                        __half2(__float2half_rn(p0), __float2half_rn(p1));
                }
                ssum += __shfl_xor_sync(0xFFFFFFFFu, ssum, 1);
                ssum += __shfl_xor_sync(0xFFFFFFFFu, ssum, 2);
                if ((lane & 3) == 0) redS[ng][rloc] = ssum;
                const float sc = __expf(mrow[mt][hf] - mnew);
#pragma unroll
                for (int nt = 0; nt < 8; nt++) {
                    Oacc[mt][nt][hf * 2] *= sc;
                    Oacc[mt][nt][hf * 2 + 1] *= sc;
                }
                lrow[mt][hf] *= sc;
                mrow[mt][hf] = mnew;
            }
        __syncthreads();

        // ---- pass C: finish l ----
#pragma unroll
        for (int mt = 0; mt < 2; mt++)
#pragma unroll
            for (int hf = 0; hf < 2; hf++) {
                const int rloc = wm + mt * 16 + (lane >> 2) + hf * 8;
                lrow[mt][hf] += redS[0][rloc] + redS[1][rloc];
            }

        // ---- P @ V (single pass), accumulate into Oacc ----
        CP_WAIT0();
        __syncthreads();
        const int rl = lane & 15;
        const int kb = lane >> 4;
#pragma unroll
        for (int c = 0; c < 2; c++) {
#pragma unroll
            for (int k16 = 0; k16 < 4; k16++) {
                const int kbyte = k16 * 32 + kb * 16;
                uint32_t pfh[2][4], vf[4][4];
#pragma unroll
                for (int mt = 0; mt < 2; mt++) {
                    const uint32_t off = SWZ((wm + mt * 16 + rl) * 128 + kbyte);
                    LDSM4(pfh[mt], sb + c * 16384 + off);
                }
#pragma unroll
                for (int q = 0; q < 4; q++) {
                    const uint32_t off = SWZ((wn + q * 16 + rl) * 128 + kbyte);
                    LDSM4(vf[q], sb + 98304 + c * 16384 + off);
                }
#pragma unroll
                for (int mt = 0; mt < 2; mt++)
#pragma unroll
                    for (int nt = 0; nt < 8; nt++) {
                        const int q = nt >> 1, s = nt & 1;
                        MMA_F16(Oacc[mt][nt], pfh[mt], vf[q][s], vf[q][s + 2]);
                    }
            }
        }
        __syncthreads();   // protect P/V smem before next jt's loads
    }

    // ---- epilogue: normalize and write ctx fp16 ----
#pragma unroll
    for (int mt = 0; mt < 2; mt++)
#pragma unroll
        for (int hf = 0; hf < 2; hf++) {
            const int row = m0 + wm + mt * 16 + (lane >> 2) + hf * 8;
            const float inv = 1.0f / lrow[mt][hf];
#pragma unroll
            for (int nt = 0; nt < 8; nt++) {
                const int col = wn + nt * 8 + (lane & 3) * 2;
                const size_t o = (size_t)row * CTX_D + (size_t)h * DV + col;
                *reinterpret_cast<__half2*>(ch + o) =
                    __half2(__float2half_rn(Oacc[mt][nt][hf * 2] * inv),
                            __float2half_rn(Oacc[mt][nt][hf * 2 + 1] * inv));
            }
        }
}

// ---------------- weight converts ----------------
__global__ void conv_w2(const float* __restrict__ W, __half* __restrict__ Th, int K, int N)
{
    __shared__ float t[64][33];
    const int k0 = blockIdx.x * 64, n0 = blockIdx.y * 32;
    const int tx = threadIdx.x, ty = threadIdx.y;
#pragma unroll
    for (int i = 0; i < 8; i++)
        t[ty + i * 8][tx] = W[(size_t)(k0 + ty + i * 8) * N + n0 + tx];
    __syncthreads();
#pragma unroll
    for (int i = 0; i < 4; i++) {
        const int n = n0 + ty + i * 8;
        const int cidx = ty + i * 8;
        __half2 v = __half2(__float2half_rn(t[tx * 2][cidx]),
                            __float2half_rn(t[tx * 2 + 1][cidx]));
        *reinterpret_cast<__half2*>(Th + (size_t)n * K + k0 + tx * 2) = v;
    }
}

// vectorized hi/lo split convert: 64k x 32n tile, __half2 stores, n guarded
__global__ void conv_w_split2(const float* __restrict__ W, __half* __restrict__ Th,
                              __half* __restrict__ Tl, int K, int N)
{
    __shared__ float t[64][33];
    const int k0 = blockIdx.x * 64, n0 = blockIdx.y * 32;
    const int tx = threadIdx.x, ty = threadIdx.y;
#pragma unroll
    for (int i = 0; i < 8; i++) {
        const int n = n0 + tx;
        t[ty + i * 8][tx] = (n < N) ? W[(size_t)(k0 + ty + i * 8) * N + n] : 0.0f;
    }
    __syncthreads();
#pragma unroll
    for (int i = 0; i < 4; i++) {
        const int n = n0 + ty + i * 8;
        const int cidx = ty + i * 8;
        __half h0, l0, h1, l1;
        split_h(t[tx * 2][cidx], h0, l0);
        split_h(t[tx * 2 + 1][cidx], h1, l1);
        const size_t o = (size_t)n * K + k0 + tx * 2;
        *reinterpret_cast<__half2*>(Th + o) = __half2(h0, h1);
        *reinterpret_cast<__half2*>(Tl + o) = __half2(l0, l1);
    }
}

// ---------------- activation convert ----------------
__global__ void conv_a(const float* __restrict__ A, __half* __restrict__ H,
                       __half* __restrict__ L, int n4)
{
    const int i = blockIdx.x * blockDim.x + threadIdx.x;
    if (i >= n4) return;
    const float4 v = reinterpret_cast<const float4*>(A)[i];
    __half h0, l0, h1, l1, h2, l2, h3, l3;
    split_h(v.x, h0, l0); split_h(v.y, h1, l1);
    split_h(v.z, h2, l2); split_h(v.w, h3, l3);
    __half2* Hp = reinterpret_cast<__half2*>(H) + i * 2;
    __half2* Lp = reinterpret_cast<__half2*>(L) + i * 2;
    Hp[0] = __half2(h0, h1); Hp[1] = __half2(h2, h3);
    Lp[0] = __half2(l0, l1); Lp[1] = __half2(l2, l3);
}

// ---------------- rmsnorm fused to fp16 hi/lo ----------------
__global__ void rmsnorm_h(const float* __restrict__ x, const float* __restrict__ gamma,
                          __half* __restrict__ yh, __half* __restrict__ yl,
                          int D, int xstride)
{
    const int row = blockIdx.x;
    const float* xr = x + (size_t)row * xstride;
    float s = 0.0f;
    for (int i = threadIdx.x; i < D; i += 256) { const float v = xr[i]; s += v * v; }
    __shared__ float red[256];
    red[threadIdx.x] = s;
    __syncthreads();
    for (int o = 128; o > 0; o >>= 1) {
        if (threadIdx.x < o) red[threadIdx.x] += red[threadIdx.x + o];
        __syncthreads();
    }
    const float inv = rsqrtf(red[0] / (float)D + 1e-6f);
    for (int i = threadIdx.x; i < D; i += 256) {
        __half h, l;
        split_h(xr[i] * inv * gamma[i], h, l);
        yh[(size_t)row * D + i] = h;
        yl[(size_t)row * D + i] = l;
    }
}

// ---------------- k_pe RoPE ----------------
__global__ void rope_k_kernel(const float* __restrict__ comp, float* __restrict__ kpe)
{
    const int t = blockIdx.x * blockDim.x + threadIdx.x;
    if (t >= S_LEN * 32) return;
    const int d = t & 31;
    const int s = t >> 5;
    float c, sn;
    rope_cs(s, d, c, sn);
    const float* src = comp + (size_t)s * COMP_D + QLORA + KVLORA;
    const float x1 = src[d], x2 = src[d + 32];
    kpe[s * DR + d]      = x1 * c - x2 * sn;
    kpe[s * DR + d + 32] = x2 * c + x1 * sn;
}

// ---------------- broadcast roped k_pe into per-head K cols 128..191 (hi only) --
__global__ void fill_kpe(const float* __restrict__ kpe, __half* __restrict__ Kh)
{
    const int t = blockIdx.x * blockDim.x + threadIdx.x;
    if (t >= NH * S_LEN * 32) return;
    const int d2 = t & 31;
    const int j  = (t >> 5) & (S_LEN - 1);
    const int h  = t >> 15;
    const int d = d2 * 2;
    const size_t o = ((size_t)h * S_LEN + j) * DQK + 128 + d;
    *reinterpret_cast<__half2*>(Kh + o) =
        __half2(__float2half_rn(kpe[j * DR + d]),
                __float2half_rn(kpe[j * DR + d + 1]));
}

// ---------------- build V^T per head (transpose, single fp16) ----------------
__global__ void build_vt(const float* __restrict__ kv, __half* __restrict__ Vth)
{
    __shared__ float t[32][33];
    const int j0 = blockIdx.x * 32, d0 = blockIdx.y * 32, h = blockIdx.z;
    const int tx = threadIdx.x, ty = threadIdx.y;
#pragma unroll
    for (int i = 0; i < 4; i++)
        t[ty + i * 8][tx] = kv[(size_t)(j0 + ty + i * 8) * KVD + h * 256 + 128 + d0 + tx];
    __syncthreads();
    const size_t base = (size_t)h * DV * S_LEN;
#pragma unroll
    for (int i = 0; i < 4; i++)
        Vth[base + (size_t)(d0 + ty + i * 8) * S_LEN + j0 + tx] =
            __float2half_rn(t[tx][ty + i * 8]);
}

// ---------------- launch ----------------
extern "C" void kernel_launch(void* const* d_in, const int* in_sizes, int n_in,
                              void* d_out, int out_size)
{
    const float* hs       = (const float*)d_in[0];
    const float* w_kv_a   = (const float*)d_in[1];
    const float* q_gamma  = (const float*)d_in[2];
    const float* kv_gamma = (const float*)d_in[3];
    const float* w_q_b    = (const float*)d_in[4];
    const float* w_kv_b   = (const float*)d_in[5];
    const float* w_o      = (const float*)d_in[6];
    float* out = (float*)d_out;

    float *comp, *kv, *kpe;
    __half *ah, *al, *bh, *bl, *wah, *wal, *wq, *wkv, *wo, *qh, *ql, *kh, *vth;
    cudaGetSymbolAddress((void**)&comp, g_comp);
    cudaGetSymbolAddress((void**)&ah,   g_ah);
    cudaGetSymbolAddress((void**)&al,   g_al);
    cudaGetSymbolAddress((void**)&bh,   g_bh);
    cudaGetSymbolAddress((void**)&bl,   g_bl);
    cudaGetSymbolAddress((void**)&wah,  g_wa_h);
    cudaGetSymbolAddress((void**)&wal,  g_wa_l);
    cudaGetSymbolAddress((void**)&wq,   g_wq);
    cudaGetSymbolAddress((void**)&wkv,  g_wkv);
    cudaGetSymbolAddress((void**)&wo,   g_wo);
    cudaGetSymbolAddress((void**)&kv,   g_kv);
    cudaGetSymbolAddress((void**)&kpe,  g_kpe);
    cudaGetSymbolAddress((void**)&qh,   g_qh);
    cudaGetSymbolAddress((void**)&ql,   g_ql);
    cudaGetSymbolAddress((void**)&kh,   g_kh);
    cudaGetSymbolAddress((void**)&vth,  g_vth);

    cudaFuncSetAttribute(mma_gemm3, cudaFuncAttributeMaxDynamicSharedMemorySize, 131072);
    cudaFuncSetAttribute(mma_gemm_q, cudaFuncAttributeMaxDynamicSharedMemorySize, 65536);
    cudaFuncSetAttribute(mma_gemm_kv, cudaFuncAttributeMaxDynamicSharedMemorySize, 98304);
    cudaFuncSetAttribute(mma_gemm1, cudaFuncAttributeMaxDynamicSharedMemorySize, 65536);
    cudaFuncSetAttribute(flash_mma, cudaFuncAttributeMaxDynamicSharedMemorySize, 131072);
    const dim3 T256(256);
    const dim3 TW(32, 8);

    // side stream + events (created per call; never destroyed)
    cudaStream_t s2;
    cudaStreamCreateWithFlags(&s2, cudaStreamNonBlocking);
    cudaEvent_t evFork, evA, evQ, evO, evComp, evKVdone;
    cudaEventCreateWithFlags(&evFork,   cudaEventDisableTiming);
    cudaEventCreateWithFlags(&evA,      cudaEventDisableTiming);
    cudaEventCreateWithFlags(&evQ,      cudaEventDisableTiming);
    cudaEventCreateWithFlags(&evO,      cudaEventDisableTiming);
    cudaEventCreateWithFlags(&evComp,   cudaEventDisableTiming);
    cudaEventCreateWithFlags(&evKVdone, cudaEventDisableTiming);

    cudaEventRecord(evFork, 0);
    cudaStreamWaitEvent(s2, evFork, 0);

    // side stream (phase 1): activation split + q/kv weight conversions
    conv_a<<<(S_LEN * HID_D / 4 + 255) / 256, 256, 0, s2>>>(hs, ah, al, S_LEN * HID_D / 4);
    cudaEventRecord(evA, s2);
    conv_w2<<<dim3(QLORA / 64, QD / 32), TW, 0, s2>>>(w_q_b, wq, QLORA, QD);
    cudaEventRecord(evQ, s2);
    conv_w2<<<dim3(KVLORA / 64, KVD / 32), TW, 0, s2>>>(w_kv_b, wkv, KVLORA, KVD);

    // main: comp = hs @ w_kv_a  (3-pass; N pad 2176)
    conv_w_split2<<<dim3(HID_D / 64, 2176 / 32), TW>>>(w_kv_a, wah, wal, HID_D, COMP_D);
    cudaStreamWaitEvent(0, evA, 0);
    mma_gemm3<<<dim3(17, 8), T256, 131072>>>(ah, al, wah, wal, comp, COMP_D, HID_D);
    cudaEventRecord(evComp, 0);

    // side stream (phase 2): entire kv chain (ordered after conv_w2(wkv) on s2)
    cudaStreamWaitEvent(s2, evComp, 0);
    rope_k_kernel<<<(S_LEN * 32) / 256, 256, 0, s2>>>(comp, kpe);
    fill_kpe<<<(NH * S_LEN * 32) / 256, 256, 0, s2>>>(kpe, kh);
    rmsnorm_h<<<S_LEN, 256, 0, s2>>>(comp + QLORA, kv_gamma, bh, bl, KVLORA, COMP_D);
    mma_gemm_kv<<<dim3(KVD / 128, 8), T256, 98304, s2>>>(bh, bl, wkv, kh, kv);
    build_vt<<<dim3(32, 4, NH), TW, 0, s2>>>(kv, vth);
    cudaEventRecord(evKVdone, s2);

    // side stream (phase 3): w_o conversion, overlaps flash
    conv_w2<<<dim3(CTX_D / 64, HID_D / 32), TW, 0, s2>>>(w_o, wo, CTX_D, HID_D);
    cudaEventRecord(evO, s2);

    // main: q chain (concurrent with kv chain)
    rmsnorm_h<<<S_LEN, 256>>>(comp, q_gamma, ah, al, QLORA, COMP_D);
    cudaStreamWaitEvent(0, evQ, 0);
    mma_gemm_q<<<dim3(QD / 128, 8), T256, 65536>>>(ah, wq, qh, ql);

    // main: fused flash attention -> ctx fp16 in ah
    cudaStreamWaitEvent(0, evKVdone, 0);
    flash_mma<<<dim3(NH, 8), T256, 131072>>>(qh, ql, kh, vth, ah);

    // main: out = ctx @ w_o  (1-pass)
    cudaStreamWaitEvent(0, evO, 0);
    mma_gemm1<<<dim3(HID_D / 128, 8), T256, 65536>>>(ah, wo, out, HID_D, CTX_D);
}

// round 15
// speedup vs baseline: 1.3639x; 1.0312x over previous
#include <cuda_runtime.h>
#include <cuda_fp16.h>
#include <math.h>
#include <stdint.h>

// ---------------- problem constants ----------------
#define S_LEN 1024
#define HID_D 7168
#define NH 128
#define DN 128
#define DR 64
#define DV 128
#define QLORA 1536
#define KVLORA 512
#define COMP_D (QLORA + KVLORA + DR)      // 2112
#define QD (NH * (DN + DR))               // 24576
#define KVD (NH * (DN + DV))              // 32768
#define CTX_D (NH * DV)                   // 16384
#define DQK 192

// ---------------- scratch (device globals) ----------------
__device__ float g_comp[S_LEN * COMP_D];
__device__ __half g_ah[(size_t)S_LEN * 16384];                   // activations hi (also ctx)
__device__ __half g_al[(size_t)S_LEN * 16384];                   // activations lo
__device__ __half g_bh[S_LEN * KVLORA];                          // kv-chain activations hi
__device__ __half g_bl[S_LEN * KVLORA];                          // kv-chain activations lo
__device__ __half g_wa[15597568];                                // w_kv_a (2176*7168)
__device__ __half g_wq[(size_t)QD * QLORA];                      // w_q_b^T
__device__ __half g_wkv[(size_t)KVD * KVLORA];                   // w_kv_b^T
__device__ __half g_wo[(size_t)HID_D * CTX_D];                   // w_o^T
__device__ float g_kv[(size_t)S_LEN * KVD];                      // v half only used
__device__ float g_kpe[S_LEN * DR];
__device__ __half g_qh[(size_t)NH * S_LEN * DQK];
__device__ __half g_ql[(size_t)NH * S_LEN * DQK];
__device__ __half g_kh[(size_t)NH * S_LEN * DQK];
__device__ __half g_vth[(size_t)NH * DV * S_LEN];

// ---------------- PTX helpers ----------------
__device__ __forceinline__ uint32_t smem_u32(const void* p) {
    uint32_t a;
    asm("{ .reg .u64 t; cvta.to.shared.u64 t, %1; cvt.u32.u64 %0, t; }" : "=r"(a) : "l"(p));
    return a;
}
#define CP16(dst, src) \
    asm volatile("cp.async.cg.shared.global [%0], [%1], 16;" :: "r"(dst), "l"(src) : "memory")
#define CP_COMMIT() asm volatile("cp.async.commit_group;" ::: "memory")
#define CP_WAIT1() asm volatile("cp.async.wait_group 1;" ::: "memory")
#define CP_WAIT0() asm volatile("cp.async.wait_group 0;" ::: "memory")

#define LDSM4(r, a) \
    asm volatile("ldmatrix.sync.aligned.m8n8.x4.shared.b16 {%0,%1,%2,%3}, [%4];" \
        : "=r"((r)[0]), "=r"((r)[1]), "=r"((r)[2]), "=r"((r)[3]) : "r"(a))

#define MMA_F16(d, a, b0, b1) \
    asm volatile("mma.sync.aligned.m16n8k16.row.col.f32.f16.f16.f32 " \
        "{%0,%1,%2,%3}, {%4,%5,%6,%7}, {%8,%9}, {%0,%1,%2,%3};" \
        : "+f"((d)[0]), "+f"((d)[1]), "+f"((d)[2]), "+f"((d)[3]) \
        : "r"((a)[0]), "r"((a)[1]), "r"((a)[2]), "r"((a)[3]), "r"(b0), "r"(b1))

#define SWZ(o) ((o) ^ (((o) >> 3) & 0x70))

__device__ __forceinline__ void split_h(float v, __half& h, __half& l) {
    h = __float2half_rn(v);
    l = __float2half_rn(v - __half2float(h));
}

// ---------------- shared GEMM body (2-stage pipeline, R8-proven) ----------------
// NPASS=1: ah*bh        NPASS=2: ah*bh + al*bh        NPASS=3: + ah*bl
template <int NPASS>
__device__ __forceinline__ void gemm_body(
    const __half* __restrict__ Ah, const __half* __restrict__ Al,
    const __half* __restrict__ Bh, const __half* __restrict__ Bl,
    int K, int nch, int m0, int n0, uint32_t sb, int tid, float acc[2][8][4])
{
    constexpr int CA = (NPASS >= 2) ? 2 : 1;
    constexpr int CB = (NPASS == 3) ? 2 : 1;
    constexpr int NT = CA + CB;
    constexpr int STAGE = NT * 16384;
    const int lane = tid & 31;
    const int wid = tid >> 5;
    const int wm = (wid & 3) * 32;
    const int wn = (wid >> 2) * 64;

    auto load_stage = [&](int c, int s) {
        const int kc = c << 6;
#pragma unroll
        for (int it = 0; it < NT * 4; it++) {
            const int t = tid + it * 256;
            const int tensor = t >> 10;
            const int rem = t & 1023;
            const int row = rem >> 3;
            const int ch = rem & 7;
            const __half* src;
            int grow;
            if (tensor < CA) {
                src = (CA == 2 && tensor == 1) ? Al : Ah;
                grow = m0 + row;
            } else {
                src = (CB == 2 && tensor == CA + 1) ? Bl : Bh;
                grow = n0 + row;
            }
            const __half* sp = src + (size_t)grow * K + kc + ch * 8;
            const uint32_t dst = sb + s * STAGE + tensor * 16384 + SWZ(row * 128 + ch * 16);
            CP16(dst, sp);
        }
        CP_COMMIT();
    };

    load_stage(0, 0);

    for (int c = 0; c < nch; c++) {
        const int buf = c & 1;
        if (c + 1 < nch) { load_stage(c + 1, buf ^ 1); CP_WAIT1(); }
        else             { CP_WAIT0(); }
        __syncthreads();

        const uint32_t st = sb + buf * STAGE;
        const uint32_t sA_h = st;
        const uint32_t sA_l = st + 16384;
        const uint32_t sB_h = st + CA * 16384;
        const uint32_t sB_l = sB_h + 16384;
        const int rl = lane & 15;
        const int kb = lane >> 4;

#pragma unroll
        for (int k16 = 0; k16 < 4; k16++) {
            const int kbyte = k16 * 32 + kb * 16;
            uint32_t afh[2][4], afl[2][4], bfh[4][4], bfl[4][4];
#pragma unroll
            for (int mt = 0; mt < 2; mt++) {
                const uint32_t off = SWZ((wm + mt * 16 + rl) * 128 + kbyte);
                LDSM4(afh[mt], sA_h + off);
                if (CA == 2) LDSM4(afl[mt], sA_l + off);
            }
#pragma unroll
            for (int q = 0; q < 4; q++) {
                const uint32_t off = SWZ((wn + q * 16 + rl) * 128 + kbyte);
                LDSM4(bfh[q], sB_h + off);
                if (CB == 2) LDSM4(bfl[q], sB_l + off);
            }
#pragma unroll
            for (int mt = 0; mt < 2; mt++)
#pragma unroll
                for (int nt = 0; nt < 8; nt++) {
                    const int q = nt >> 1, s = nt & 1;
                    MMA_F16(acc[mt][nt], afh[mt], bfh[q][s], bfh[q][s + 2]);
                    if (CA == 2) MMA_F16(acc[mt][nt], afl[mt], bfh[q][s], bfh[q][s + 2]);
                    if (CB == 2) MMA_F16(acc[mt][nt], afh[mt], bfl[q][s], bfl[q][s + 2]);
                }
        }
        __syncthreads();
    }
}

#define GEMM_PROLOGUE() \
    extern __shared__ __align__(128) char smem[]; \
    const uint32_t sb = smem_u32(smem); \
    const int tid = threadIdx.x; \
    const int lane = tid & 31; \
    const int wid = tid >> 5; \
    const int m0 = blockIdx.y * 128, n0 = blockIdx.x * 128; \
    const int wm = (wid & 3) * 32, wn = (wid >> 2) * 64; \
    float acc[2][8][4]; \
    _Pragma("unroll") for (int mt = 0; mt < 2; mt++) \
    _Pragma("unroll") for (int nt = 0; nt < 8; nt++) \
    _Pragma("unroll") for (int e = 0; e < 4; e++) acc[mt][nt][e] = 0.0f;

// ---------------- comp GEMM: 2-pass, fp32 out, N guarded (96KB, 2 CTA/SM) -------
__global__ __launch_bounds__(256, 2) void mma_gemm2(
    const __half* __restrict__ Ah, const __half* __restrict__ Al,
    const __half* __restrict__ Bh,
    float* __restrict__ C, int N, int K)
{
    GEMM_PROLOGUE();
    gemm_body<2>(Ah, Al, Bh, nullptr, K, K >> 6, m0, n0, sb, tid, acc);
#pragma unroll
    for (int mt = 0; mt < 2; mt++) {
        const int row = m0 + wm + mt * 16 + (lane >> 2);
#pragma unroll
        for (int nt = 0; nt < 8; nt++) {
            const int col = n0 + wn + nt * 8 + (lane & 3) * 2;
            if (col < N) {
                *reinterpret_cast<float2*>(C + (size_t)row * N + col) =
                    make_float2(acc[mt][nt][0], acc[mt][nt][1]);
                *reinterpret_cast<float2*>(C + (size_t)(row + 8) * N + col) =
                    make_float2(acc[mt][nt][2], acc[mt][nt][3]);
            }
        }
    }
}

// ---------------- w_o GEMM: 1-pass, fp32 out (64KB, 2 CTA/SM) ----------
__global__ __launch_bounds__(256, 2) void mma_gemm1(
    const __half* __restrict__ Ah, const __half* __restrict__ Bh,
    float* __restrict__ C, int N, int K)
{
    GEMM_PROLOGUE();
    gemm_body<1>(Ah, nullptr, Bh, nullptr, K, K >> 6, m0, n0, sb, tid, acc);
#pragma unroll
    for (int mt = 0; mt < 2; mt++) {
        const int row = m0 + wm + mt * 16 + (lane >> 2);
#pragma unroll
        for (int nt = 0; nt < 8; nt++) {
            const int col = n0 + wn + nt * 8 + (lane & 3) * 2;
            *reinterpret_cast<float2*>(C + (size_t)row * N + col) =
                make_float2(acc[mt][nt][0], acc[mt][nt][1]);
            *reinterpret_cast<float2*>(C + (size_t)(row + 8) * N + col) =
                make_float2(acc[mt][nt][2], acc[mt][nt][3]);
        }
    }
}

// ---------------- RoPE angle ----------------
__device__ __forceinline__ void rope_cs(int s, int d, float& c, float& sn)
{
    const float inv = exp2f(-(float)d * (13.287712379549449f / 32.0f));
    sincosf((float)s * inv, &sn, &c);
}

// ---------------- q GEMM: 1-pass, fused RoPE + split (64KB, 2 CTA/SM) -----------
__global__ __launch_bounds__(256, 2) void mma_gemm_q(
    const __half* __restrict__ Ah, const __half* __restrict__ Bh,
    __half* __restrict__ Qh, __half* __restrict__ Ql)
{
    GEMM_PROLOGUE();
    gemm_body<1>(Ah, nullptr, Bh, nullptr, QLORA, QLORA >> 6, m0, n0, sb, tid, acc);

    const int base64 = n0 + wn;
    if ((base64 / 64) % 3 != 2) {
#pragma unroll
        for (int mt = 0; mt < 2; mt++)
#pragma unroll
            for (int half_i = 0; half_i < 2; half_i++) {
                const int row = m0 + wm + mt * 16 + (lane >> 2) + half_i * 8;
#pragma unroll
                for (int nt = 0; nt < 8; nt++) {
                    const int c = base64 + nt * 8 + (lane & 3) * 2;
                    const int h = c / 192;
                    const int cr = c - h * 192;
                    const size_t o = ((size_t)h * S_LEN + row) * DQK + cr;
                    __half h0, l0, h1, l1;
                    split_h(acc[mt][nt][half_i * 2], h0, l0);
                    split_h(acc[mt][nt][half_i * 2 + 1], h1, l1);
                    *reinterpret_cast<__half2*>(Qh + o) = __half2(h0, h1);
                    *reinterpret_cast<__half2*>(Ql + o) = __half2(l0, l1);
                }
            }
    } else {
        const int h = base64 / 192;
#pragma unroll
        for (int mt = 0; mt < 2; mt++)
#pragma unroll
            for (int half_i = 0; half_i < 2; half_i++) {
                const int row = m0 + wm + mt * 16 + (lane >> 2) + half_i * 8;
                const size_t rb = ((size_t)h * S_LEN + row) * DQK + 128;
#pragma unroll
                for (int ntL = 0; ntL < 4; ntL++) {
                    const int d0 = ntL * 8 + (lane & 3) * 2;
                    float o0[2], o1[2];
#pragma unroll
                    for (int e = 0; e < 2; e++) {
                        float cc, ss;
                        rope_cs(row, d0 + e, cc, ss);
                        const float v1 = acc[mt][ntL][half_i * 2 + e];
                        const float v2 = acc[mt][ntL + 4][half_i * 2 + e];
                        o0[e] = v1 * cc - v2 * ss;
                        o1[e] = v2 * cc + v1 * ss;
                    }
                    __half h0, l0, h1, l1;
                    split_h(o0[0], h0, l0); split_h(o0[1], h1, l1);
                    *reinterpret_cast<__half2*>(Qh + rb + d0) = __half2(h0, h1);
                    *reinterpret_cast<__half2*>(Ql + rb + d0) = __half2(l0, l1);
                    split_h(o1[0], h0, l0); split_h(o1[1], h1, l1);
                    *reinterpret_cast<__half2*>(Qh + rb + d0 + 32) = __half2(h0, h1);
                    *reinterpret_cast<__half2*>(Ql + rb + d0 + 32) = __half2(l0, l1);
                }
            }
    }
}

// ---------------- kv GEMM: 2-pass, k_nope -> Kh only; v -> fp32 (96KB, 2 CTA/SM)
__global__ __launch_bounds__(256, 2) void mma_gemm_kv(
    const __half* __restrict__ Ah, const __half* __restrict__ Al,
    const __half* __restrict__ Bh,
    __half* __restrict__ Kh, float* __restrict__ kv)
{
    GEMM_PROLOGUE();
    gemm_body<2>(Ah, Al, Bh, nullptr, KVLORA, KVLORA >> 6, m0, n0, sb, tid, acc);

    const int base64 = n0 + wn;
    const int blk4 = (base64 / 64) & 3;
    if (blk4 < 2) {
        const int h = base64 / 256;
#pragma unroll
        for (int mt = 0; mt < 2; mt++)
#pragma unroll
            for (int half_i = 0; half_i < 2; half_i++) {
                const int row = m0 + wm + mt * 16 + (lane >> 2) + half_i * 8;
#pragma unroll
                for (int nt = 0; nt < 8; nt++) {
                    const int c = base64 + nt * 8 + (lane & 3) * 2;
                    const int cr = c - h * 256;
                    const size_t o = ((size_t)h * S_LEN + row) * DQK + cr;
                    *reinterpret_cast<__half2*>(Kh + o) =
                        __half2(__float2half_rn(acc[mt][nt][half_i * 2]),
                                __float2half_rn(acc[mt][nt][half_i * 2 + 1]));
                }
            }
    } else {
#pragma unroll
        for (int mt = 0; mt < 2; mt++) {
            const int row = m0 + wm + mt * 16 + (lane >> 2);
#pragma unroll
            for (int nt = 0; nt < 8; nt++) {
                const int c = base64 + nt * 8 + (lane & 3) * 2;
                *reinterpret_cast<float2*>(kv + (size_t)row * KVD + c) =
                    make_float2(acc[mt][nt][0], acc[mt][nt][1]);
                *reinterpret_cast<float2*>(kv + (size_t)(row + 8) * KVD + c) =
                    make_float2(acc[mt][nt][2], acc[mt][nt][3]);
            }
        }
    }
}

// ---------------- fused flash attention per (head, i-tile) ----------------
// S phase: 2-pass (Qh+Ql) x Kh. smem: [0,96K) stages (P reuses [0,32K)), [96K,128K) V
__global__ __launch_bounds__(256, 1) void flash_mma(
    const __half* __restrict__ Qh, const __half* __restrict__ Ql,
    const __half* __restrict__ Kh,
    const __half* __restrict__ Vth, __half* __restrict__ ch)
{
    extern __shared__ __align__(128) char smem[];
    __shared__ float redM[2][128];
    __shared__ float redS[2][128];
    const uint32_t sb = smem_u32(smem);
    const int tid = threadIdx.x;
    const int lane = tid & 31;
    const int wid = tid >> 5;
    const int h = blockIdx.x;
    const int it = 7 - blockIdx.y;          // heavy tiles first
    const int m0 = it * 128;
    const int wm = (wid & 3) * 32, wn = (wid >> 2) * 64;
    const int ng = wid >> 2;
    const size_t hoff = (size_t)h * S_LEN * DQK;
    const size_t voff = (size_t)h * DV * S_LEN;
    const float scale = 0.07216878364870323f;   // 1/sqrt(192)

    float Oacc[2][8][4];
    float mrow[2][2], lrow[2][2];
#pragma unroll
    for (int mt = 0; mt < 2; mt++)
#pragma unroll
        for (int nt = 0; nt < 8; nt++)
#pragma unroll
            for (int e = 0; e < 4; e++) Oacc[mt][nt][e] = 0.0f;
#pragma unroll
    for (int mt = 0; mt < 2; mt++)
#pragma unroll
        for (int hf = 0; hf < 2; hf++) { mrow[mt][hf] = -3.4e38f; lrow[mt][hf] = 0.0f; }

    for (int jt = 0; jt <= it; jt++) {
        // ---- S = (Qh+Ql) @ Kh^T (2-pass) ----
        float Sacc[2][8][4];
#pragma unroll
        for (int mt = 0; mt < 2; mt++)
#pragma unroll
            for (int nt = 0; nt < 8; nt++)
#pragma unroll
                for (int e = 0; e < 4; e++) Sacc[mt][nt][e] = 0.0f;

        gemm_body<2>(Qh + hoff, Ql + hoff, Kh + hoff, nullptr,
                     DQK, 3, m0, jt * 128, sb, tid, Sacc);

        // ---- prefetch V tile (2 chunks of [128 d][64 j]) at [96K,128K) ----
#pragma unroll
        for (int itv = 0; itv < 8; itv++) {
            const int t = tid + itv * 256;
            const int c = t >> 10;
            const int rem = t & 1023;
            const int d = rem >> 3;
            const int seg = rem & 7;
            const __half* sp = Vth + voff + (size_t)d * S_LEN + jt * 128 + c * 64 + seg * 8;
            CP16(sb + 98304 + c * 16384 + SWZ(d * 128 + seg * 16), sp);
        }
        CP_COMMIT();

        // ---- pass A: scale + mask + row max ----
#pragma unroll
        for (int mt = 0; mt < 2; mt++)
#pragma unroll
            for (int hf = 0; hf < 2; hf++) {
                const int rloc = wm + mt * 16 + (lane >> 2) + hf * 8;
                float mx = -3.4e38f;
#pragma unroll
                for (int nt = 0; nt < 8; nt++)
#pragma unroll
                    for (int e = 0; e < 2; e++) {
                        float s = Sacc[mt][nt][hf * 2 + e] * scale;
                        if (jt == it) {
                            const int cg = jt * 128 + wn + nt * 8 + (lane & 3) * 2 + e;
                            if (cg > m0 + rloc) s = -3.4e38f;
                        }
                        Sacc[mt][nt][hf * 2 + e] = s;
                        mx = fmaxf(mx, s);
                    }
                mx = fmaxf(mx, __shfl_xor_sync(0xFFFFFFFFu, mx, 1));
                mx = fmaxf(mx, __shfl_xor_sync(0xFFFFFFFFu, mx, 2));
                if ((lane & 3) == 0) redM[ng][rloc] = mx;
            }
        __syncthreads();

        // ---- pass B: exp, write P (single fp16) to smem, row sums, O rescale ----
#pragma unroll
        for (int mt = 0; mt < 2; mt++)
#pragma unroll
            for (int hf = 0; hf < 2; hf++) {
                const int rloc = wm + mt * 16 + (lane >> 2) + hf * 8;
                const float mnew = fmaxf(mrow[mt][hf],
                                         fmaxf(redM[0][rloc], redM[1][rloc]));
                float ssum = 0.0f;
#pragma unroll
                for (int nt = 0; nt < 8; nt++) {
                    const float p0 = __expf(Sacc[mt][nt][hf * 2] - mnew);
                    const float p1 = __expf(Sacc[mt][nt][hf * 2 + 1] - mnew);
                    ssum += p0 + p1;
                    const uint32_t off = SWZ(rloc * 128 + (nt * 8 + (lane & 3) * 2) * 2);
                    *reinterpret_cast<__half2*>(smem + ng * 16384 + off) =
                        __half2(__float2half_rn(p0), __float2half_rn(p1));
                }
                ssum += __shfl_xor_sync(0xFFFFFFFFu, ssum, 1);
                ssum += __shfl_xor_sync(0xFFFFFFFFu, ssum, 2);
                if ((lane & 3) == 0) redS[ng][rloc] = ssum;
                const float sc = __expf(mrow[mt][hf] - mnew);
#pragma unroll
                for (int nt = 0; nt < 8; nt++) {
                    Oacc[mt][nt][hf * 2] *= sc;
                    Oacc[mt][nt][hf * 2 + 1] *= sc;
                }
                lrow[mt][hf] *= sc;
                mrow[mt][hf] = mnew;
            }
        __syncthreads();

        // ---- pass C: finish l ----
#pragma unroll
        for (int mt = 0; mt < 2; mt++)
#pragma unroll
            for (int hf = 0; hf < 2; hf++) {
                const int rloc = wm + mt * 16 + (lane >> 2) + hf * 8;
                lrow[mt][hf] += redS[0][rloc] + redS[1][rloc];
            }

        // ---- P @ V (single pass), accumulate into Oacc ----
        CP_WAIT0();
        __syncthreads();
        const int rl = lane & 15;
        const int kb = lane >> 4;
#pragma unroll
        for (int c = 0; c < 2; c++) {
#pragma unroll
            for (int k16 = 0; k16 < 4; k16++) {
                const int kbyte = k16 * 32 + kb * 16;
                uint32_t pfh[2][4], vf[4][4];
#pragma unroll
                for (int mt = 0; mt < 2; mt++) {
                    const uint32_t off = SWZ((wm + mt * 16 + rl) * 128 + kbyte);
                    LDSM4(pfh[mt], sb + c * 16384 + off);
                }
#pragma unroll
                for (int q = 0; q < 4; q++) {
                    const uint32_t off = SWZ((wn + q * 16 + rl) * 128 + kbyte);
                    LDSM4(vf[q], sb + 98304 + c * 16384 + off);
                }
#pragma unroll
                for (int mt = 0; mt < 2; mt++)
#pragma unroll
                    for (int nt = 0; nt < 8; nt++) {
                        const int q = nt >> 1, s = nt & 1;
                        MMA_F16(Oacc[mt][nt], pfh[mt], vf[q][s], vf[q][s + 2]);
                    }
            }
        }
        __syncthreads();   // protect P/V smem before next jt's loads
    }

    // ---- epilogue: normalize and write ctx fp16 ----
#pragma unroll
    for (int mt = 0; mt < 2; mt++)
#pragma unroll
        for (int hf = 0; hf < 2; hf++) {
            const int row = m0 + wm + mt * 16 + (lane >> 2) + hf * 8;
            const float inv = 1.0f / lrow[mt][hf];
#pragma unroll
            for (int nt = 0; nt < 8; nt++) {
                const int col = wn + nt * 8 + (lane & 3) * 2;
                const size_t o = (size_t)row * CTX_D + (size_t)h * DV + col;
                *reinterpret_cast<__half2*>(ch + o) =
                    __half2(__float2half_rn(Oacc[mt][nt][hf * 2] * inv),
                            __float2half_rn(Oacc[mt][nt][hf * 2 + 1] * inv));
            }
        }
}

// ---------------- weight converts ----------------
__global__ void conv_w2(const float* __restrict__ W, __half* __restrict__ Th, int K, int N)
{
    __shared__ float t[64][33];
    const int k0 = blockIdx.x * 64, n0 = blockIdx.y * 32;
    const int tx = threadIdx.x, ty = threadIdx.y;
#pragma unroll
    for (int i = 0; i < 8; i++)
        t[ty + i * 8][tx] = W[(size_t)(k0 + ty + i * 8) * N + n0 + tx];
    __syncthreads();
#pragma unroll
    for (int i = 0; i < 4; i++) {
        const int n = n0 + ty + i * 8;
        const int cidx = ty + i * 8;
        __half2 v = __half2(__float2half_rn(t[tx * 2][cidx]),
                            __float2half_rn(t[tx * 2 + 1][cidx]));
        *reinterpret_cast<__half2*>(Th + (size_t)n * K + k0 + tx * 2) = v;
    }
}

// guarded single convert (for w_kv_a, N=2112 padded to 2176 rows)
__global__ void conv_w2g(const float* __restrict__ W, __half* __restrict__ Th, int K, int N)
{
    __shared__ float t[64][33];
    const int k0 = blockIdx.x * 64, n0 = blockIdx.y * 32;
    const int tx = threadIdx.x, ty = threadIdx.y;
#pragma unroll
    for (int i = 0; i < 8; i++) {
        const int n = n0 + tx;
        t[ty + i * 8][tx] = (n < N) ? W[(size_t)(k0 + ty + i * 8) * N + n] : 0.0f;
    }
    __syncthreads();
#pragma unroll
    for (int i = 0; i < 4; i++) {
        const int n = n0 + ty + i * 8;
        const int cidx = ty + i * 8;
        __half2 v = __half2(__float2half_rn(t[tx * 2][cidx]),
                            __float2half_rn(t[tx * 2 + 1][cidx]));
        *reinterpret_cast<__half2*>(Th + (size_t)n * K + k0 + tx * 2) = v;
    }
}

// ---------------- activation convert ----------------
__global__ void conv_a(const float* __restrict__ A, __half* __restrict__ H,
                       __half* __restrict__ L, int n4)
{
    const int i = blockIdx.x * blockDim.x + threadIdx.x;
    if (i >= n4) return;
    const float4 v = reinterpret_cast<const float4*>(A)[i];
    __half h0, l0, h1, l1, h2, l2, h3, l3;
    split_h(v.x, h0, l0); split_h(v.y, h1, l1);
    split_h(v.z, h2, l2); split_h(v.w, h3, l3);
    __half2* Hp = reinterpret_cast<__half2*>(H) + i * 2;
    __half2* Lp = reinterpret_cast<__half2*>(L) + i * 2;
    Hp[0] = __half2(h0, h1); Hp[1] = __half2(h2, h3);
    Lp[0] = __half2(l0, l1); Lp[1] = __half2(l2, l3);
}

// ---------------- rmsnorm fused to fp16 hi/lo ----------------
__global__ void rmsnorm_h(const float* __restrict__ x, const float* __restrict__ gamma,
                          __half* __restrict__ yh, __half* __restrict__ yl,
                          int D, int xstride)
{
    const int row = blockIdx.x;
    const float* xr = x + (size_t)row * xstride;
    float s = 0.0f;
    for (int i = threadIdx.x; i < D; i += 256) { const float v = xr[i]; s += v * v; }
    __shared__ float red[256];
    red[threadIdx.x] = s;
    __syncthreads();
    for (int o = 128; o > 0; o >>= 1) {
        if (threadIdx.x < o) red[threadIdx.x] += red[threadIdx.x + o];
        __syncthreads();
    }
    const float inv = rsqrtf(red[0] / (float)D + 1e-6f);
    for (int i = threadIdx.x; i < D; i += 256) {
        __half h, l;
        split_h(xr[i] * inv * gamma[i], h, l);
        yh[(size_t)row * D + i] = h;
        yl[(size_t)row * D + i] = l;
    }
}

// ---------------- k_pe RoPE ----------------
__global__ void rope_k_kernel(const float* __restrict__ comp, float* __restrict__ kpe)
{
    const int t = blockIdx.x * blockDim.x + threadIdx.x;
    if (t >= S_LEN * 32) return;
    const int d = t & 31;
    const int s = t >> 5;
    float c, sn;
    rope_cs(s, d, c, sn);
    const float* src = comp + (size_t)s * COMP_D + QLORA + KVLORA;
    const float x1 = src[d], x2 = src[d + 32];
    kpe[s * DR + d]      = x1 * c - x2 * sn;
    kpe[s * DR + d + 32] = x2 * c + x1 * sn;
}

// ---------------- broadcast roped k_pe into per-head K cols 128..191 (hi only) --
__global__ void fill_kpe(const float* __restrict__ kpe, __half* __restrict__ Kh)
{
    const int t = blockIdx.x * blockDim.x + threadIdx.x;
    if (t >= NH * S_LEN * 32) return;
    const int d2 = t & 31;
    const int j  = (t >> 5) & (S_LEN - 1);
    const int h  = t >> 15;
    const int d = d2 * 2;
    const size_t o = ((size_t)h * S_LEN + j) * DQK + 128 + d;
    *reinterpret_cast<__half2*>(Kh + o) =
        __half2(__float2half_rn(kpe[j * DR + d]),
                __float2half_rn(kpe[j * DR + d + 1]));
}

// ---------------- build V^T per head (transpose, single fp16) ----------------
__global__ void build_vt(const float* __restrict__ kv, __half* __restrict__ Vth)
{
    __shared__ float t[32][33];
    const int j0 = blockIdx.x * 32, d0 = blockIdx.y * 32, h = blockIdx.z;
    const int tx = threadIdx.x, ty = threadIdx.y;
#pragma unroll
    for (int i = 0; i < 4; i++)
        t[ty + i * 8][tx] = kv[(size_t)(j0 + ty + i * 8) * KVD + h * 256 + 128 + d0 + tx];
    __syncthreads();
    const size_t base = (size_t)h * DV * S_LEN;
#pragma unroll
    for (int i = 0; i < 4; i++)
        Vth[base + (size_t)(d0 + ty + i * 8) * S_LEN + j0 + tx] =
            __float2half_rn(t[tx][ty + i * 8]);
}

// ---------------- launch ----------------
extern "C" void kernel_launch(void* const* d_in, const int* in_sizes, int n_in,
                              void* d_out, int out_size)
{
    const float* hs       = (const float*)d_in[0];
    const float* w_kv_a   = (const float*)d_in[1];
    const float* q_gamma  = (const float*)d_in[2];
    const float* kv_gamma = (const float*)d_in[3];
    const float* w_q_b    = (const float*)d_in[4];
    const float* w_kv_b   = (const float*)d_in[5];
    const float* w_o      = (const float*)d_in[6];
    float* out = (float*)d_out;

    float *comp, *kv, *kpe;
    __half *ah, *al, *bh, *bl, *wa, *wq, *wkv, *wo, *qh, *ql, *kh, *vth;
    cudaGetSymbolAddress((void**)&comp, g_comp);
    cudaGetSymbolAddress((void**)&ah,   g_ah);
    cudaGetSymbolAddress((void**)&al,   g_al);
    cudaGetSymbolAddress((void**)&bh,   g_bh);
    cudaGetSymbolAddress((void**)&bl,   g_bl);
    cudaGetSymbolAddress((void**)&wa,   g_wa);
    cudaGetSymbolAddress((void**)&wq,   g_wq);
    cudaGetSymbolAddress((void**)&wkv,  g_wkv);
    cudaGetSymbolAddress((void**)&wo,   g_wo);
    cudaGetSymbolAddress((void**)&kv,   g_kv);
    cudaGetSymbolAddress((void**)&kpe,  g_kpe);
    cudaGetSymbolAddress((void**)&qh,   g_qh);
    cudaGetSymbolAddress((void**)&ql,   g_ql);
    cudaGetSymbolAddress((void**)&kh,   g_kh);
    cudaGetSymbolAddress((void**)&vth,  g_vth);

    cudaFuncSetAttribute(mma_gemm2, cudaFuncAttributeMaxDynamicSharedMemorySize, 98304);
    cudaFuncSetAttribute(mma_gemm_q, cudaFuncAttributeMaxDynamicSharedMemorySize, 65536);
    cudaFuncSetAttribute(mma_gemm_kv, cudaFuncAttributeMaxDynamicSharedMemorySize, 98304);
    cudaFuncSetAttribute(mma_gemm1, cudaFuncAttributeMaxDynamicSharedMemorySize, 65536);
    cudaFuncSetAttribute(flash_mma, cudaFuncAttributeMaxDynamicSharedMemorySize, 131072);
    const dim3 T256(256);
    const dim3 TW(32, 8);

    // side stream + events (created per call; never destroyed)
    cudaStream_t s2;
    cudaStreamCreateWithFlags(&s2, cudaStreamNonBlocking);
    cudaEvent_t evFork, evA, evQ, evO, evComp, evKVdone;
    cudaEventCreateWithFlags(&evFork,   cudaEventDisableTiming);
    cudaEventCreateWithFlags(&evA,      cudaEventDisableTiming);
    cudaEventCreateWithFlags(&evQ,      cudaEventDisableTiming);
    cudaEventCreateWithFlags(&evO,      cudaEventDisableTiming);
    cudaEventCreateWithFlags(&evComp,   cudaEventDisableTiming);
    cudaEventCreateWithFlags(&evKVdone, cudaEventDisableTiming);

    cudaEventRecord(evFork, 0);
    cudaStreamWaitEvent(s2, evFork, 0);

    // side stream (phase 1): activation split + q/kv weight conversions
    conv_a<<<(S_LEN * HID_D / 4 + 255) / 256, 256, 0, s2>>>(hs, ah, al, S_LEN * HID_D / 4);
    cudaEventRecord(evA, s2);
    conv_w2<<<dim3(QLORA / 64, QD / 32), TW, 0, s2>>>(w_q_b, wq, QLORA, QD);
    cudaEventRecord(evQ, s2);
    conv_w2<<<dim3(KVLORA / 64, KVD / 32), TW, 0, s2>>>(w_kv_b, wkv, KVLORA, KVD);

    // main: comp = hs @ w_kv_a  (2-pass; N pad 2176)
    conv_w2g<<<dim3(HID_D / 64, 2176 / 32), TW>>>(w_kv_a, wa, HID_D, COMP_D);
    cudaStreamWaitEvent(0, evA, 0);
    mma_gemm2<<<dim3(17, 8), T256, 98304>>>(ah, al, wa, comp, COMP_D, HID_D);
    cudaEventRecord(evComp, 0);

    // side stream (phase 2): entire kv chain (ordered after conv_w2(wkv) on s2)
    cudaStreamWaitEvent(s2, evComp, 0);
    rope_k_kernel<<<(S_LEN * 32) / 256, 256, 0, s2>>>(comp, kpe);
    fill_kpe<<<(NH * S_LEN * 32) / 256, 256, 0, s2>>>(kpe, kh);
    rmsnorm_h<<<S_LEN, 256, 0, s2>>>(comp + QLORA, kv_gamma, bh, bl, KVLORA, COMP_D);
    mma_gemm_kv<<<dim3(KVD / 128, 8), T256, 98304, s2>>>(bh, bl, wkv, kh, kv);
    build_vt<<<dim3(32, 4, NH), TW, 0, s2>>>(kv, vth);
    cudaEventRecord(evKVdone, s2);

    // side stream (phase 3): w_o conversion, overlaps flash
    conv_w2<<<dim3(CTX_D / 64, HID_D / 32), TW, 0, s2>>>(w_o, wo, CTX_D, HID_D);
    cudaEventRecord(evO, s2);

    // main: q chain (concurrent with kv chain)
    rmsnorm_h<<<S_LEN, 256>>>(comp, q_gamma, ah, al, QLORA, COMP_D);
    cudaStreamWaitEvent(0, evQ, 0);
    mma_gemm_q<<<dim3(QD / 128, 8), T256, 65536>>>(ah, wq, qh, ql);

    // main: fused flash attention -> ctx fp16 in ah
    cudaStreamWaitEvent(0, evKVdone, 0);
    flash_mma<<<dim3(NH, 8), T256, 131072>>>(qh, ql, kh, vth, ah);

    // main: out = ctx @ w_o  (1-pass)
    cudaStreamWaitEvent(0, evO, 0);
    mma_gemm1<<<dim3(HID_D / 128, 8), T256, 65536>>>(ah, wo, out, HID_D, CTX_D);
}